// round 7
// baseline (speedup 1.0000x reference)
#include <cuda_runtime.h>
#include <cuda_bf16.h>
#include <cuda_fp16.h>
#include <cstdint>
#include <cstddef>

// ============================================================
// Problem constants
// ============================================================
#define NN   100000      // nodes
#define NE   1600000     // edges
#define NP   100096      // padded: 128*782
#define NB128 782        // GEMM row tiles (128 rows each)
#define D    256
#define DH   128

// ============================================================
// Device global scratch (no cudaMalloc allowed)
// ============================================================
__device__ __align__(256) __nv_bfloat16 g_xhi[(size_t)NP * D];   // layer-1 input hi
__device__ __align__(256) __nv_bfloat16 g_xlo[(size_t)NP * D];   // layer-1 input lo
__device__ __align__(256) __half g_h[(size_t)NP * D];            // activations (fp16)
__device__ __align__(256) float g_a[(size_t)NP * DH];   // relu(x@W2^T + b2)
__device__ __align__(256) float g_y[(size_t)NP * DH];   // x@W3^T (pre-aggregation)
__device__ __align__(256) float g_nm[(size_t)NP * DH];  // aggregated neighbor sum
__device__ __align__(256) __nv_bfloat16 g_w1hi[D * D],  g_w1lo[D * D];
__device__ __align__(256) __half g_w2hi[DH * D], g_w2lo[DH * D];
__device__ __align__(256) __half g_w3hi[DH * D], g_w3lo[DH * D];
__device__ __align__(256) __half g_wd1hi[D * D], g_wd1lo[D * D];
__device__ __align__(256) int g_rowptr[NN + 1];
__device__ __align__(256) int g_cursor[NN];
__device__ __align__(256) int g_cnt[NN];
__device__ __align__(256) int g_colidx[NE];
__device__ __align__(256) int g_src[NE];
__device__ __align__(256) int g_dst[NE];
__device__ int g_is64;

// ============================================================
// Helpers
// ============================================================
__device__ __forceinline__ uint32_t smem_u32(const void* p) {
    uint32_t a;
    asm("{ .reg .u64 t; cvta.to.shared.u64 t, %1; cvt.u32.u64 %0, t; }"
        : "=r"(a) : "l"(p));
    return a;
}

#define SW128(o) ((o) ^ (((o) >> 3) & 0x70))

__device__ __forceinline__ void cp16(uint32_t dst, const void* src) {
    asm volatile("cp.async.cg.shared.global [%0], [%1], 16;" :: "r"(dst), "l"(src));
}
__device__ __forceinline__ void cp_commit() {
    asm volatile("cp.async.commit_group;" ::: "memory");
}
template <int N>
__device__ __forceinline__ void cp_wait() {
    asm volatile("cp.async.wait_group %0;" :: "n"(N) : "memory");
}

__device__ __forceinline__ void ldsm4(uint32_t* r, uint32_t addr) {
    asm volatile("ldmatrix.sync.aligned.m8n8.x4.shared.b16 {%0,%1,%2,%3}, [%4];"
        : "=r"(r[0]), "=r"(r[1]), "=r"(r[2]), "=r"(r[3]) : "r"(addr));
}

__device__ __forceinline__ void mma_bf16(float* c, const uint32_t* a,
                                         uint32_t b0, uint32_t b1) {
    asm volatile(
        "mma.sync.aligned.m16n8k16.row.col.f32.bf16.bf16.f32 "
        "{%0,%1,%2,%3}, {%4,%5,%6,%7}, {%8,%9}, {%0,%1,%2,%3};"
        : "+f"(c[0]), "+f"(c[1]), "+f"(c[2]), "+f"(c[3])
        : "r"(a[0]), "r"(a[1]), "r"(a[2]), "r"(a[3]), "r"(b0), "r"(b1));
}
__device__ __forceinline__ void mma_f16(float* c, const uint32_t* a,
                                        uint32_t b0, uint32_t b1) {
    asm volatile(
        "mma.sync.aligned.m16n8k16.row.col.f32.f16.f16.f32 "
        "{%0,%1,%2,%3}, {%4,%5,%6,%7}, {%8,%9}, {%0,%1,%2,%3};"
        : "+f"(c[0]), "+f"(c[1]), "+f"(c[2]), "+f"(c[3])
        : "r"(a[0]), "r"(a[1]), "r"(a[2]), "r"(a[3]), "r"(b0), "r"(b1));
}

__device__ __forceinline__ void split_bf(float v, __nv_bfloat16& h, __nv_bfloat16& l) {
    h = __float2bfloat16(v);
    l = __float2bfloat16(v - __bfloat162float(h));
}
__device__ __forceinline__ void split_hf(float v, __half& h, __half& l) {
    h = __float2half_rn(v);
    l = __float2half_rn(v - __half2float(h));
}
__device__ __forceinline__ uint32_t pack2(__nv_bfloat16 a, __nv_bfloat16 b) {
    __nv_bfloat162 t; t.x = a; t.y = b;
    return *reinterpret_cast<uint32_t*>(&t);
}
__device__ __forceinline__ uint32_t pack2h(__half a, __half b) {
    __half2 t; t.x = a; t.y = b;
    return *reinterpret_cast<uint32_t*>(&t);
}

// ============================================================
// fp32 -> bf16 hi/lo split of x
// ============================================================
__global__ void conv_x_kernel(const float* __restrict__ x) {
    size_t i4 = (size_t)blockIdx.x * blockDim.x + threadIdx.x;
    if (i4 >= (size_t)NP * 64) return;
    float4 v = make_float4(0.f, 0.f, 0.f, 0.f);
    if (i4 < (size_t)NN * 64) v = __ldg(((const float4*)x) + i4);
    __nv_bfloat16 h0, l0, h1, l1, h2, l2, h3, l3;
    split_bf(v.x, h0, l0); split_bf(v.y, h1, l1);
    split_bf(v.z, h2, l2); split_bf(v.w, h3, l3);
    ((uint2*)g_xhi)[i4] = make_uint2(pack2(h0, h1), pack2(h2, h3));
    ((uint2*)g_xlo)[i4] = make_uint2(pack2(l0, l1), pack2(l2, l3));
}

// one kernel converts all four weight matrices
// W1 -> bf16 hi/lo, W2/W3/Wd1 -> fp16 hi/lo
__global__ void conv_w_all_kernel(const float* __restrict__ W1,
                                  const float* __restrict__ W2,
                                  const float* __restrict__ W3,
                                  const float* __restrict__ Wd1) {
    int i = blockIdx.x * blockDim.x + threadIdx.x;   // float4 index, 49152 total
    if (i < 16384) {
        float4 v = __ldg(((const float4*)W1) + i);
        __nv_bfloat16 h0, l0, h1, l1, h2, l2, h3, l3;
        split_bf(v.x, h0, l0); split_bf(v.y, h1, l1);
        split_bf(v.z, h2, l2); split_bf(v.w, h3, l3);
        ((uint2*)g_w1hi)[i] = make_uint2(pack2(h0, h1), pack2(h2, h3));
        ((uint2*)g_w1lo)[i] = make_uint2(pack2(l0, l1), pack2(l2, l3));
        return;
    }
    const float* w; __half *hi, *lo; int off;
    if (i < 24576)      { w = W2;  hi = g_w2hi;  lo = g_w2lo;  off = i - 16384; }
    else if (i < 32768) { w = W3;  hi = g_w3hi;  lo = g_w3lo;  off = i - 24576; }
    else if (i < 49152) { w = Wd1; hi = g_wd1hi; lo = g_wd1lo; off = i - 32768; }
    else return;
    float4 v = __ldg(((const float4*)w) + off);
    __half h0, l0, h1, l1, h2, l2, h3, l3;
    split_hf(v.x, h0, l0); split_hf(v.y, h1, l1);
    split_hf(v.z, h2, l2); split_hf(v.w, h3, l3);
    ((uint2*)hi)[off] = make_uint2(pack2h(h0, h1), pack2h(h2, h3));
    ((uint2*)lo)[off] = make_uint2(pack2h(l0, l1), pack2h(l2, l3));
}

// ============================================================
// CSR build chain (runs on side stream)
// ============================================================
__global__ void zero_cnt_kernel() {
    int i = blockIdx.x * blockDim.x + threadIdx.x;
    if (i < NN) g_cnt[i] = 0;
}

__global__ void detect_kernel(const int* __restrict__ ei) {
    int z = 1;
    for (int i = 0; i < 64; i++)
        if (ei[2 * i + 1] != 0) { z = 0; break; }
    g_is64 = z;
}

__global__ void extract_kernel(const int* __restrict__ ei) {
    int e = blockIdx.x * blockDim.x + threadIdx.x;
    if (e >= NE) return;
    int s, d;
    if (g_is64) {
        s = __ldg(&ei[2 * e]);
        d = __ldg(&ei[2 * ((size_t)NE + e)]);
    } else {
        s = __ldg(&ei[e]);
        d = __ldg(&ei[NE + e]);
    }
    g_src[e] = s;
    g_dst[e] = d;
    if ((unsigned)d < NN) atomicAdd(&g_cnt[d], 1);
}

__global__ void scan_kernel() {
    __shared__ int sd[1024];
    int t = threadIdx.x;
    const int PER = (NN + 1023) / 1024;   // 98
    int b = t * PER;
    int e = b + PER; if (e > NN) e = NN; if (b > NN) b = NN;
    int s = 0;
    for (int i = b; i < e; i++) s += g_cnt[i];
    sd[t] = s;
    __syncthreads();
    for (int off = 1; off < 1024; off <<= 1) {
        int v = (t >= off) ? sd[t - off] : 0;
        __syncthreads();
        sd[t] += v;
        __syncthreads();
    }
    int run = sd[t] - s;   // exclusive prefix
    for (int i = b; i < e; i++) {
        g_rowptr[i] = run;
        g_cursor[i] = run;
        run += g_cnt[i];
    }
    if (t == 1023) g_rowptr[NN] = run;
}

__global__ void fill_edges_kernel() {
    int e = blockIdx.x * blockDim.x + threadIdx.x;
    if (e >= NE) return;
    unsigned s = (unsigned)g_src[e];
    unsigned d = (unsigned)g_dst[e];
    if (s < NN && d < NN) {
        int p = atomicAdd(&g_cursor[d], 1);
        g_colidx[p] = (int)s;
    }
}

// ============================================================
// N=256 GEMM (layer-1 bf16 3-pass, final fp16 2-pass)
// CTA tile 128x256, 8 warps (2 row x 4 col), warp tile 64x64.
// ============================================================
static constexpr int SSTRIDE = 260;

template <int MODE>   // 0 = layer-1 (bf16 exact), 2 = final head (fp16)
struct GCfg {
    static constexpr bool BF   = (MODE == 0);
    static constexpr int OF_AL = 16384;
    static constexpr int OF_BH = BF ? 32768 : 16384;
    static constexpr int OF_BL = BF ? 65536 : 49152;
    static constexpr int STG   = BF ? 98304 : 81920;
    static constexpr int SMEM  = 2 * STG;
};

template <int MODE>
__device__ __forceinline__ void issue_chunk(
        uint32_t sbuf, int rowbase, int kb, int tid,
        const uint8_t* BloH, const uint8_t* BloL,
        const uint8_t* BupH, const uint8_t* BupL) {
    using C = GCfg<MODE>;
    for (int t = tid; t < 1024; t += 256) {
        int r = t >> 3, g = t & 7;
        uint32_t so = SW128((uint32_t)(r * 128 + g * 16));
        size_t ob = ((size_t)(rowbase + r) * D + kb + g * 8) * 2;
        if (C::BF) {
            cp16(sbuf + so,            (const uint8_t*)g_xhi + ob);
            cp16(sbuf + C::OF_AL + so, (const uint8_t*)g_xlo + ob);
        } else {
            cp16(sbuf + so,            (const uint8_t*)g_h + ob);
        }
    }
    for (int t = tid; t < 2048; t += 256) {
        int r = t >> 3, g = t & 7;
        uint32_t so = SW128((uint32_t)(r * 128 + g * 16));
        size_t ob = ((size_t)(r < 128 ? r : r - 128) * D + kb + g * 8) * 2;
        const uint8_t* sh = (r < 128 ? BloH : BupH) + ob;
        const uint8_t* sl = (r < 128 ? BloL : BupL) + ob;
        cp16(sbuf + C::OF_BH + so, sh);
        cp16(sbuf + C::OF_BL + so, sl);
    }
}

template <int MODE>
__global__ void __launch_bounds__(256, 1)
gemm_kernel(const float* __restrict__ bias, const float* __restrict__ wd2,
            const float* __restrict__ bd2, float* __restrict__ out) {
    using C = GCfg<MODE>;
    extern __shared__ char smem[];
    uint32_t sb = smem_u32(smem);
    int tid = threadIdx.x, wid = tid >> 5, lane = tid & 31;
    int rowbase = blockIdx.x * 128;
    int wrow = wid & 1;
    int wcol = wid >> 1;

    const uint8_t *BloH, *BloL, *BupH, *BupL;
    if (MODE == 0) {
        BloH = (const uint8_t*)g_w1hi;  BloL = (const uint8_t*)g_w1lo;
        BupH = (const uint8_t*)(g_w1hi + 128 * D);  BupL = (const uint8_t*)(g_w1lo + 128 * D);
    } else {
        BloH = (const uint8_t*)g_wd1hi; BloL = (const uint8_t*)g_wd1lo;
        BupH = (const uint8_t*)(g_wd1hi + 128 * D); BupL = (const uint8_t*)(g_wd1lo + 128 * D);
    }

    float c[4][8][4];
    #pragma unroll
    for (int mt = 0; mt < 4; mt++)
        #pragma unroll
        for (int nt = 0; nt < 8; nt++)
            #pragma unroll
            for (int q = 0; q < 4; q++) c[mt][nt][q] = 0.f;

    int q8 = lane >> 3, l8 = lane & 7;

    issue_chunk<MODE>(sb, rowbase, 0, tid, BloH, BloL, BupH, BupL);
    cp_commit();

    for (int ch = 0; ch < 4; ch++) {
        uint32_t buf = sb + (uint32_t)(ch & 1) * C::STG;
        if (ch < 3) {
            issue_chunk<MODE>(sb + (uint32_t)((ch + 1) & 1) * C::STG, rowbase,
                              (ch + 1) * 64, tid, BloH, BloL, BupH, BupL);
            cp_commit();
            cp_wait<1>();
        } else {
            cp_wait<0>();
        }
        __syncthreads();

        #pragma unroll
        for (int ks = 0; ks < 4; ks++) {
            uint32_t ah[4][4], al[4][4];
            #pragma unroll
            for (int mt = 0; mt < 4; mt++) {
                int row = wrow * 64 + mt * 16 + (q8 & 1) * 8 + l8;
                uint32_t off = SW128((uint32_t)(row * 128 + ks * 32 + (q8 >> 1) * 16));
                ldsm4(ah[mt], buf + off);
                if (C::BF) ldsm4(al[mt], buf + C::OF_AL + off);
            }
            uint32_t bh[4][4], bl[4][4];
            #pragma unroll
            for (int nt = 0; nt < 4; nt++) {
                int nrow = wcol * 64 + nt * 16 + ((q8 >> 1) & 1) * 8 + l8;
                uint32_t off = SW128((uint32_t)(nrow * 128 + ks * 32 + (q8 & 1) * 16));
                ldsm4(bh[nt], buf + C::OF_BH + off);
                ldsm4(bl[nt], buf + C::OF_BL + off);
            }
            #pragma unroll
            for (int mt = 0; mt < 4; mt++)
                #pragma unroll
                for (int nt = 0; nt < 4; nt++) {
                    if (C::BF) {
                        mma_bf16(c[mt][nt * 2],     ah[mt], bh[nt][0], bh[nt][1]);
                        mma_bf16(c[mt][nt * 2],     ah[mt], bl[nt][0], bl[nt][1]);
                        mma_bf16(c[mt][nt * 2],     al[mt], bh[nt][0], bh[nt][1]);
                        mma_bf16(c[mt][nt * 2 + 1], ah[mt], bh[nt][2], bh[nt][3]);
                        mma_bf16(c[mt][nt * 2 + 1], ah[mt], bl[nt][2], bl[nt][3]);
                        mma_bf16(c[mt][nt * 2 + 1], al[mt], bh[nt][2], bh[nt][3]);
                    } else {
                        mma_f16(c[mt][nt * 2],     ah[mt], bh[nt][0], bh[nt][1]);
                        mma_f16(c[mt][nt * 2],     ah[mt], bl[nt][0], bl[nt][1]);
                        mma_f16(c[mt][nt * 2 + 1], ah[mt], bh[nt][2], bh[nt][3]);
                        mma_f16(c[mt][nt * 2 + 1], ah[mt], bl[nt][2], bl[nt][3]);
                    }
                }
        }
        __syncthreads();
    }

    float* stage = reinterpret_cast<float*>(smem);
    #pragma unroll
    for (int mt = 0; mt < 4; mt++)
        #pragma unroll
        for (int nt = 0; nt < 8; nt++) {
            int r0  = wrow * 64 + mt * 16 + (lane >> 2);
            int col = wcol * 64 + nt * 8 + 2 * (lane & 3);
            float* p = stage + r0 * SSTRIDE + col;
            p[0] = c[mt][nt][0];
            p[1] = c[mt][nt][1];
            p[8 * SSTRIDE]     = c[mt][nt][2];
            p[8 * SSTRIDE + 1] = c[mt][nt][3];
        }
    __syncthreads();

    for (int r = wid; r < 128; r += 8) {
        int gr = rowbase + r;
        bool ok = gr < NN;
        const float* rowp = stage + r * SSTRIDE + lane * 8;
        int cb = lane * 8;

        if (MODE == 0) {
            float v[8];
            float ss = 0.f;
            #pragma unroll
            for (int j = 0; j < 8; j++) {
                v[j] = fmaxf(rowp[j] + __ldg(&bias[cb + j]), 0.f);
                ss += v[j] * v[j];
            }
            #pragma unroll
            for (int off = 16; off >= 1; off >>= 1)
                ss += __shfl_xor_sync(0xffffffffu, ss, off);
            float rn = rsqrtf(ss);
            if (ok) {
                __half h[8];
                #pragma unroll
                for (int j = 0; j < 8; j++) h[j] = __float2half_rn(v[j] * rn);
                *reinterpret_cast<uint4*>(g_h + (size_t)gr * D + cb) =
                    make_uint4(pack2h(h[0], h[1]), pack2h(h[2], h[3]),
                               pack2h(h[4], h[5]), pack2h(h[6], h[7]));
            }
        } else {
            float acc = 0.f;
            #pragma unroll
            for (int j = 0; j < 8; j++) {
                float vv = fmaxf(rowp[j] + __ldg(&bias[cb + j]), 0.f);
                acc += vv * __ldg(&wd2[cb + j]);
            }
            #pragma unroll
            for (int off = 16; off >= 1; off >>= 1)
                acc += __shfl_xor_sync(0xffffffffu, acc, off);
            if (lane == 0 && ok) out[gr] = acc + __ldg(bd2);
        }
    }
}

// ============================================================
// N=128 GEMM: CTA 128x128, 8 warps (4 row x 2 col), warp 32x64,
// fp16 A single + B hi/lo (2 passes). K chunked 64, 2-stage.
//  WHICH=0: B=W3 -> g_y raw     WHICH=1: B=W2 -> g_a relu(+bias)
// ============================================================
static constexpr int OF128_A  = 0;
static constexpr int OF128_BH = 16384;
static constexpr int OF128_BL = 32768;
static constexpr int STG128   = 49152;
static constexpr int SM128    = 2 * STG128;   // 96 KB
static constexpr int SSTR2    = 132;

template <int WHICH>
__global__ void __launch_bounds__(256, 1)
gemm128_kernel(const float* __restrict__ bias) {
    extern __shared__ char smem[];
    uint32_t sb = smem_u32(smem);
    int tid = threadIdx.x, wid = tid >> 5, lane = tid & 31;
    int rowbase = blockIdx.x * 128;
    int wrow = wid & 3;        // 4 strips of 32 rows
    int wcol = wid >> 2;       // 2 strips of 64 cols
    const uint8_t* BH = (const uint8_t*)(WHICH ? g_w2hi : g_w3hi);
    const uint8_t* BL = (const uint8_t*)(WHICH ? g_w2lo : g_w3lo);

    float c[2][8][4];
    #pragma unroll
    for (int mt = 0; mt < 2; mt++)
        #pragma unroll
        for (int nt = 0; nt < 8; nt++)
            #pragma unroll
            for (int q = 0; q < 4; q++) c[mt][nt][q] = 0.f;

    int q8 = lane >> 3, l8 = lane & 7;

    auto issue = [&](uint32_t sbuf, int kb) {
        for (int t = tid; t < 1024; t += 256) {
            int r = t >> 3, g = t & 7;
            uint32_t so = SW128((uint32_t)(r * 128 + g * 16));
            cp16(sbuf + OF128_A + so,
                 (const uint8_t*)g_h + ((size_t)(rowbase + r) * D + kb + g * 8) * 2);
            size_t ob = ((size_t)r * D + kb + g * 8) * 2;
            cp16(sbuf + OF128_BH + so, BH + ob);
            cp16(sbuf + OF128_BL + so, BL + ob);
        }
    };

    issue(sb, 0);
    cp_commit();

    for (int ch = 0; ch < 4; ch++) {
        uint32_t buf = sb + (uint32_t)(ch & 1) * STG128;
        if (ch < 3) {
            issue(sb + (uint32_t)((ch + 1) & 1) * STG128, (ch + 1) * 64);
            cp_commit();
            cp_wait<1>();
        } else {
            cp_wait<0>();
        }
        __syncthreads();

        #pragma unroll
        for (int ks = 0; ks < 4; ks++) {
            uint32_t a[2][4];
            #pragma unroll
            for (int mt = 0; mt < 2; mt++) {
                int row = wrow * 32 + mt * 16 + (q8 & 1) * 8 + l8;
                uint32_t off = SW128((uint32_t)(row * 128 + ks * 32 + (q8 >> 1) * 16));
                ldsm4(a[mt], buf + OF128_A + off);
            }
            uint32_t bh[4][4], bl[4][4];
            #pragma unroll
            for (int nt = 0; nt < 4; nt++) {
                int nrow = wcol * 64 + nt * 16 + ((q8 >> 1) & 1) * 8 + l8;
                uint32_t off = SW128((uint32_t)(nrow * 128 + ks * 32 + (q8 & 1) * 16));
                ldsm4(bh[nt], buf + OF128_BH + off);
                ldsm4(bl[nt], buf + OF128_BL + off);
            }
            #pragma unroll
            for (int mt = 0; mt < 2; mt++)
                #pragma unroll
                for (int nt = 0; nt < 4; nt++) {
                    mma_f16(c[mt][nt * 2],     a[mt], bh[nt][0], bh[nt][1]);
                    mma_f16(c[mt][nt * 2],     a[mt], bl[nt][0], bl[nt][1]);
                    mma_f16(c[mt][nt * 2 + 1], a[mt], bh[nt][2], bh[nt][3]);
                    mma_f16(c[mt][nt * 2 + 1], a[mt], bl[nt][2], bl[nt][3]);
                }
        }
        __syncthreads();
    }

    float* stage = reinterpret_cast<float*>(smem);
    #pragma unroll
    for (int mt = 0; mt < 2; mt++)
        #pragma unroll
        for (int nt = 0; nt < 8; nt++) {
            int r0  = wrow * 32 + mt * 16 + (lane >> 2);
            int col = wcol * 64 + nt * 8 + 2 * (lane & 3);
            float* p = stage + r0 * SSTR2 + col;
            p[0] = c[mt][nt][0];
            p[1] = c[mt][nt][1];
            p[8 * SSTR2]     = c[mt][nt][2];
            p[8 * SSTR2 + 1] = c[mt][nt][3];
        }
    __syncthreads();

    for (int r = wid; r < 128; r += 8) {
        int gr = rowbase + r;
        if (gr >= NN) continue;
        int cb = lane * 4;
        const float* rp = stage + r * SSTR2 + cb;
        float4 v;
        if (WHICH) {
            v.x = fmaxf(rp[0] + __ldg(&bias[cb + 0]), 0.f);
            v.y = fmaxf(rp[1] + __ldg(&bias[cb + 1]), 0.f);
            v.z = fmaxf(rp[2] + __ldg(&bias[cb + 2]), 0.f);
            v.w = fmaxf(rp[3] + __ldg(&bias[cb + 3]), 0.f);
            *reinterpret_cast<float4*>(g_a + (size_t)gr * DH + cb) = v;
        } else {
            v = make_float4(rp[0], rp[1], rp[2], rp[3]);
            *reinterpret_cast<float4*>(g_y + (size_t)gr * DH + cb) = v;
        }
    }
}

// ============================================================
// CSR gather-reduce: nm[n] = sum over src of y[src]  (warp/node)
// ============================================================
__global__ void agg_gather_kernel() {
    int gw = (blockIdx.x * blockDim.x + threadIdx.x) >> 5;
    int lane = threadIdx.x & 31;
    if (gw >= NN) return;
    int n = gw;
    int beg = __ldg(&g_rowptr[n]);
    int end = __ldg(&g_rowptr[n + 1]);

    float ax = 0.f, ay = 0.f, az = 0.f, aw = 0.f;
    int i = beg;
    for (; i + 4 <= end; i += 4) {
        int s0 = __ldg(&g_colidx[i]);
        int s1 = __ldg(&g_colidx[i + 1]);
        int s2 = __ldg(&g_colidx[i + 2]);
        int s3 = __ldg(&g_colidx[i + 3]);
        float4 v0 = __ldg(reinterpret_cast<const float4*>(g_y + (size_t)s0 * DH) + lane);
        float4 v1 = __ldg(reinterpret_cast<const float4*>(g_y + (size_t)s1 * DH) + lane);
        float4 v2 = __ldg(reinterpret_cast<const float4*>(g_y + (size_t)s2 * DH) + lane);
        float4 v3 = __ldg(reinterpret_cast<const float4*>(g_y + (size_t)s3 * DH) + lane);
        ax += v0.x + v1.x + v2.x + v3.x;
        ay += v0.y + v1.y + v2.y + v3.y;
        az += v0.z + v1.z + v2.z + v3.z;
        aw += v0.w + v1.w + v2.w + v3.w;
    }
    for (; i < end; i++) {
        int s = __ldg(&g_colidx[i]);
        float4 v = __ldg(reinterpret_cast<const float4*>(g_y + (size_t)s * DH) + lane);
        ax += v.x; ay += v.y; az += v.z; aw += v.w;
    }
    *(reinterpret_cast<float4*>(g_nm + (size_t)n * DH) + lane) =
        make_float4(ax, ay, az, aw);
}

// ============================================================
// Combine: h[n] = fp16(l2norm([a[n], relu(nm[n]+b3)]))   (warp/node)
// ============================================================
__global__ void combine_kernel(const float* __restrict__ b3) {
    int gw = (blockIdx.x * blockDim.x + threadIdx.x) >> 5;
    int lane = threadIdx.x & 31;
    if (gw >= NN) return;
    int n = gw;
    float4 nm = __ldg(reinterpret_cast<const float4*>(g_nm + (size_t)n * DH) + lane);
    float4 av = __ldg(reinterpret_cast<const float4*>(g_a + (size_t)n * DH) + lane);
    float4 bb = __ldg(reinterpret_cast<const float4*>(b3) + lane);
    float m0 = fmaxf(nm.x + bb.x, 0.f);
    float m1 = fmaxf(nm.y + bb.y, 0.f);
    float m2 = fmaxf(nm.z + bb.z, 0.f);
    float m3 = fmaxf(nm.w + bb.w, 0.f);

    float ss = av.x * av.x + av.y * av.y + av.z * av.z + av.w * av.w
             + m0 * m0 + m1 * m1 + m2 * m2 + m3 * m3;
    #pragma unroll
    for (int off = 16; off >= 1; off >>= 1)
        ss += __shfl_xor_sync(0xffffffffu, ss, off);
    float rn = rsqrtf(ss);

    size_t base = (size_t)n * D;
    *reinterpret_cast<uint2*>(g_h + base + lane * 4) =
        make_uint2(pack2h(__float2half_rn(av.x * rn), __float2half_rn(av.y * rn)),
                   pack2h(__float2half_rn(av.z * rn), __float2half_rn(av.w * rn)));
    *reinterpret_cast<uint2*>(g_h + base + 128 + lane * 4) =
        make_uint2(pack2h(__float2half_rn(m0 * rn), __float2half_rn(m1 * rn)),
                   pack2h(__float2half_rn(m2 * rn), __float2half_rn(m3 * rn)));
}

// ============================================================
// Host launcher — dual-stream fork/join (capture-safe pattern)
// ============================================================
static cudaStream_t s2 = nullptr;
static cudaEvent_t evFork, evCSR, evY0, evA0, evY1, evA1;

extern "C" void kernel_launch(void* const* d_in, const int* in_sizes, int n_in,
                              void* d_out, int out_size) {
    const float* x   = (const float*)d_in[0];
    const int*   ei  = (const int*)d_in[1];    // int32 or int64 (auto-detected)
    const float* W1  = (const float*)d_in[2];
    const float* b1  = (const float*)d_in[3];
    const float* W2  = (const float*)d_in[4];
    const float* b2  = (const float*)d_in[5];
    const float* W3  = (const float*)d_in[6];
    const float* b3  = (const float*)d_in[7];
    const float* Wd1 = (const float*)d_in[8];
    const float* bd1 = (const float*)d_in[9];
    const float* Wd2 = (const float*)d_in[10];
    const float* bd2 = (const float*)d_in[11];
    float* out = (float*)d_out;

    if (!s2) {
        cudaStreamCreateWithFlags(&s2, cudaStreamNonBlocking);
        cudaEventCreateWithFlags(&evFork, cudaEventDisableTiming);
        cudaEventCreateWithFlags(&evCSR,  cudaEventDisableTiming);
        cudaEventCreateWithFlags(&evY0,   cudaEventDisableTiming);
        cudaEventCreateWithFlags(&evA0,   cudaEventDisableTiming);
        cudaEventCreateWithFlags(&evY1,   cudaEventDisableTiming);
        cudaEventCreateWithFlags(&evA1,   cudaEventDisableTiming);
        cudaFuncSetAttribute(gemm_kernel<0>,  cudaFuncAttributeMaxDynamicSharedMemorySize, GCfg<0>::SMEM);
        cudaFuncSetAttribute(gemm_kernel<2>,  cudaFuncAttributeMaxDynamicSharedMemorySize, GCfg<2>::SMEM);
        cudaFuncSetAttribute(gemm128_kernel<0>, cudaFuncAttributeMaxDynamicSharedMemorySize, SM128);
        cudaFuncSetAttribute(gemm128_kernel<1>, cudaFuncAttributeMaxDynamicSharedMemorySize, SM128);
    }

    // ---- fork side stream: CSR build (independent of conv/gemm0)
    cudaEventRecord(evFork, 0);
    cudaStreamWaitEvent(s2, evFork, 0);
    zero_cnt_kernel<<<(NN + 255) / 256, 256, 0, s2>>>();
    detect_kernel<<<1, 1, 0, s2>>>(ei);
    extract_kernel<<<(NE + 255) / 256, 256, 0, s2>>>(ei);
    scan_kernel<<<1, 1024, 0, s2>>>();
    fill_edges_kernel<<<(NE + 255) / 256, 256, 0, s2>>>();
    cudaEventRecord(evCSR, s2);

    // ---- main stream: conversions + layer 1
    conv_x_kernel<<<(int)(((size_t)NP * 64 + 255) / 256), 256>>>(x);
    conv_w_all_kernel<<<192, 256>>>(W1, W2, W3, Wd1);
    gemm_kernel<0><<<NB128, 256, GCfg<0>::SMEM>>>(b1, nullptr, nullptr, nullptr);

    // ---- conv layer 1: gemm_y -> { gather || gemm_a(s2) } -> combine
    gemm128_kernel<0><<<NB128, 256, SM128>>>(nullptr);
    cudaEventRecord(evY0, 0);
    cudaStreamWaitEvent(s2, evY0, 0);
    gemm128_kernel<1><<<NB128, 256, SM128, s2>>>(b2);
    cudaEventRecord(evA0, s2);
    cudaStreamWaitEvent(0, evCSR, 0);
    agg_gather_kernel<<<(NN * 32 + 255) / 256, 256>>>();
    cudaStreamWaitEvent(0, evA0, 0);
    combine_kernel<<<(NN * 32 + 255) / 256, 256>>>(b3);

    // ---- conv layer 2
    gemm128_kernel<0><<<NB128, 256, SM128>>>(nullptr);
    cudaEventRecord(evY1, 0);
    cudaStreamWaitEvent(s2, evY1, 0);
    gemm128_kernel<1><<<NB128, 256, SM128, s2>>>(b2);
    cudaEventRecord(evA1, s2);
    agg_gather_kernel<<<(NN * 32 + 255) / 256, 256>>>();
    cudaStreamWaitEvent(0, evA1, 0);
    combine_kernel<<<(NN * 32 + 255) / 256, 256>>>(b3);

    // ---- head: out = relu(h @ Wd1^T + bd1) @ Wd2^T + bd2
    gemm_kernel<2><<<NB128, 256, GCfg<2>::SMEM>>>(bd1, Wd2, bd2, out);
}

// round 8
// speedup vs baseline: 1.3384x; 1.3384x over previous
#include <cuda_runtime.h>
#include <cuda_bf16.h>
#include <cuda_fp16.h>
#include <cstdint>
#include <cstddef>

// ============================================================
// Problem constants
// ============================================================
#define NN   100000      // nodes
#define NE   1600000     // edges
#define NP   100096      // padded: 128*782
#define NB128 782        // GEMM row tiles (128 rows each)
#define D    256
#define DH   128

// ============================================================
// Device global scratch (no cudaMalloc allowed)
// ============================================================
__device__ __align__(256) __nv_bfloat16 g_xhi[(size_t)NP * D];   // layer-1 input hi
__device__ __align__(256) __nv_bfloat16 g_xlo[(size_t)NP * D];   // layer-1 input lo
__device__ __align__(256) __half g_h[(size_t)NP * D];            // activations (fp16)
__device__ __align__(256) float g_a[(size_t)NP * DH];   // relu(x@W2^T + b2)
__device__ __align__(256) float g_y[(size_t)NP * DH];   // x@W3^T (pre-aggregation)
__device__ __align__(256) float g_nm[(size_t)NP * DH];  // aggregated neighbor sum
__device__ __align__(256) __nv_bfloat16 g_w1hi[D * D],  g_w1lo[D * D];
__device__ __align__(256) __half g_w2hi[DH * D], g_w2lo[DH * D];
__device__ __align__(256) __half g_w3hi[DH * D], g_w3lo[DH * D];
__device__ __align__(256) __half g_wd1hi[D * D], g_wd1lo[D * D];
__device__ __align__(256) int g_rowptr[NN + 1];
__device__ __align__(256) int g_cursor[NN];
__device__ __align__(256) int g_cnt[NN];
__device__ __align__(256) int g_colidx[NE];
__device__ int g_is64;

// ============================================================
// Helpers
// ============================================================
__device__ __forceinline__ uint32_t smem_u32(const void* p) {
    uint32_t a;
    asm("{ .reg .u64 t; cvta.to.shared.u64 t, %1; cvt.u32.u64 %0, t; }"
        : "=r"(a) : "l"(p));
    return a;
}

#define SW128(o) ((o) ^ (((o) >> 3) & 0x70))

__device__ __forceinline__ void cp16(uint32_t dst, const void* src) {
    asm volatile("cp.async.cg.shared.global [%0], [%1], 16;" :: "r"(dst), "l"(src));
}
__device__ __forceinline__ void cp_commit() {
    asm volatile("cp.async.commit_group;" ::: "memory");
}
template <int N>
__device__ __forceinline__ void cp_wait() {
    asm volatile("cp.async.wait_group %0;" :: "n"(N) : "memory");
}

__device__ __forceinline__ void ldsm4(uint32_t* r, uint32_t addr) {
    asm volatile("ldmatrix.sync.aligned.m8n8.x4.shared.b16 {%0,%1,%2,%3}, [%4];"
        : "=r"(r[0]), "=r"(r[1]), "=r"(r[2]), "=r"(r[3]) : "r"(addr));
}

__device__ __forceinline__ void mma_bf16(float* c, const uint32_t* a,
                                         uint32_t b0, uint32_t b1) {
    asm volatile(
        "mma.sync.aligned.m16n8k16.row.col.f32.bf16.bf16.f32 "
        "{%0,%1,%2,%3}, {%4,%5,%6,%7}, {%8,%9}, {%0,%1,%2,%3};"
        : "+f"(c[0]), "+f"(c[1]), "+f"(c[2]), "+f"(c[3])
        : "r"(a[0]), "r"(a[1]), "r"(a[2]), "r"(a[3]), "r"(b0), "r"(b1));
}
__device__ __forceinline__ void mma_f16(float* c, const uint32_t* a,
                                        uint32_t b0, uint32_t b1) {
    asm volatile(
        "mma.sync.aligned.m16n8k16.row.col.f32.f16.f16.f32 "
        "{%0,%1,%2,%3}, {%4,%5,%6,%7}, {%8,%9}, {%0,%1,%2,%3};"
        : "+f"(c[0]), "+f"(c[1]), "+f"(c[2]), "+f"(c[3])
        : "r"(a[0]), "r"(a[1]), "r"(a[2]), "r"(a[3]), "r"(b0), "r"(b1));
}

__device__ __forceinline__ void split_bf(float v, __nv_bfloat16& h, __nv_bfloat16& l) {
    h = __float2bfloat16(v);
    l = __float2bfloat16(v - __bfloat162float(h));
}
__device__ __forceinline__ void split_hf(float v, __half& h, __half& l) {
    h = __float2half_rn(v);
    l = __float2half_rn(v - __half2float(h));
}
__device__ __forceinline__ uint32_t pack2(__nv_bfloat16 a, __nv_bfloat16 b) {
    __nv_bfloat162 t; t.x = a; t.y = b;
    return *reinterpret_cast<uint32_t*>(&t);
}
__device__ __forceinline__ uint32_t pack2h(__half a, __half b) {
    __half2 t; t.x = a; t.y = b;
    return *reinterpret_cast<uint32_t*>(&t);
}

// ============================================================
// fp32 -> bf16 hi/lo split of x (+ zero g_cnt piggyback)
// ============================================================
__global__ void conv_x_kernel(const float* __restrict__ x) {
    size_t i4 = (size_t)blockIdx.x * blockDim.x + threadIdx.x;
    if (i4 < NN) g_cnt[i4] = 0;
    if (i4 >= (size_t)NP * 64) return;
    float4 v = make_float4(0.f, 0.f, 0.f, 0.f);
    if (i4 < (size_t)NN * 64) v = __ldg(((const float4*)x) + i4);
    __nv_bfloat16 h0, l0, h1, l1, h2, l2, h3, l3;
    split_bf(v.x, h0, l0); split_bf(v.y, h1, l1);
    split_bf(v.z, h2, l2); split_bf(v.w, h3, l3);
    ((uint2*)g_xhi)[i4] = make_uint2(pack2(h0, h1), pack2(h2, h3));
    ((uint2*)g_xlo)[i4] = make_uint2(pack2(l0, l1), pack2(l2, l3));
}

// one kernel converts all four weight matrices
// W1 -> bf16 hi/lo, W2/W3/Wd1 -> fp16 hi/lo
__global__ void conv_w_all_kernel(const float* __restrict__ W1,
                                  const float* __restrict__ W2,
                                  const float* __restrict__ W3,
                                  const float* __restrict__ Wd1) {
    int i = blockIdx.x * blockDim.x + threadIdx.x;   // float4 index, 49152 total
    if (i < 16384) {
        float4 v = __ldg(((const float4*)W1) + i);
        __nv_bfloat16 h0, l0, h1, l1, h2, l2, h3, l3;
        split_bf(v.x, h0, l0); split_bf(v.y, h1, l1);
        split_bf(v.z, h2, l2); split_bf(v.w, h3, l3);
        ((uint2*)g_w1hi)[i] = make_uint2(pack2(h0, h1), pack2(h2, h3));
        ((uint2*)g_w1lo)[i] = make_uint2(pack2(l0, l1), pack2(l2, l3));
        return;
    }
    const float* w; __half *hi, *lo; int off;
    if (i < 24576)      { w = W2;  hi = g_w2hi;  lo = g_w2lo;  off = i - 16384; }
    else if (i < 32768) { w = W3;  hi = g_w3hi;  lo = g_w3lo;  off = i - 24576; }
    else if (i < 49152) { w = Wd1; hi = g_wd1hi; lo = g_wd1lo; off = i - 32768; }
    else return;
    float4 v = __ldg(((const float4*)w) + off);
    __half h0, l0, h1, l1, h2, l2, h3, l3;
    split_hf(v.x, h0, l0); split_hf(v.y, h1, l1);
    split_hf(v.z, h2, l2); split_hf(v.w, h3, l3);
    ((uint2*)hi)[off] = make_uint2(pack2h(h0, h1), pack2h(h2, h3));
    ((uint2*)lo)[off] = make_uint2(pack2h(l0, l1), pack2h(l2, l3));
}

// ============================================================
// CSR build (all serial on main stream — narrow kernels must not
// overlap occupancy-1 GEMMs: RF contention starves them)
// ============================================================
__global__ void detect_kernel(const int* __restrict__ ei) {
    int z = 1;
    for (int i = 0; i < 64; i++)
        if (ei[2 * i + 1] != 0) { z = 0; break; }
    g_is64 = z;
}

// count degrees directly from ei (no src/dst round trip)
__global__ void count_kernel(const int* __restrict__ ei) {
    int e = blockIdx.x * blockDim.x + threadIdx.x;
    if (e >= NE) return;
    int d = g_is64 ? __ldg(&ei[2 * ((size_t)NE + e)]) : __ldg(&ei[NE + e]);
    if ((unsigned)d < NN) atomicAdd(&g_cnt[d], 1);
}

__global__ void scan_kernel() {
    __shared__ int sd[1024];
    int t = threadIdx.x;
    const int PER = (NN + 1023) / 1024;   // 98
    int b = t * PER;
    int e = b + PER; if (e > NN) e = NN; if (b > NN) b = NN;
    int s = 0;
    for (int i = b; i < e; i++) s += g_cnt[i];
    sd[t] = s;
    __syncthreads();
    for (int off = 1; off < 1024; off <<= 1) {
        int v = (t >= off) ? sd[t - off] : 0;
        __syncthreads();
        sd[t] += v;
        __syncthreads();
    }
    int run = sd[t] - s;   // exclusive prefix
    for (int i = b; i < e; i++) {
        g_rowptr[i] = run;
        g_cursor[i] = run;
        run += g_cnt[i];
    }
    if (t == 1023) g_rowptr[NN] = run;
}

__global__ void fill_edges_kernel(const int* __restrict__ ei) {
    int e = blockIdx.x * blockDim.x + threadIdx.x;
    if (e >= NE) return;
    int s, d;
    if (g_is64) {
        s = __ldg(&ei[2 * e]);
        d = __ldg(&ei[2 * ((size_t)NE + e)]);
    } else {
        s = __ldg(&ei[e]);
        d = __ldg(&ei[NE + e]);
    }
    if ((unsigned)s < NN && (unsigned)d < NN) {
        int p = atomicAdd(&g_cursor[d], 1);
        g_colidx[p] = s;
    }
}

// ============================================================
// N=256 GEMM (layer-1 bf16 3-pass, final fp16 2-pass)
// CTA tile 128x256, 8 warps (2 row x 4 col), warp tile 64x64.
// ============================================================
static constexpr int SSTRIDE = 260;

template <int MODE>   // 0 = layer-1 (bf16 exact), 2 = final head (fp16)
struct GCfg {
    static constexpr bool BF   = (MODE == 0);
    static constexpr int OF_AL = 16384;
    static constexpr int OF_BH = BF ? 32768 : 16384;
    static constexpr int OF_BL = BF ? 65536 : 49152;
    static constexpr int STG   = BF ? 98304 : 81920;
    static constexpr int SMEM  = 2 * STG;
};

template <int MODE>
__device__ __forceinline__ void issue_chunk(
        uint32_t sbuf, int rowbase, int kb, int tid,
        const uint8_t* BloH, const uint8_t* BloL,
        const uint8_t* BupH, const uint8_t* BupL) {
    using C = GCfg<MODE>;
    for (int t = tid; t < 1024; t += 256) {
        int r = t >> 3, g = t & 7;
        uint32_t so = SW128((uint32_t)(r * 128 + g * 16));
        size_t ob = ((size_t)(rowbase + r) * D + kb + g * 8) * 2;
        if (C::BF) {
            cp16(sbuf + so,            (const uint8_t*)g_xhi + ob);
            cp16(sbuf + C::OF_AL + so, (const uint8_t*)g_xlo + ob);
        } else {
            cp16(sbuf + so,            (const uint8_t*)g_h + ob);
        }
    }
    for (int t = tid; t < 2048; t += 256) {
        int r = t >> 3, g = t & 7;
        uint32_t so = SW128((uint32_t)(r * 128 + g * 16));
        size_t ob = ((size_t)(r < 128 ? r : r - 128) * D + kb + g * 8) * 2;
        const uint8_t* sh = (r < 128 ? BloH : BupH) + ob;
        const uint8_t* sl = (r < 128 ? BloL : BupL) + ob;
        cp16(sbuf + C::OF_BH + so, sh);
        cp16(sbuf + C::OF_BL + so, sl);
    }
}

template <int MODE>
__global__ void __launch_bounds__(256, 1)
gemm_kernel(const float* __restrict__ bias, const float* __restrict__ wd2,
            const float* __restrict__ bd2, float* __restrict__ out) {
    using C = GCfg<MODE>;
    extern __shared__ char smem[];
    uint32_t sb = smem_u32(smem);
    int tid = threadIdx.x, wid = tid >> 5, lane = tid & 31;
    int rowbase = blockIdx.x * 128;
    int wrow = wid & 1;
    int wcol = wid >> 1;

    const uint8_t *BloH, *BloL, *BupH, *BupL;
    if (MODE == 0) {
        BloH = (const uint8_t*)g_w1hi;  BloL = (const uint8_t*)g_w1lo;
        BupH = (const uint8_t*)(g_w1hi + 128 * D);  BupL = (const uint8_t*)(g_w1lo + 128 * D);
    } else {
        BloH = (const uint8_t*)g_wd1hi; BloL = (const uint8_t*)g_wd1lo;
        BupH = (const uint8_t*)(g_wd1hi + 128 * D); BupL = (const uint8_t*)(g_wd1lo + 128 * D);
    }

    float c[4][8][4];
    #pragma unroll
    for (int mt = 0; mt < 4; mt++)
        #pragma unroll
        for (int nt = 0; nt < 8; nt++)
            #pragma unroll
            for (int q = 0; q < 4; q++) c[mt][nt][q] = 0.f;

    int q8 = lane >> 3, l8 = lane & 7;

    issue_chunk<MODE>(sb, rowbase, 0, tid, BloH, BloL, BupH, BupL);
    cp_commit();

    for (int ch = 0; ch < 4; ch++) {
        uint32_t buf = sb + (uint32_t)(ch & 1) * C::STG;
        if (ch < 3) {
            issue_chunk<MODE>(sb + (uint32_t)((ch + 1) & 1) * C::STG, rowbase,
                              (ch + 1) * 64, tid, BloH, BloL, BupH, BupL);
            cp_commit();
            cp_wait<1>();
        } else {
            cp_wait<0>();
        }
        __syncthreads();

        #pragma unroll
        for (int ks = 0; ks < 4; ks++) {
            uint32_t ah[4][4], al[4][4];
            #pragma unroll
            for (int mt = 0; mt < 4; mt++) {
                int row = wrow * 64 + mt * 16 + (q8 & 1) * 8 + l8;
                uint32_t off = SW128((uint32_t)(row * 128 + ks * 32 + (q8 >> 1) * 16));
                ldsm4(ah[mt], buf + off);
                if (C::BF) ldsm4(al[mt], buf + C::OF_AL + off);
            }
            uint32_t bh[4][4], bl[4][4];
            #pragma unroll
            for (int nt = 0; nt < 4; nt++) {
                int nrow = wcol * 64 + nt * 16 + ((q8 >> 1) & 1) * 8 + l8;
                uint32_t off = SW128((uint32_t)(nrow * 128 + ks * 32 + (q8 & 1) * 16));
                ldsm4(bh[nt], buf + C::OF_BH + off);
                ldsm4(bl[nt], buf + C::OF_BL + off);
            }
            #pragma unroll
            for (int mt = 0; mt < 4; mt++)
                #pragma unroll
                for (int nt = 0; nt < 4; nt++) {
                    if (C::BF) {
                        mma_bf16(c[mt][nt * 2],     ah[mt], bh[nt][0], bh[nt][1]);
                        mma_bf16(c[mt][nt * 2],     ah[mt], bl[nt][0], bl[nt][1]);
                        mma_bf16(c[mt][nt * 2],     al[mt], bh[nt][0], bh[nt][1]);
                        mma_bf16(c[mt][nt * 2 + 1], ah[mt], bh[nt][2], bh[nt][3]);
                        mma_bf16(c[mt][nt * 2 + 1], ah[mt], bl[nt][2], bl[nt][3]);
                        mma_bf16(c[mt][nt * 2 + 1], al[mt], bh[nt][2], bh[nt][3]);
                    } else {
                        mma_f16(c[mt][nt * 2],     ah[mt], bh[nt][0], bh[nt][1]);
                        mma_f16(c[mt][nt * 2],     ah[mt], bl[nt][0], bl[nt][1]);
                        mma_f16(c[mt][nt * 2 + 1], ah[mt], bh[nt][2], bh[nt][3]);
                        mma_f16(c[mt][nt * 2 + 1], ah[mt], bl[nt][2], bl[nt][3]);
                    }
                }
        }
        __syncthreads();
    }

    float* stage = reinterpret_cast<float*>(smem);
    #pragma unroll
    for (int mt = 0; mt < 4; mt++)
        #pragma unroll
        for (int nt = 0; nt < 8; nt++) {
            int r0  = wrow * 64 + mt * 16 + (lane >> 2);
            int col = wcol * 64 + nt * 8 + 2 * (lane & 3);
            float* p = stage + r0 * SSTRIDE + col;
            p[0] = c[mt][nt][0];
            p[1] = c[mt][nt][1];
            p[8 * SSTRIDE]     = c[mt][nt][2];
            p[8 * SSTRIDE + 1] = c[mt][nt][3];
        }
    __syncthreads();

    for (int r = wid; r < 128; r += 8) {
        int gr = rowbase + r;
        bool ok = gr < NN;
        const float* rowp = stage + r * SSTRIDE + lane * 8;
        int cb = lane * 8;

        if (MODE == 0) {
            float v[8];
            float ss = 0.f;
            #pragma unroll
            for (int j = 0; j < 8; j++) {
                v[j] = fmaxf(rowp[j] + __ldg(&bias[cb + j]), 0.f);
                ss += v[j] * v[j];
            }
            #pragma unroll
            for (int off = 16; off >= 1; off >>= 1)
                ss += __shfl_xor_sync(0xffffffffu, ss, off);
            float rn = rsqrtf(ss);
            if (ok) {
                __half h[8];
                #pragma unroll
                for (int j = 0; j < 8; j++) h[j] = __float2half_rn(v[j] * rn);
                *reinterpret_cast<uint4*>(g_h + (size_t)gr * D + cb) =
                    make_uint4(pack2h(h[0], h[1]), pack2h(h[2], h[3]),
                               pack2h(h[4], h[5]), pack2h(h[6], h[7]));
            }
        } else {
            float acc = 0.f;
            #pragma unroll
            for (int j = 0; j < 8; j++) {
                float vv = fmaxf(rowp[j] + __ldg(&bias[cb + j]), 0.f);
                acc += vv * __ldg(&wd2[cb + j]);
            }
            #pragma unroll
            for (int off = 16; off >= 1; off >>= 1)
                acc += __shfl_xor_sync(0xffffffffu, acc, off);
            if (lane == 0 && ok) out[gr] = acc + __ldg(bd2);
        }
    }
}

// ============================================================
// N=128 GEMM: CTA 128x128, 8 warps (4 row x 2 col), warp 32x64,
// fp16 A single + B hi/lo (2 passes). K chunked 64, 2-stage.
//  WHICH=0: B=W3 -> g_y raw     WHICH=1: B=W2 -> g_a relu(+bias)
// ============================================================
static constexpr int OF128_A  = 0;
static constexpr int OF128_BH = 16384;
static constexpr int OF128_BL = 32768;
static constexpr int STG128   = 49152;
static constexpr int SM128    = 2 * STG128;   // 96 KB
static constexpr int SSTR2    = 132;

template <int WHICH>
__global__ void __launch_bounds__(256, 1)
gemm128_kernel(const float* __restrict__ bias) {
    extern __shared__ char smem[];
    uint32_t sb = smem_u32(smem);
    int tid = threadIdx.x, wid = tid >> 5, lane = tid & 31;
    int rowbase = blockIdx.x * 128;
    int wrow = wid & 3;        // 4 strips of 32 rows
    int wcol = wid >> 2;       // 2 strips of 64 cols
    const uint8_t* BH = (const uint8_t*)(WHICH ? g_w2hi : g_w3hi);
    const uint8_t* BL = (const uint8_t*)(WHICH ? g_w2lo : g_w3lo);

    float c[2][8][4];
    #pragma unroll
    for (int mt = 0; mt < 2; mt++)
        #pragma unroll
        for (int nt = 0; nt < 8; nt++)
            #pragma unroll
            for (int q = 0; q < 4; q++) c[mt][nt][q] = 0.f;

    int q8 = lane >> 3, l8 = lane & 7;

    auto issue = [&](uint32_t sbuf, int kb) {
        for (int t = tid; t < 1024; t += 256) {
            int r = t >> 3, g = t & 7;
            uint32_t so = SW128((uint32_t)(r * 128 + g * 16));
            cp16(sbuf + OF128_A + so,
                 (const uint8_t*)g_h + ((size_t)(rowbase + r) * D + kb + g * 8) * 2);
            size_t ob = ((size_t)r * D + kb + g * 8) * 2;
            cp16(sbuf + OF128_BH + so, BH + ob);
            cp16(sbuf + OF128_BL + so, BL + ob);
        }
    };

    issue(sb, 0);
    cp_commit();

    for (int ch = 0; ch < 4; ch++) {
        uint32_t buf = sb + (uint32_t)(ch & 1) * STG128;
        if (ch < 3) {
            issue(sb + (uint32_t)((ch + 1) & 1) * STG128, (ch + 1) * 64);
            cp_commit();
            cp_wait<1>();
        } else {
            cp_wait<0>();
        }
        __syncthreads();

        #pragma unroll
        for (int ks = 0; ks < 4; ks++) {
            uint32_t a[2][4];
            #pragma unroll
            for (int mt = 0; mt < 2; mt++) {
                int row = wrow * 32 + mt * 16 + (q8 & 1) * 8 + l8;
                uint32_t off = SW128((uint32_t)(row * 128 + ks * 32 + (q8 >> 1) * 16));
                ldsm4(a[mt], buf + OF128_A + off);
            }
            uint32_t bh[4][4], bl[4][4];
            #pragma unroll
            for (int nt = 0; nt < 4; nt++) {
                int nrow = wcol * 64 + nt * 16 + ((q8 >> 1) & 1) * 8 + l8;
                uint32_t off = SW128((uint32_t)(nrow * 128 + ks * 32 + (q8 & 1) * 16));
                ldsm4(bh[nt], buf + OF128_BH + off);
                ldsm4(bl[nt], buf + OF128_BL + off);
            }
            #pragma unroll
            for (int mt = 0; mt < 2; mt++)
                #pragma unroll
                for (int nt = 0; nt < 4; nt++) {
                    mma_f16(c[mt][nt * 2],     a[mt], bh[nt][0], bh[nt][1]);
                    mma_f16(c[mt][nt * 2],     a[mt], bl[nt][0], bl[nt][1]);
                    mma_f16(c[mt][nt * 2 + 1], a[mt], bh[nt][2], bh[nt][3]);
                    mma_f16(c[mt][nt * 2 + 1], a[mt], bl[nt][2], bl[nt][3]);
                }
        }
        __syncthreads();
    }

    float* stage = reinterpret_cast<float*>(smem);
    #pragma unroll
    for (int mt = 0; mt < 2; mt++)
        #pragma unroll
        for (int nt = 0; nt < 8; nt++) {
            int r0  = wrow * 32 + mt * 16 + (lane >> 2);
            int col = wcol * 64 + nt * 8 + 2 * (lane & 3);
            float* p = stage + r0 * SSTR2 + col;
            p[0] = c[mt][nt][0];
            p[1] = c[mt][nt][1];
            p[8 * SSTR2]     = c[mt][nt][2];
            p[8 * SSTR2 + 1] = c[mt][nt][3];
        }
    __syncthreads();

    for (int r = wid; r < 128; r += 8) {
        int gr = rowbase + r;
        if (gr >= NN) continue;
        int cb = lane * 4;
        const float* rp = stage + r * SSTR2 + cb;
        float4 v;
        if (WHICH) {
            v.x = fmaxf(rp[0] + __ldg(&bias[cb + 0]), 0.f);
            v.y = fmaxf(rp[1] + __ldg(&bias[cb + 1]), 0.f);
            v.z = fmaxf(rp[2] + __ldg(&bias[cb + 2]), 0.f);
            v.w = fmaxf(rp[3] + __ldg(&bias[cb + 3]), 0.f);
            *reinterpret_cast<float4*>(g_a + (size_t)gr * DH + cb) = v;
        } else {
            v = make_float4(rp[0], rp[1], rp[2], rp[3]);
            *reinterpret_cast<float4*>(g_y + (size_t)gr * DH + cb) = v;
        }
    }
}

// ============================================================
// CSR gather-reduce: nm[n] = sum over src of y[src]  (warp/node)
// Wide grid — safe to overlap with gemm128 on the other stream.
// ============================================================
__global__ void agg_gather_kernel() {
    int gw = (blockIdx.x * blockDim.x + threadIdx.x) >> 5;
    int lane = threadIdx.x & 31;
    if (gw >= NN) return;
    int n = gw;
    int beg = __ldg(&g_rowptr[n]);
    int end = __ldg(&g_rowptr[n + 1]);

    float ax = 0.f, ay = 0.f, az = 0.f, aw = 0.f;
    int i = beg;
    for (; i + 4 <= end; i += 4) {
        int s0 = __ldg(&g_colidx[i]);
        int s1 = __ldg(&g_colidx[i + 1]);
        int s2 = __ldg(&g_colidx[i + 2]);
        int s3 = __ldg(&g_colidx[i + 3]);
        float4 v0 = __ldg(reinterpret_cast<const float4*>(g_y + (size_t)s0 * DH) + lane);
        float4 v1 = __ldg(reinterpret_cast<const float4*>(g_y + (size_t)s1 * DH) + lane);
        float4 v2 = __ldg(reinterpret_cast<const float4*>(g_y + (size_t)s2 * DH) + lane);
        float4 v3 = __ldg(reinterpret_cast<const float4*>(g_y + (size_t)s3 * DH) + lane);
        ax += v0.x + v1.x + v2.x + v3.x;
        ay += v0.y + v1.y + v2.y + v3.y;
        az += v0.z + v1.z + v2.z + v3.z;
        aw += v0.w + v1.w + v2.w + v3.w;
    }
    for (; i < end; i++) {
        int s = __ldg(&g_colidx[i]);
        float4 v = __ldg(reinterpret_cast<const float4*>(g_y + (size_t)s * DH) + lane);
        ax += v.x; ay += v.y; az += v.z; aw += v.w;
    }
    *(reinterpret_cast<float4*>(g_nm + (size_t)n * DH) + lane) =
        make_float4(ax, ay, az, aw);
}

// ============================================================
// Combine: h[n] = fp16(l2norm([a[n], relu(nm[n]+b3)]))   (warp/node)
// ============================================================
__global__ void combine_kernel(const float* __restrict__ b3) {
    int gw = (blockIdx.x * blockDim.x + threadIdx.x) >> 5;
    int lane = threadIdx.x & 31;
    if (gw >= NN) return;
    int n = gw;
    float4 nm = __ldg(reinterpret_cast<const float4*>(g_nm + (size_t)n * DH) + lane);
    float4 av = __ldg(reinterpret_cast<const float4*>(g_a + (size_t)n * DH) + lane);
    float4 bb = __ldg(reinterpret_cast<const float4*>(b3) + lane);
    float m0 = fmaxf(nm.x + bb.x, 0.f);
    float m1 = fmaxf(nm.y + bb.y, 0.f);
    float m2 = fmaxf(nm.z + bb.z, 0.f);
    float m3 = fmaxf(nm.w + bb.w, 0.f);

    float ss = av.x * av.x + av.y * av.y + av.z * av.z + av.w * av.w
             + m0 * m0 + m1 * m1 + m2 * m2 + m3 * m3;
    #pragma unroll
    for (int off = 16; off >= 1; off >>= 1)
        ss += __shfl_xor_sync(0xffffffffu, ss, off);
    float rn = rsqrtf(ss);

    size_t base = (size_t)n * D;
    *reinterpret_cast<uint2*>(g_h + base + lane * 4) =
        make_uint2(pack2h(__float2half_rn(av.x * rn), __float2half_rn(av.y * rn)),
                   pack2h(__float2half_rn(av.z * rn), __float2half_rn(av.w * rn)));
    *reinterpret_cast<uint2*>(g_h + base + 128 + lane * 4) =
        make_uint2(pack2h(__float2half_rn(m0 * rn), __float2half_rn(m1 * rn)),
                   pack2h(__float2half_rn(m2 * rn), __float2half_rn(m3 * rn)));
}

// ============================================================
// Host launcher — serial backbone; ONLY wide-grid overlap:
// per layer, agg_gather (main) || gemm128_a (s2)
// ============================================================
static cudaStream_t s2 = nullptr;
static cudaEvent_t evY0, evA0, evY1, evA1;

extern "C" void kernel_launch(void* const* d_in, const int* in_sizes, int n_in,
                              void* d_out, int out_size) {
    const float* x   = (const float*)d_in[0];
    const int*   ei  = (const int*)d_in[1];    // int32 or int64 (auto-detected)
    const float* W1  = (const float*)d_in[2];
    const float* b1  = (const float*)d_in[3];
    const float* W2  = (const float*)d_in[4];
    const float* b2  = (const float*)d_in[5];
    const float* W3  = (const float*)d_in[6];
    const float* b3  = (const float*)d_in[7];
    const float* Wd1 = (const float*)d_in[8];
    const float* bd1 = (const float*)d_in[9];
    const float* Wd2 = (const float*)d_in[10];
    const float* bd2 = (const float*)d_in[11];
    float* out = (float*)d_out;

    if (!s2) {
        cudaStreamCreateWithFlags(&s2, cudaStreamNonBlocking);
        cudaEventCreateWithFlags(&evY0, cudaEventDisableTiming);
        cudaEventCreateWithFlags(&evA0, cudaEventDisableTiming);
        cudaEventCreateWithFlags(&evY1, cudaEventDisableTiming);
        cudaEventCreateWithFlags(&evA1, cudaEventDisableTiming);
        cudaFuncSetAttribute(gemm_kernel<0>,  cudaFuncAttributeMaxDynamicSharedMemorySize, GCfg<0>::SMEM);
        cudaFuncSetAttribute(gemm_kernel<2>,  cudaFuncAttributeMaxDynamicSharedMemorySize, GCfg<2>::SMEM);
        cudaFuncSetAttribute(gemm128_kernel<0>, cudaFuncAttributeMaxDynamicSharedMemorySize, SM128);
        cudaFuncSetAttribute(gemm128_kernel<1>, cudaFuncAttributeMaxDynamicSharedMemorySize, SM128);
    }

    // ---- serial: conversions + CSR build (conv_x zeroes g_cnt)
    conv_x_kernel<<<(int)(((size_t)NP * 64 + 255) / 256), 256>>>(x);
    conv_w_all_kernel<<<192, 256>>>(W1, W2, W3, Wd1);
    detect_kernel<<<1, 1>>>(ei);
    count_kernel<<<(NE + 255) / 256, 256>>>(ei);
    scan_kernel<<<1, 1024>>>();
    fill_edges_kernel<<<(NE + 255) / 256, 256>>>(ei);

    // ---- layer 1: h = fp16(l2norm(relu(x @ W1^T + b1)))  [bf16 3-pass]
    gemm_kernel<0><<<NB128, 256, GCfg<0>::SMEM>>>(b1, nullptr, nullptr, nullptr);

    // ---- conv layer 1: gemm_y -> { gather(main) || gemm_a(s2) } -> combine
    gemm128_kernel<0><<<NB128, 256, SM128>>>(nullptr);
    cudaEventRecord(evY0, 0);
    cudaStreamWaitEvent(s2, evY0, 0);
    gemm128_kernel<1><<<NB128, 256, SM128, s2>>>(b2);
    cudaEventRecord(evA0, s2);
    agg_gather_kernel<<<(NN * 32 + 255) / 256, 256>>>();
    cudaStreamWaitEvent(0, evA0, 0);
    combine_kernel<<<(NN * 32 + 255) / 256, 256>>>(b3);

    // ---- conv layer 2
    gemm128_kernel<0><<<NB128, 256, SM128>>>(nullptr);
    cudaEventRecord(evY1, 0);
    cudaStreamWaitEvent(s2, evY1, 0);
    gemm128_kernel<1><<<NB128, 256, SM128, s2>>>(b2);
    cudaEventRecord(evA1, s2);
    agg_gather_kernel<<<(NN * 32 + 255) / 256, 256>>>();
    cudaStreamWaitEvent(0, evA1, 0);
    combine_kernel<<<(NN * 32 + 255) / 256, 256>>>(b3);

    // ---- head: out = relu(h @ Wd1^T + bd1) @ Wd2^T + bd2  [fp16 2-pass]
    gemm_kernel<2><<<NB128, 256, GCfg<2>::SMEM>>>(bd1, Wd2, bd2, out);
}

// round 9
// speedup vs baseline: 1.3459x; 1.0057x over previous
#include <cuda_runtime.h>
#include <cuda_bf16.h>
#include <cuda_fp16.h>
#include <cstdint>
#include <cstddef>

// ============================================================
// Problem constants
// ============================================================
#define NN   100000      // nodes
#define NE   1600000     // edges
#define NP   100096      // padded: 128*782
#define NB128 782        // GEMM row tiles (128 rows each)
#define D    256
#define DH   128

// ============================================================
// Device global scratch (no cudaMalloc allowed)
// ============================================================
__device__ __align__(256) __nv_bfloat16 g_xhi[(size_t)NP * D];   // layer-1 input hi
__device__ __align__(256) __nv_bfloat16 g_xlo[(size_t)NP * D];   // layer-1 input lo
__device__ __align__(256) __half g_h[(size_t)NP * D];            // activations (fp16)
__device__ __align__(256) float g_a[(size_t)NP * DH];   // relu(x@W2^T + b2)
__device__ __align__(256) float g_y[(size_t)NP * DH];   // x@W3^T (pre-aggregation)
__device__ __align__(256) __nv_bfloat16 g_w1hi[D * D],  g_w1lo[D * D];
__device__ __align__(256) __half g_w2hi[DH * D], g_w2lo[DH * D];
__device__ __align__(256) __half g_w3hi[DH * D], g_w3lo[DH * D];
__device__ __align__(256) __half g_wd1hi[D * D], g_wd1lo[D * D];
__device__ __align__(256) int g_rowptr[NN + 1];
__device__ __align__(256) int g_cursor[NN];
__device__ __align__(256) int g_cnt[NN];
__device__ __align__(256) int g_colidx[NE];
__device__ int g_is64;

// ============================================================
// Helpers
// ============================================================
__device__ __forceinline__ uint32_t smem_u32(const void* p) {
    uint32_t a;
    asm("{ .reg .u64 t; cvta.to.shared.u64 t, %1; cvt.u32.u64 %0, t; }"
        : "=r"(a) : "l"(p));
    return a;
}

#define SW128(o) ((o) ^ (((o) >> 3) & 0x70))

__device__ __forceinline__ void cp16(uint32_t dst, const void* src) {
    asm volatile("cp.async.cg.shared.global [%0], [%1], 16;" :: "r"(dst), "l"(src));
}
__device__ __forceinline__ void cp_commit() {
    asm volatile("cp.async.commit_group;" ::: "memory");
}
template <int N>
__device__ __forceinline__ void cp_wait() {
    asm volatile("cp.async.wait_group %0;" :: "n"(N) : "memory");
}

__device__ __forceinline__ void ldsm4(uint32_t* r, uint32_t addr) {
    asm volatile("ldmatrix.sync.aligned.m8n8.x4.shared.b16 {%0,%1,%2,%3}, [%4];"
        : "=r"(r[0]), "=r"(r[1]), "=r"(r[2]), "=r"(r[3]) : "r"(addr));
}

__device__ __forceinline__ void mma_bf16(float* c, const uint32_t* a,
                                         uint32_t b0, uint32_t b1) {
    asm volatile(
        "mma.sync.aligned.m16n8k16.row.col.f32.bf16.bf16.f32 "
        "{%0,%1,%2,%3}, {%4,%5,%6,%7}, {%8,%9}, {%0,%1,%2,%3};"
        : "+f"(c[0]), "+f"(c[1]), "+f"(c[2]), "+f"(c[3])
        : "r"(a[0]), "r"(a[1]), "r"(a[2]), "r"(a[3]), "r"(b0), "r"(b1));
}
__device__ __forceinline__ void mma_f16(float* c, const uint32_t* a,
                                        uint32_t b0, uint32_t b1) {
    asm volatile(
        "mma.sync.aligned.m16n8k16.row.col.f32.f16.f16.f32 "
        "{%0,%1,%2,%3}, {%4,%5,%6,%7}, {%8,%9}, {%0,%1,%2,%3};"
        : "+f"(c[0]), "+f"(c[1]), "+f"(c[2]), "+f"(c[3])
        : "r"(a[0]), "r"(a[1]), "r"(a[2]), "r"(a[3]), "r"(b0), "r"(b1));
}

__device__ __forceinline__ void split_bf(float v, __nv_bfloat16& h, __nv_bfloat16& l) {
    h = __float2bfloat16(v);
    l = __float2bfloat16(v - __bfloat162float(h));
}
__device__ __forceinline__ void split_hf(float v, __half& h, __half& l) {
    h = __float2half_rn(v);
    l = __float2half_rn(v - __half2float(h));
}
__device__ __forceinline__ uint32_t pack2(__nv_bfloat16 a, __nv_bfloat16 b) {
    __nv_bfloat162 t; t.x = a; t.y = b;
    return *reinterpret_cast<uint32_t*>(&t);
}
__device__ __forceinline__ uint32_t pack2h(__half a, __half b) {
    __half2 t; t.x = a; t.y = b;
    return *reinterpret_cast<uint32_t*>(&t);
}

// ============================================================
// fp32 -> bf16 hi/lo split of x (+ zero g_cnt piggyback)
// ============================================================
__global__ void conv_x_kernel(const float* __restrict__ x) {
    size_t i4 = (size_t)blockIdx.x * blockDim.x + threadIdx.x;
    if (i4 < NN) g_cnt[i4] = 0;
    if (i4 >= (size_t)NP * 64) return;
    float4 v = make_float4(0.f, 0.f, 0.f, 0.f);
    if (i4 < (size_t)NN * 64) v = __ldg(((const float4*)x) + i4);
    __nv_bfloat16 h0, l0, h1, l1, h2, l2, h3, l3;
    split_bf(v.x, h0, l0); split_bf(v.y, h1, l1);
    split_bf(v.z, h2, l2); split_bf(v.w, h3, l3);
    ((uint2*)g_xhi)[i4] = make_uint2(pack2(h0, h1), pack2(h2, h3));
    ((uint2*)g_xlo)[i4] = make_uint2(pack2(l0, l1), pack2(l2, l3));
}

// one kernel converts all four weight matrices
// W1 -> bf16 hi/lo, W2/W3/Wd1 -> fp16 hi/lo
__global__ void conv_w_all_kernel(const float* __restrict__ W1,
                                  const float* __restrict__ W2,
                                  const float* __restrict__ W3,
                                  const float* __restrict__ Wd1) {
    int i = blockIdx.x * blockDim.x + threadIdx.x;   // float4 index, 49152 total
    if (i < 16384) {
        float4 v = __ldg(((const float4*)W1) + i);
        __nv_bfloat16 h0, l0, h1, l1, h2, l2, h3, l3;
        split_bf(v.x, h0, l0); split_bf(v.y, h1, l1);
        split_bf(v.z, h2, l2); split_bf(v.w, h3, l3);
        ((uint2*)g_w1hi)[i] = make_uint2(pack2(h0, h1), pack2(h2, h3));
        ((uint2*)g_w1lo)[i] = make_uint2(pack2(l0, l1), pack2(l2, l3));
        return;
    }
    const float* w; __half *hi, *lo; int off;
    if (i < 24576)      { w = W2;  hi = g_w2hi;  lo = g_w2lo;  off = i - 16384; }
    else if (i < 32768) { w = W3;  hi = g_w3hi;  lo = g_w3lo;  off = i - 24576; }
    else if (i < 49152) { w = Wd1; hi = g_wd1hi; lo = g_wd1lo; off = i - 32768; }
    else return;
    float4 v = __ldg(((const float4*)w) + off);
    __half h0, l0, h1, l1, h2, l2, h3, l3;
    split_hf(v.x, h0, l0); split_hf(v.y, h1, l1);
    split_hf(v.z, h2, l2); split_hf(v.w, h3, l3);
    ((uint2*)hi)[off] = make_uint2(pack2h(h0, h1), pack2h(h2, h3));
    ((uint2*)lo)[off] = make_uint2(pack2h(l0, l1), pack2h(l2, l3));
}

// ============================================================
// CSR build (serial on main stream; reads edge_index directly)
// ============================================================
__global__ void detect_kernel(const int* __restrict__ ei) {
    int z = 1;
    for (int i = 0; i < 64; i++)
        if (ei[2 * i + 1] != 0) { z = 0; break; }
    g_is64 = z;
}

__global__ void count_kernel(const int* __restrict__ ei) {
    int e = blockIdx.x * blockDim.x + threadIdx.x;
    if (e >= NE) return;
    int d = g_is64 ? __ldg(&ei[2 * ((size_t)NE + e)]) : __ldg(&ei[NE + e]);
    if ((unsigned)d < NN) atomicAdd(&g_cnt[d], 1);
}

__global__ void scan_kernel() {
    __shared__ int sd[1024];
    int t = threadIdx.x;
    const int PER = (NN + 1023) / 1024;   // 98
    int b = t * PER;
    int e = b + PER; if (e > NN) e = NN; if (b > NN) b = NN;
    int s = 0;
    for (int i = b; i < e; i++) s += g_cnt[i];
    sd[t] = s;
    __syncthreads();
    for (int off = 1; off < 1024; off <<= 1) {
        int v = (t >= off) ? sd[t - off] : 0;
        __syncthreads();
        sd[t] += v;
        __syncthreads();
    }
    int run = sd[t] - s;   // exclusive prefix
    for (int i = b; i < e; i++) {
        g_rowptr[i] = run;
        g_cursor[i] = run;
        run += g_cnt[i];
    }
    if (t == 1023) g_rowptr[NN] = run;
}

__global__ void fill_edges_kernel(const int* __restrict__ ei) {
    int e = blockIdx.x * blockDim.x + threadIdx.x;
    if (e >= NE) return;
    int s, d;
    if (g_is64) {
        s = __ldg(&ei[2 * e]);
        d = __ldg(&ei[2 * ((size_t)NE + e)]);
    } else {
        s = __ldg(&ei[e]);
        d = __ldg(&ei[NE + e]);
    }
    if ((unsigned)s < NN && (unsigned)d < NN) {
        int p = atomicAdd(&g_cursor[d], 1);
        g_colidx[p] = s;
    }
}

// ============================================================
// N=256 GEMM: CTA tile 128x256, 8 warps (2 row x 4 col),
// warp tile 64x64, K chunked 64, 2-stage cp.async pipeline.
//  MODE 0: layer-1, bf16 3-pass exact -> relu(+b1), l2norm -> g_h
//  MODE 1: mid, fp16 2-pass -> cols[0:128) relu(+b2)->g_a ;
//                              cols[128:256) raw -> g_y
//  MODE 2: final, fp16 2-pass -> relu(+bd1) then dot wd2 -> out
// ============================================================
static constexpr int SSTRIDE = 260;

template <int MODE>
struct GCfg {
    static constexpr bool BF   = (MODE == 0);
    static constexpr int OF_AL = 16384;
    static constexpr int OF_BH = BF ? 32768 : 16384;
    static constexpr int OF_BL = BF ? 65536 : 49152;
    static constexpr int STG   = BF ? 98304 : 81920;
    static constexpr int SMEM  = 2 * STG;
};

template <int MODE>
__device__ __forceinline__ void issue_chunk(
        uint32_t sbuf, int rowbase, int kb, int tid,
        const uint8_t* BloH, const uint8_t* BloL,
        const uint8_t* BupH, const uint8_t* BupL) {
    using C = GCfg<MODE>;
    for (int t = tid; t < 1024; t += 256) {
        int r = t >> 3, g = t & 7;
        uint32_t so = SW128((uint32_t)(r * 128 + g * 16));
        size_t ob = ((size_t)(rowbase + r) * D + kb + g * 8) * 2;
        if (C::BF) {
            cp16(sbuf + so,            (const uint8_t*)g_xhi + ob);
            cp16(sbuf + C::OF_AL + so, (const uint8_t*)g_xlo + ob);
        } else {
            cp16(sbuf + so,            (const uint8_t*)g_h + ob);
        }
    }
    for (int t = tid; t < 2048; t += 256) {
        int r = t >> 3, g = t & 7;
        uint32_t so = SW128((uint32_t)(r * 128 + g * 16));
        size_t ob = ((size_t)(r < 128 ? r : r - 128) * D + kb + g * 8) * 2;
        const uint8_t* sh = (r < 128 ? BloH : BupH) + ob;
        const uint8_t* sl = (r < 128 ? BloL : BupL) + ob;
        cp16(sbuf + C::OF_BH + so, sh);
        cp16(sbuf + C::OF_BL + so, sl);
    }
}

template <int MODE>
__global__ void __launch_bounds__(256, 1)
gemm_kernel(const float* __restrict__ bias, const float* __restrict__ wd2,
            const float* __restrict__ bd2, float* __restrict__ out) {
    using C = GCfg<MODE>;
    extern __shared__ char smem[];
    uint32_t sb = smem_u32(smem);
    int tid = threadIdx.x, wid = tid >> 5, lane = tid & 31;
    int rowbase = blockIdx.x * 128;
    int wrow = wid & 1;
    int wcol = wid >> 1;

    const uint8_t *BloH, *BloL, *BupH, *BupL;
    if (MODE == 0) {
        BloH = (const uint8_t*)g_w1hi;  BloL = (const uint8_t*)g_w1lo;
        BupH = (const uint8_t*)(g_w1hi + 128 * D);  BupL = (const uint8_t*)(g_w1lo + 128 * D);
    } else if (MODE == 1) {
        BloH = (const uint8_t*)g_w2hi;  BloL = (const uint8_t*)g_w2lo;
        BupH = (const uint8_t*)g_w3hi;  BupL = (const uint8_t*)g_w3lo;
    } else {
        BloH = (const uint8_t*)g_wd1hi; BloL = (const uint8_t*)g_wd1lo;
        BupH = (const uint8_t*)(g_wd1hi + 128 * D); BupL = (const uint8_t*)(g_wd1lo + 128 * D);
    }

    float c[4][8][4];
    #pragma unroll
    for (int mt = 0; mt < 4; mt++)
        #pragma unroll
        for (int nt = 0; nt < 8; nt++)
            #pragma unroll
            for (int q = 0; q < 4; q++) c[mt][nt][q] = 0.f;

    int q8 = lane >> 3, l8 = lane & 7;

    issue_chunk<MODE>(sb, rowbase, 0, tid, BloH, BloL, BupH, BupL);
    cp_commit();

    for (int ch = 0; ch < 4; ch++) {
        uint32_t buf = sb + (uint32_t)(ch & 1) * C::STG;
        if (ch < 3) {
            issue_chunk<MODE>(sb + (uint32_t)((ch + 1) & 1) * C::STG, rowbase,
                              (ch + 1) * 64, tid, BloH, BloL, BupH, BupL);
            cp_commit();
            cp_wait<1>();
        } else {
            cp_wait<0>();
        }
        __syncthreads();

        #pragma unroll
        for (int ks = 0; ks < 4; ks++) {
            uint32_t ah[4][4], al[4][4];
            #pragma unroll
            for (int mt = 0; mt < 4; mt++) {
                int row = wrow * 64 + mt * 16 + (q8 & 1) * 8 + l8;
                uint32_t off = SW128((uint32_t)(row * 128 + ks * 32 + (q8 >> 1) * 16));
                ldsm4(ah[mt], buf + off);
                if (C::BF) ldsm4(al[mt], buf + C::OF_AL + off);
            }
            uint32_t bh[4][4], bl[4][4];
            #pragma unroll
            for (int nt = 0; nt < 4; nt++) {
                int nrow = wcol * 64 + nt * 16 + ((q8 >> 1) & 1) * 8 + l8;
                uint32_t off = SW128((uint32_t)(nrow * 128 + ks * 32 + (q8 & 1) * 16));
                ldsm4(bh[nt], buf + C::OF_BH + off);
                ldsm4(bl[nt], buf + C::OF_BL + off);
            }
            #pragma unroll
            for (int mt = 0; mt < 4; mt++)
                #pragma unroll
                for (int nt = 0; nt < 4; nt++) {
                    if (C::BF) {
                        mma_bf16(c[mt][nt * 2],     ah[mt], bh[nt][0], bh[nt][1]);
                        mma_bf16(c[mt][nt * 2],     ah[mt], bl[nt][0], bl[nt][1]);
                        mma_bf16(c[mt][nt * 2],     al[mt], bh[nt][0], bh[nt][1]);
                        mma_bf16(c[mt][nt * 2 + 1], ah[mt], bh[nt][2], bh[nt][3]);
                        mma_bf16(c[mt][nt * 2 + 1], ah[mt], bl[nt][2], bl[nt][3]);
                        mma_bf16(c[mt][nt * 2 + 1], al[mt], bh[nt][2], bh[nt][3]);
                    } else {
                        mma_f16(c[mt][nt * 2],     ah[mt], bh[nt][0], bh[nt][1]);
                        mma_f16(c[mt][nt * 2],     ah[mt], bl[nt][0], bl[nt][1]);
                        mma_f16(c[mt][nt * 2 + 1], ah[mt], bh[nt][2], bh[nt][3]);
                        mma_f16(c[mt][nt * 2 + 1], ah[mt], bl[nt][2], bl[nt][3]);
                    }
                }
        }
        __syncthreads();
    }

    // ---- stage accumulators into smem (overlays the pipeline buffers)
    float* stage = reinterpret_cast<float*>(smem);
    #pragma unroll
    for (int mt = 0; mt < 4; mt++)
        #pragma unroll
        for (int nt = 0; nt < 8; nt++) {
            int r0  = wrow * 64 + mt * 16 + (lane >> 2);
            int col = wcol * 64 + nt * 8 + 2 * (lane & 3);
            float* p = stage + r0 * SSTRIDE + col;
            p[0] = c[mt][nt][0];
            p[1] = c[mt][nt][1];
            p[8 * SSTRIDE]     = c[mt][nt][2];
            p[8 * SSTRIDE + 1] = c[mt][nt][3];
        }
    __syncthreads();

    // ---- row-wise fused epilogue: warp per row, lane owns 8 contiguous cols
    for (int r = wid; r < 128; r += 8) {
        int gr = rowbase + r;
        bool ok = gr < NN;
        const float* rowp = stage + r * SSTRIDE + lane * 8;
        int cb = lane * 8;

        if (MODE == 0) {
            float v[8];
            float ss = 0.f;
            #pragma unroll
            for (int j = 0; j < 8; j++) {
                v[j] = fmaxf(rowp[j] + __ldg(&bias[cb + j]), 0.f);
                ss += v[j] * v[j];
            }
            #pragma unroll
            for (int off = 16; off >= 1; off >>= 1)
                ss += __shfl_xor_sync(0xffffffffu, ss, off);
            float rn = rsqrtf(ss);
            if (ok) {
                __half h[8];
                #pragma unroll
                for (int j = 0; j < 8; j++) h[j] = __float2half_rn(v[j] * rn);
                *reinterpret_cast<uint4*>(g_h + (size_t)gr * D + cb) =
                    make_uint4(pack2h(h[0], h[1]), pack2h(h[2], h[3]),
                               pack2h(h[4], h[5]), pack2h(h[6], h[7]));
            }
        } else if (MODE == 1) {
            float v[8];
            if (lane < 16) {
                #pragma unroll
                for (int j = 0; j < 8; j++)
                    v[j] = fmaxf(rowp[j] + __ldg(&bias[cb + j]), 0.f);
                if (ok) {
                    float4* dst = reinterpret_cast<float4*>(g_a + (size_t)gr * DH + cb);
                    dst[0] = make_float4(v[0], v[1], v[2], v[3]);
                    dst[1] = make_float4(v[4], v[5], v[6], v[7]);
                }
            } else {
                #pragma unroll
                for (int j = 0; j < 8; j++) v[j] = rowp[j];
                if (ok) {
                    float4* dst = reinterpret_cast<float4*>(g_y + (size_t)gr * DH + (cb - 128));
                    dst[0] = make_float4(v[0], v[1], v[2], v[3]);
                    dst[1] = make_float4(v[4], v[5], v[6], v[7]);
                }
            }
        } else {
            float acc = 0.f;
            #pragma unroll
            for (int j = 0; j < 8; j++) {
                float vv = fmaxf(rowp[j] + __ldg(&bias[cb + j]), 0.f);
                acc += vv * __ldg(&wd2[cb + j]);
            }
            #pragma unroll
            for (int off = 16; off >= 1; off >>= 1)
                acc += __shfl_xor_sync(0xffffffffu, acc, off);
            if (lane == 0 && ok) out[gr] = acc + __ldg(bd2);
        }
    }
}

// ============================================================
// Fused CSR gather-reduce + bias + relu + l2norm + fp16 store
// One warp per dst node; lane owns 4 cols of each 128-wide half.
// Gather loop unrolled x8 (MLP) with x4/x1 residual.
// ============================================================
__global__ void agg_combine_kernel(const float* __restrict__ b3) {
    int gw = (blockIdx.x * blockDim.x + threadIdx.x) >> 5;
    int lane = threadIdx.x & 31;
    if (gw >= NN) return;
    int n = gw;
    int beg = __ldg(&g_rowptr[n]);
    int end = __ldg(&g_rowptr[n + 1]);

    float ax = 0.f, ay = 0.f, az = 0.f, aw = 0.f;
    int i = beg;
    for (; i + 8 <= end; i += 8) {
        int s0 = __ldg(&g_colidx[i]);
        int s1 = __ldg(&g_colidx[i + 1]);
        int s2 = __ldg(&g_colidx[i + 2]);
        int s3 = __ldg(&g_colidx[i + 3]);
        int s4 = __ldg(&g_colidx[i + 4]);
        int s5 = __ldg(&g_colidx[i + 5]);
        int s6 = __ldg(&g_colidx[i + 6]);
        int s7 = __ldg(&g_colidx[i + 7]);
        float4 v0 = __ldg(reinterpret_cast<const float4*>(g_y + (size_t)s0 * DH) + lane);
        float4 v1 = __ldg(reinterpret_cast<const float4*>(g_y + (size_t)s1 * DH) + lane);
        float4 v2 = __ldg(reinterpret_cast<const float4*>(g_y + (size_t)s2 * DH) + lane);
        float4 v3 = __ldg(reinterpret_cast<const float4*>(g_y + (size_t)s3 * DH) + lane);
        float4 v4 = __ldg(reinterpret_cast<const float4*>(g_y + (size_t)s4 * DH) + lane);
        float4 v5 = __ldg(reinterpret_cast<const float4*>(g_y + (size_t)s5 * DH) + lane);
        float4 v6 = __ldg(reinterpret_cast<const float4*>(g_y + (size_t)s6 * DH) + lane);
        float4 v7 = __ldg(reinterpret_cast<const float4*>(g_y + (size_t)s7 * DH) + lane);
        ax += ((v0.x + v1.x) + (v2.x + v3.x)) + ((v4.x + v5.x) + (v6.x + v7.x));
        ay += ((v0.y + v1.y) + (v2.y + v3.y)) + ((v4.y + v5.y) + (v6.y + v7.y));
        az += ((v0.z + v1.z) + (v2.z + v3.z)) + ((v4.z + v5.z) + (v6.z + v7.z));
        aw += ((v0.w + v1.w) + (v2.w + v3.w)) + ((v4.w + v5.w) + (v6.w + v7.w));
    }
    for (; i + 4 <= end; i += 4) {
        int s0 = __ldg(&g_colidx[i]);
        int s1 = __ldg(&g_colidx[i + 1]);
        int s2 = __ldg(&g_colidx[i + 2]);
        int s3 = __ldg(&g_colidx[i + 3]);
        float4 v0 = __ldg(reinterpret_cast<const float4*>(g_y + (size_t)s0 * DH) + lane);
        float4 v1 = __ldg(reinterpret_cast<const float4*>(g_y + (size_t)s1 * DH) + lane);
        float4 v2 = __ldg(reinterpret_cast<const float4*>(g_y + (size_t)s2 * DH) + lane);
        float4 v3 = __ldg(reinterpret_cast<const float4*>(g_y + (size_t)s3 * DH) + lane);
        ax += (v0.x + v1.x) + (v2.x + v3.x);
        ay += (v0.y + v1.y) + (v2.y + v3.y);
        az += (v0.z + v1.z) + (v2.z + v3.z);
        aw += (v0.w + v1.w) + (v2.w + v3.w);
    }
    for (; i < end; i++) {
        int s = __ldg(&g_colidx[i]);
        float4 v = __ldg(reinterpret_cast<const float4*>(g_y + (size_t)s * DH) + lane);
        ax += v.x; ay += v.y; az += v.z; aw += v.w;
    }

    float4 av = __ldg(reinterpret_cast<const float4*>(g_a + (size_t)n * DH) + lane);
    float4 bb = __ldg(reinterpret_cast<const float4*>(b3) + lane);
    float m0 = fmaxf(ax + bb.x, 0.f);
    float m1 = fmaxf(ay + bb.y, 0.f);
    float m2 = fmaxf(az + bb.z, 0.f);
    float m3 = fmaxf(aw + bb.w, 0.f);

    float ss = av.x * av.x + av.y * av.y + av.z * av.z + av.w * av.w
             + m0 * m0 + m1 * m1 + m2 * m2 + m3 * m3;
    #pragma unroll
    for (int off = 16; off >= 1; off >>= 1)
        ss += __shfl_xor_sync(0xffffffffu, ss, off);
    float rn = rsqrtf(ss);

    size_t base = (size_t)n * D;
    *reinterpret_cast<uint2*>(g_h + base + lane * 4) =
        make_uint2(pack2h(__float2half_rn(av.x * rn), __float2half_rn(av.y * rn)),
                   pack2h(__float2half_rn(av.z * rn), __float2half_rn(av.w * rn)));
    *reinterpret_cast<uint2*>(g_h + base + 128 + lane * 4) =
        make_uint2(pack2h(__float2half_rn(m0 * rn), __float2half_rn(m1 * rn)),
                   pack2h(__float2half_rn(m2 * rn), __float2half_rn(m3 * rn)));
}

// ============================================================
// Host launcher — single stream, fully serial (overlap falsified
// in R7/R8: occupancy-1 GEMMs starve/negate concurrent work)
// ============================================================
extern "C" void kernel_launch(void* const* d_in, const int* in_sizes, int n_in,
                              void* d_out, int out_size) {
    const float* x   = (const float*)d_in[0];
    const int*   ei  = (const int*)d_in[1];    // int32 or int64 (auto-detected)
    const float* W1  = (const float*)d_in[2];
    const float* b1  = (const float*)d_in[3];
    const float* W2  = (const float*)d_in[4];
    const float* b2  = (const float*)d_in[5];
    const float* W3  = (const float*)d_in[6];
    const float* b3  = (const float*)d_in[7];
    const float* Wd1 = (const float*)d_in[8];
    const float* bd1 = (const float*)d_in[9];
    const float* Wd2 = (const float*)d_in[10];
    const float* bd2 = (const float*)d_in[11];
    float* out = (float*)d_out;

    cudaFuncSetAttribute(gemm_kernel<0>, cudaFuncAttributeMaxDynamicSharedMemorySize, GCfg<0>::SMEM);
    cudaFuncSetAttribute(gemm_kernel<1>, cudaFuncAttributeMaxDynamicSharedMemorySize, GCfg<1>::SMEM);
    cudaFuncSetAttribute(gemm_kernel<2>, cudaFuncAttributeMaxDynamicSharedMemorySize, GCfg<2>::SMEM);

    // conversions (conv_x zeroes g_cnt) + CSR build
    conv_x_kernel<<<(int)(((size_t)NP * 64 + 255) / 256), 256>>>(x);
    conv_w_all_kernel<<<192, 256>>>(W1, W2, W3, Wd1);
    detect_kernel<<<1, 1>>>(ei);
    count_kernel<<<(NE + 255) / 256, 256>>>(ei);
    scan_kernel<<<1, 1024>>>();
    fill_edges_kernel<<<(NE + 255) / 256, 256>>>(ei);

    // layer 1: h = fp16(l2norm(relu(x @ W1^T + b1)))   [bf16 3-pass]
    gemm_kernel<0><<<NB128, 256, GCfg<0>::SMEM>>>(b1, nullptr, nullptr, nullptr);

    // 2 conv layers  [fp16 2-pass fused N=256 GEMM + fused aggregation]
    for (int l = 0; l < 2; l++) {
        gemm_kernel<1><<<NB128, 256, GCfg<1>::SMEM>>>(b2, nullptr, nullptr, nullptr);
        agg_combine_kernel<<<(NN * 32 + 255) / 256, 256>>>(b3);
    }

    // head: out = relu(h @ Wd1^T + bd1) @ Wd2^T + bd2   [fp16 2-pass]
    gemm_kernel<2><<<NB128, 256, GCfg<2>::SMEM>>>(bd1, Wd2, bd2, out);
}

// round 10
// speedup vs baseline: 1.3782x; 1.0240x over previous
#include <cuda_runtime.h>
#include <cuda_bf16.h>
#include <cuda_fp16.h>
#include <cstdint>
#include <cstddef>

// ============================================================
// Problem constants
// ============================================================
#define NN   100000      // nodes
#define NE   1600000     // edges
#define NP   100096      // padded: 128*782
#define NB128 782        // GEMM row tiles (128 rows each)
#define D    256
#define DH   128

// ============================================================
// Device global scratch (no cudaMalloc allowed)
// ============================================================
__device__ __align__(256) __half g_h[(size_t)NP * D];   // activations (fp16)
__device__ __align__(256) float g_a[(size_t)NP * DH];   // relu(x@W2^T + b2)
__device__ __align__(256) float g_y[(size_t)NP * DH];   // x@W3^T (pre-aggregation)
__device__ __align__(256) __nv_bfloat16 g_w1hi[D * D],  g_w1lo[D * D];
__device__ __align__(256) __half g_w2hi[DH * D], g_w2lo[DH * D];   // lo scaled x1024
__device__ __align__(256) __half g_w3hi[DH * D], g_w3lo[DH * D];   // lo scaled x1024
__device__ __align__(256) __half g_wd1hi[D * D], g_wd1lo[D * D];   // lo scaled x1024
__device__ __align__(256) int g_rowptr[NN + 1];
__device__ __align__(256) int g_cursor[NN];
__device__ __align__(256) int g_cnt[NN];
__device__ __align__(256) int g_colidx[NE];
__device__ int g_is64;

// ============================================================
// Helpers
// ============================================================
__device__ __forceinline__ uint32_t smem_u32(const void* p) {
    uint32_t a;
    asm("{ .reg .u64 t; cvta.to.shared.u64 t, %1; cvt.u32.u64 %0, t; }"
        : "=r"(a) : "l"(p));
    return a;
}

#define SW128(o) ((o) ^ (((o) >> 3) & 0x70))

__device__ __forceinline__ void cp16(uint32_t dst, const void* src) {
    asm volatile("cp.async.cg.shared.global [%0], [%1], 16;" :: "r"(dst), "l"(src));
}
__device__ __forceinline__ void cp_commit() {
    asm volatile("cp.async.commit_group;" ::: "memory");
}
template <int N>
__device__ __forceinline__ void cp_wait() {
    asm volatile("cp.async.wait_group %0;" :: "n"(N) : "memory");
}

__device__ __forceinline__ void ldsm4(uint32_t* r, uint32_t addr) {
    asm volatile("ldmatrix.sync.aligned.m8n8.x4.shared.b16 {%0,%1,%2,%3}, [%4];"
        : "=r"(r[0]), "=r"(r[1]), "=r"(r[2]), "=r"(r[3]) : "r"(addr));
}

__device__ __forceinline__ void mma_bf16(float* c, const uint32_t* a,
                                         uint32_t b0, uint32_t b1) {
    asm volatile(
        "mma.sync.aligned.m16n8k16.row.col.f32.bf16.bf16.f32 "
        "{%0,%1,%2,%3}, {%4,%5,%6,%7}, {%8,%9}, {%0,%1,%2,%3};"
        : "+f"(c[0]), "+f"(c[1]), "+f"(c[2]), "+f"(c[3])
        : "r"(a[0]), "r"(a[1]), "r"(a[2]), "r"(a[3]), "r"(b0), "r"(b1));
}
__device__ __forceinline__ void mma_f16(float* c, const uint32_t* a,
                                        uint32_t b0, uint32_t b1) {
    asm volatile(
        "mma.sync.aligned.m16n8k16.row.col.f32.f16.f16.f32 "
        "{%0,%1,%2,%3}, {%4,%5,%6,%7}, {%8,%9}, {%0,%1,%2,%3};"
        : "+f"(c[0]), "+f"(c[1]), "+f"(c[2]), "+f"(c[3])
        : "r"(a[0]), "r"(a[1]), "r"(a[2]), "r"(a[3]), "r"(b0), "r"(b1));
}
// f16 accumulator variant (2 f16x2 regs) — used for the lo pass
__device__ __forceinline__ void mma_f16h(uint32_t* c2, const uint32_t* a,
                                         uint32_t b0, uint32_t b1) {
    asm volatile(
        "mma.sync.aligned.m16n8k16.row.col.f16.f16.f16.f16 "
        "{%0,%1}, {%2,%3,%4,%5}, {%6,%7}, {%0,%1};"
        : "+r"(c2[0]), "+r"(c2[1])
        : "r"(a[0]), "r"(a[1]), "r"(a[2]), "r"(a[3]), "r"(b0), "r"(b1));
}

__device__ __forceinline__ void split_bf(float v, __nv_bfloat16& h, __nv_bfloat16& l) {
    h = __float2bfloat16(v);
    l = __float2bfloat16(v - __bfloat162float(h));
}
__device__ __forceinline__ uint32_t pack2(__nv_bfloat16 a, __nv_bfloat16 b) {
    __nv_bfloat162 t; t.x = a; t.y = b;
    return *reinterpret_cast<uint32_t*>(&t);
}
__device__ __forceinline__ uint32_t pack2h(__half a, __half b) {
    __half2 t; t.x = a; t.y = b;
    return *reinterpret_cast<uint32_t*>(&t);
}

// ============================================================
// Weight conversion (one kernel) + zero g_cnt piggyback
// W1 -> bf16 hi/lo ; W2/W3/Wd1 -> fp16 hi + (lo * 1024) fp16
// ============================================================
__global__ void conv_w_all_kernel(const float* __restrict__ W1,
                                  const float* __restrict__ W2,
                                  const float* __restrict__ W3,
                                  const float* __restrict__ Wd1) {
    int i = blockIdx.x * blockDim.x + threadIdx.x;
    if (i < NN) g_cnt[i] = 0;             // zero CSR histogram (grid covers NN)
    if (i >= 49152) return;
    if (i < 16384) {
        float4 v = __ldg(((const float4*)W1) + i);
        __nv_bfloat16 h0, l0, h1, l1, h2, l2, h3, l3;
        split_bf(v.x, h0, l0); split_bf(v.y, h1, l1);
        split_bf(v.z, h2, l2); split_bf(v.w, h3, l3);
        ((uint2*)g_w1hi)[i] = make_uint2(pack2(h0, h1), pack2(h2, h3));
        ((uint2*)g_w1lo)[i] = make_uint2(pack2(l0, l1), pack2(l2, l3));
        return;
    }
    const float* w; __half *hi, *lo; int off;
    if (i < 24576)      { w = W2;  hi = g_w2hi;  lo = g_w2lo;  off = i - 16384; }
    else if (i < 32768) { w = W3;  hi = g_w3hi;  lo = g_w3lo;  off = i - 24576; }
    else                { w = Wd1; hi = g_wd1hi; lo = g_wd1lo; off = i - 32768; }
    float4 v = __ldg(((const float4*)w) + off);
    __half h0 = __float2half_rn(v.x), h1 = __float2half_rn(v.y);
    __half h2 = __float2half_rn(v.z), h3 = __float2half_rn(v.w);
    // residual scaled by 2^10 (exact) to keep lo plane in fp16 normal range
    __half l0 = __float2half_rn((v.x - __half2float(h0)) * 1024.0f);
    __half l1 = __float2half_rn((v.y - __half2float(h1)) * 1024.0f);
    __half l2 = __float2half_rn((v.z - __half2float(h2)) * 1024.0f);
    __half l3 = __float2half_rn((v.w - __half2float(h3)) * 1024.0f);
    ((uint2*)hi)[off] = make_uint2(pack2h(h0, h1), pack2h(h2, h3));
    ((uint2*)lo)[off] = make_uint2(pack2h(l0, l1), pack2h(l2, l3));
}

// ============================================================
// CSR build (serial; reads edge_index directly)
// ============================================================
__global__ void detect_kernel(const int* __restrict__ ei) {
    int z = 1;
    for (int i = 0; i < 64; i++)
        if (ei[2 * i + 1] != 0) { z = 0; break; }
    g_is64 = z;
}

__global__ void count_kernel(const int* __restrict__ ei) {
    int e = blockIdx.x * blockDim.x + threadIdx.x;
    if (e >= NE) return;
    int d = g_is64 ? __ldg(&ei[2 * ((size_t)NE + e)]) : __ldg(&ei[NE + e]);
    if ((unsigned)d < NN) atomicAdd(&g_cnt[d], 1);
}

__global__ void scan_kernel() {
    __shared__ int sd[1024];
    int t = threadIdx.x;
    const int PER = (NN + 1023) / 1024;   // 98
    int b = t * PER;
    int e = b + PER; if (e > NN) e = NN; if (b > NN) b = NN;
    int s = 0;
    for (int i = b; i < e; i++) s += g_cnt[i];
    sd[t] = s;
    __syncthreads();
    for (int off = 1; off < 1024; off <<= 1) {
        int v = (t >= off) ? sd[t - off] : 0;
        __syncthreads();
        sd[t] += v;
        __syncthreads();
    }
    int run = sd[t] - s;   // exclusive prefix
    for (int i = b; i < e; i++) {
        g_rowptr[i] = run;
        g_cursor[i] = run;
        run += g_cnt[i];
    }
    if (t == 1023) g_rowptr[NN] = run;
}

__global__ void fill_edges_kernel(const int* __restrict__ ei) {
    int e = blockIdx.x * blockDim.x + threadIdx.x;
    if (e >= NE) return;
    int s, d;
    if (g_is64) {
        s = __ldg(&ei[2 * e]);
        d = __ldg(&ei[2 * ((size_t)NE + e)]);
    } else {
        s = __ldg(&ei[e]);
        d = __ldg(&ei[NE + e]);
    }
    if ((unsigned)s < NN && (unsigned)d < NN) {
        int p = atomicAdd(&g_cursor[d], 1);
        g_colidx[p] = s;
    }
}

// ============================================================
// Layer-1 GEMM (bf16 3-pass exact) with FUSED x fp32->bf16 hi/lo
// conversion. CTA 128x256, 8 warps (2x4), warp tile 64x64.
// smem: AH 16K | AL 16K | XRAW 32K | BH0 32K | BL0 32K | BH1 32K | BL1 32K
// ============================================================
static constexpr int G0_AH  = 0;
static constexpr int G0_AL  = 16384;
static constexpr int G0_XR  = 32768;
static constexpr int G0_B0  = 65536;     // BH0; BL0 at +32768
static constexpr int G0_B1  = 131072;    // BH1; BL1 at +32768
static constexpr int G0_SMEM = 196608;
static constexpr int SSTRIDE = 260;

__global__ void __launch_bounds__(256, 1)
gemm0_kernel(const float* __restrict__ x, const float* __restrict__ bias) {
    extern __shared__ char smem[];
    uint32_t sb = smem_u32(smem);
    int tid = threadIdx.x, wid = tid >> 5, lane = tid & 31;
    int rowbase = blockIdx.x * 128;
    int wrow = wid & 1;
    int wcol = wid >> 1;

    float c[4][8][4];
    #pragma unroll
    for (int mt = 0; mt < 4; mt++)
        #pragma unroll
        for (int nt = 0; nt < 8; nt++)
            #pragma unroll
            for (int q = 0; q < 4; q++) c[mt][nt][q] = 0.f;

    int q8 = lane >> 3, l8 = lane & 7;

    auto issue_x = [&](int kb) {
        // 128 rows x 64 f32 (256B/row) = 2048 16B granules
        for (int t = tid; t < 2048; t += 256) {
            int r = t >> 4, g = t & 15;
            int gr = rowbase + r; if (gr >= NN) gr = NN - 1;   // pad rows: garbage, masked later
            cp16(sb + G0_XR + (uint32_t)(r * 256 + g * 16),
                 x + (size_t)gr * D + kb + g * 4);
        }
    };
    auto issue_B = [&](int st, int kb) {
        uint32_t bh = sb + (st ? G0_B1 : G0_B0);
        for (int t = tid; t < 2048; t += 256) {
            int r = t >> 3, g = t & 7;
            uint32_t so = SW128((uint32_t)(r * 128 + g * 16));
            size_t ob = ((size_t)r * D + kb + g * 8) * 2;
            cp16(bh + so,         (const uint8_t*)g_w1hi + ob);
            cp16(bh + 32768 + so, (const uint8_t*)g_w1lo + ob);
        }
    };

    issue_x(0); issue_B(0, 0); cp_commit();

    for (int ch = 0; ch < 4; ch++) {
        cp_wait<0>();
        __syncthreads();
        // convert XRAW (f32) -> AH/AL (bf16 hi/lo, SW128)
        #pragma unroll
        for (int j = 0; j < 8; j++) {
            int idx = tid + j * 256;                 // float4 index, 2048 total
            float4 v = reinterpret_cast<const float4*>(smem + G0_XR)[idx];
            int r = idx >> 4, g4 = idx & 15;
            uint32_t bo = (uint32_t)(r * 128 + g4 * 8);
            uint32_t so = bo ^ ((bo >> 3) & 0x70);
            __nv_bfloat16 h0, l0, h1, l1, h2, l2, h3, l3;
            split_bf(v.x, h0, l0); split_bf(v.y, h1, l1);
            split_bf(v.z, h2, l2); split_bf(v.w, h3, l3);
            *reinterpret_cast<uint2*>(smem + G0_AH + so) = make_uint2(pack2(h0, h1), pack2(h2, h3));
            *reinterpret_cast<uint2*>(smem + G0_AL + so) = make_uint2(pack2(l0, l1), pack2(l2, l3));
        }
        __syncthreads();
        if (ch < 3) { issue_x((ch + 1) * 64); issue_B((ch + 1) & 1, (ch + 1) * 64); cp_commit(); }

        uint32_t bbh = sb + ((ch & 1) ? G0_B1 : G0_B0);
        #pragma unroll
        for (int ks = 0; ks < 4; ks++) {
            uint32_t ah[4][4], al[4][4];
            #pragma unroll
            for (int mt = 0; mt < 4; mt++) {
                int row = wrow * 64 + mt * 16 + (q8 & 1) * 8 + l8;
                uint32_t off = SW128((uint32_t)(row * 128 + ks * 32 + (q8 >> 1) * 16));
                ldsm4(ah[mt], sb + G0_AH + off);
                ldsm4(al[mt], sb + G0_AL + off);
            }
            #pragma unroll
            for (int nt = 0; nt < 4; nt++) {
                int nrow = wcol * 64 + nt * 16 + ((q8 >> 1) & 1) * 8 + l8;
                uint32_t off = SW128((uint32_t)(nrow * 128 + ks * 32 + (q8 & 1) * 16));
                uint32_t bh[4], bl[4];
                ldsm4(bh, bbh + off);
                ldsm4(bl, bbh + 32768 + off);
                #pragma unroll
                for (int mt = 0; mt < 4; mt++) {
                    mma_bf16(c[mt][nt * 2],     ah[mt], bh[0], bh[1]);
                    mma_bf16(c[mt][nt * 2],     ah[mt], bl[0], bl[1]);
                    mma_bf16(c[mt][nt * 2],     al[mt], bh[0], bh[1]);
                    mma_bf16(c[mt][nt * 2 + 1], ah[mt], bh[2], bh[3]);
                    mma_bf16(c[mt][nt * 2 + 1], ah[mt], bl[2], bl[3]);
                    mma_bf16(c[mt][nt * 2 + 1], al[mt], bh[2], bh[3]);
                }
            }
        }
        __syncthreads();
    }

    // ---- stage accumulators, fused epilogue (relu+b1, l2norm, fp16 store)
    float* stage = reinterpret_cast<float*>(smem);
    #pragma unroll
    for (int mt = 0; mt < 4; mt++)
        #pragma unroll
        for (int nt = 0; nt < 8; nt++) {
            int r0  = wrow * 64 + mt * 16 + (lane >> 2);
            int col = wcol * 64 + nt * 8 + 2 * (lane & 3);
            float* p = stage + r0 * SSTRIDE + col;
            p[0] = c[mt][nt][0];
            p[1] = c[mt][nt][1];
            p[8 * SSTRIDE]     = c[mt][nt][2];
            p[8 * SSTRIDE + 1] = c[mt][nt][3];
        }
    __syncthreads();

    for (int r = wid; r < 128; r += 8) {
        int gr = rowbase + r;
        bool ok = gr < NN;
        const float* rowp = stage + r * SSTRIDE + lane * 8;
        int cb = lane * 8;
        float v[8];
        float ss = 0.f;
        #pragma unroll
        for (int j = 0; j < 8; j++) {
            v[j] = fmaxf(rowp[j] + __ldg(&bias[cb + j]), 0.f);
            ss += v[j] * v[j];
        }
        #pragma unroll
        for (int off = 16; off >= 1; off >>= 1)
            ss += __shfl_xor_sync(0xffffffffu, ss, off);
        float rn = rsqrtf(ss);
        if (ok) {
            __half h[8];
            #pragma unroll
            for (int j = 0; j < 8; j++) h[j] = __float2half_rn(v[j] * rn);
            *reinterpret_cast<uint4*>(g_h + (size_t)gr * D + cb) =
                make_uint4(pack2h(h[0], h[1]), pack2h(h[2], h[3]),
                           pack2h(h[4], h[5]), pack2h(h[6], h[7]));
        }
    }
}

// ============================================================
// fp16 N=256 GEMM (mid MODE 1, final MODE 2): CTA 128x256,
// hi pass f32-acc + lo pass f16-acc (lo plane pre-scaled x1024).
// ============================================================
static constexpr int F_OF_BH = 16384;
static constexpr int F_OF_BL = 49152;
static constexpr int F_STG   = 81920;
static constexpr int F_SMEM  = 2 * F_STG;

template <int MODE>   // 1 = mid ([W2;W3]) , 2 = final (Wd1)
__global__ void __launch_bounds__(256, 1)
gemm_kernel(const float* __restrict__ bias, const float* __restrict__ wd2,
            const float* __restrict__ bd2, float* __restrict__ out) {
    extern __shared__ char smem[];
    uint32_t sb = smem_u32(smem);
    int tid = threadIdx.x, wid = tid >> 5, lane = tid & 31;
    int rowbase = blockIdx.x * 128;
    int wrow = wid & 1;
    int wcol = wid >> 1;

    const uint8_t *BloH, *BloL, *BupH, *BupL;
    if (MODE == 1) {
        BloH = (const uint8_t*)g_w2hi;  BloL = (const uint8_t*)g_w2lo;
        BupH = (const uint8_t*)g_w3hi;  BupL = (const uint8_t*)g_w3lo;
    } else {
        BloH = (const uint8_t*)g_wd1hi; BloL = (const uint8_t*)g_wd1lo;
        BupH = (const uint8_t*)(g_wd1hi + 128 * D); BupL = (const uint8_t*)(g_wd1lo + 128 * D);
    }

    float c[4][8][4];
    uint32_t c16[4][8][2];
    #pragma unroll
    for (int mt = 0; mt < 4; mt++)
        #pragma unroll
        for (int nt = 0; nt < 8; nt++) {
            #pragma unroll
            for (int q = 0; q < 4; q++) c[mt][nt][q] = 0.f;
            c16[mt][nt][0] = 0u; c16[mt][nt][1] = 0u;
        }

    int q8 = lane >> 3, l8 = lane & 7;

    auto issue = [&](uint32_t sbuf, int kb) {
        for (int t = tid; t < 1024; t += 256) {
            int r = t >> 3, g = t & 7;
            uint32_t so = SW128((uint32_t)(r * 128 + g * 16));
            cp16(sbuf + so,
                 (const uint8_t*)g_h + ((size_t)(rowbase + r) * D + kb + g * 8) * 2);
        }
        for (int t = tid; t < 2048; t += 256) {
            int r = t >> 3, g = t & 7;
            uint32_t so = SW128((uint32_t)(r * 128 + g * 16));
            size_t ob = ((size_t)(r < 128 ? r : r - 128) * D + kb + g * 8) * 2;
            cp16(sbuf + F_OF_BH + so, (r < 128 ? BloH : BupH) + ob);
            cp16(sbuf + F_OF_BL + so, (r < 128 ? BloL : BupL) + ob);
        }
    };

    issue(sb, 0);
    cp_commit();

    for (int ch = 0; ch < 4; ch++) {
        uint32_t buf = sb + (uint32_t)(ch & 1) * F_STG;
        if (ch < 3) {
            issue(sb + (uint32_t)((ch + 1) & 1) * F_STG, (ch + 1) * 64);
            cp_commit();
            cp_wait<1>();
        } else {
            cp_wait<0>();
        }
        __syncthreads();

        #pragma unroll
        for (int ks = 0; ks < 4; ks++) {
            uint32_t ah[4][4];
            #pragma unroll
            for (int mt = 0; mt < 4; mt++) {
                int row = wrow * 64 + mt * 16 + (q8 & 1) * 8 + l8;
                uint32_t off = SW128((uint32_t)(row * 128 + ks * 32 + (q8 >> 1) * 16));
                ldsm4(ah[mt], buf + off);
            }
            #pragma unroll
            for (int nt = 0; nt < 4; nt++) {
                int nrow = wcol * 64 + nt * 16 + ((q8 >> 1) & 1) * 8 + l8;
                uint32_t off = SW128((uint32_t)(nrow * 128 + ks * 32 + (q8 & 1) * 16));
                uint32_t bh[4], bl[4];
                ldsm4(bh, buf + F_OF_BH + off);
                ldsm4(bl, buf + F_OF_BL + off);
                #pragma unroll
                for (int mt = 0; mt < 4; mt++) {
                    mma_f16 (c[mt][nt * 2],       ah[mt], bh[0], bh[1]);   // hi, f32 acc
                    mma_f16 (c[mt][nt * 2 + 1],   ah[mt], bh[2], bh[3]);
                    mma_f16h(c16[mt][nt * 2],     ah[mt], bl[0], bl[1]);   // lo, f16 acc
                    mma_f16h(c16[mt][nt * 2 + 1], ah[mt], bl[2], bl[3]);
                }
            }
        }
        __syncthreads();
    }

    // fold f16 lo accumulators into f32 master (undo x1024 scale)
    const float INV = 1.0f / 1024.0f;
    #pragma unroll
    for (int mt = 0; mt < 4; mt++)
        #pragma unroll
        for (int nt = 0; nt < 8; nt++) {
            __half2 p0 = *reinterpret_cast<__half2*>(&c16[mt][nt][0]);
            __half2 p1 = *reinterpret_cast<__half2*>(&c16[mt][nt][1]);
            c[mt][nt][0] += __low2float(p0) * INV;
            c[mt][nt][1] += __high2float(p0) * INV;
            c[mt][nt][2] += __low2float(p1) * INV;
            c[mt][nt][3] += __high2float(p1) * INV;
        }

    // ---- stage + epilogue
    float* stage = reinterpret_cast<float*>(smem);
    #pragma unroll
    for (int mt = 0; mt < 4; mt++)
        #pragma unroll
        for (int nt = 0; nt < 8; nt++) {
            int r0  = wrow * 64 + mt * 16 + (lane >> 2);
            int col = wcol * 64 + nt * 8 + 2 * (lane & 3);
            float* p = stage + r0 * SSTRIDE + col;
            p[0] = c[mt][nt][0];
            p[1] = c[mt][nt][1];
            p[8 * SSTRIDE]     = c[mt][nt][2];
            p[8 * SSTRIDE + 1] = c[mt][nt][3];
        }
    __syncthreads();

    for (int r = wid; r < 128; r += 8) {
        int gr = rowbase + r;
        bool ok = gr < NN;
        const float* rowp = stage + r * SSTRIDE + lane * 8;
        int cb = lane * 8;

        if (MODE == 1) {
            float v[8];
            if (lane < 16) {
                #pragma unroll
                for (int j = 0; j < 8; j++)
                    v[j] = fmaxf(rowp[j] + __ldg(&bias[cb + j]), 0.f);
                if (ok) {
                    float4* dst = reinterpret_cast<float4*>(g_a + (size_t)gr * DH + cb);
                    dst[0] = make_float4(v[0], v[1], v[2], v[3]);
                    dst[1] = make_float4(v[4], v[5], v[6], v[7]);
                }
            } else {
                #pragma unroll
                for (int j = 0; j < 8; j++) v[j] = rowp[j];
                if (ok) {
                    float4* dst = reinterpret_cast<float4*>(g_y + (size_t)gr * DH + (cb - 128));
                    dst[0] = make_float4(v[0], v[1], v[2], v[3]);
                    dst[1] = make_float4(v[4], v[5], v[6], v[7]);
                }
            }
        } else {
            float acc = 0.f;
            #pragma unroll
            for (int j = 0; j < 8; j++) {
                float vv = fmaxf(rowp[j] + __ldg(&bias[cb + j]), 0.f);
                acc += vv * __ldg(&wd2[cb + j]);
            }
            #pragma unroll
            for (int off = 16; off >= 1; off >>= 1)
                acc += __shfl_xor_sync(0xffffffffu, acc, off);
            if (lane == 0 && ok) out[gr] = acc + __ldg(bd2);
        }
    }
}

// ============================================================
// Fused CSR gather-reduce + bias + relu + l2norm + fp16 store
// One warp per dst node; lane owns 4 cols of each 128-wide half.
// ============================================================
__global__ void agg_combine_kernel(const float* __restrict__ b3) {
    int gw = (blockIdx.x * blockDim.x + threadIdx.x) >> 5;
    int lane = threadIdx.x & 31;
    if (gw >= NN) return;
    int n = gw;
    int beg = __ldg(&g_rowptr[n]);
    int end = __ldg(&g_rowptr[n + 1]);

    float ax = 0.f, ay = 0.f, az = 0.f, aw = 0.f;
    int i = beg;
    for (; i + 4 <= end; i += 4) {
        int s0 = __ldg(&g_colidx[i]);
        int s1 = __ldg(&g_colidx[i + 1]);
        int s2 = __ldg(&g_colidx[i + 2]);
        int s3 = __ldg(&g_colidx[i + 3]);
        float4 v0 = __ldg(reinterpret_cast<const float4*>(g_y + (size_t)s0 * DH) + lane);
        float4 v1 = __ldg(reinterpret_cast<const float4*>(g_y + (size_t)s1 * DH) + lane);
        float4 v2 = __ldg(reinterpret_cast<const float4*>(g_y + (size_t)s2 * DH) + lane);
        float4 v3 = __ldg(reinterpret_cast<const float4*>(g_y + (size_t)s3 * DH) + lane);
        ax += (v0.x + v1.x) + (v2.x + v3.x);
        ay += (v0.y + v1.y) + (v2.y + v3.y);
        az += (v0.z + v1.z) + (v2.z + v3.z);
        aw += (v0.w + v1.w) + (v2.w + v3.w);
    }
    for (; i < end; i++) {
        int s = __ldg(&g_colidx[i]);
        float4 v = __ldg(reinterpret_cast<const float4*>(g_y + (size_t)s * DH) + lane);
        ax += v.x; ay += v.y; az += v.z; aw += v.w;
    }

    float4 av = __ldg(reinterpret_cast<const float4*>(g_a + (size_t)n * DH) + lane);
    float4 bb = __ldg(reinterpret_cast<const float4*>(b3) + lane);
    float m0 = fmaxf(ax + bb.x, 0.f);
    float m1 = fmaxf(ay + bb.y, 0.f);
    float m2 = fmaxf(az + bb.z, 0.f);
    float m3 = fmaxf(aw + bb.w, 0.f);

    float ss = av.x * av.x + av.y * av.y + av.z * av.z + av.w * av.w
             + m0 * m0 + m1 * m1 + m2 * m2 + m3 * m3;
    #pragma unroll
    for (int off = 16; off >= 1; off >>= 1)
        ss += __shfl_xor_sync(0xffffffffu, ss, off);
    float rn = rsqrtf(ss);

    size_t base = (size_t)n * D;
    *reinterpret_cast<uint2*>(g_h + base + lane * 4) =
        make_uint2(pack2h(__float2half_rn(av.x * rn), __float2half_rn(av.y * rn)),
                   pack2h(__float2half_rn(av.z * rn), __float2half_rn(av.w * rn)));
    *reinterpret_cast<uint2*>(g_h + base + 128 + lane * 4) =
        make_uint2(pack2h(__float2half_rn(m0 * rn), __float2half_rn(m1 * rn)),
                   pack2h(__float2half_rn(m2 * rn), __float2half_rn(m3 * rn)));
}

// ============================================================
// Host launcher — single stream, fully serial
// ============================================================
extern "C" void kernel_launch(void* const* d_in, const int* in_sizes, int n_in,
                              void* d_out, int out_size) {
    const float* x   = (const float*)d_in[0];
    const int*   ei  = (const int*)d_in[1];    // int32 or int64 (auto-detected)
    const float* W1  = (const float*)d_in[2];
    const float* b1  = (const float*)d_in[3];
    const float* W2  = (const float*)d_in[4];
    const float* b2  = (const float*)d_in[5];
    const float* W3  = (const float*)d_in[6];
    const float* b3  = (const float*)d_in[7];
    const float* Wd1 = (const float*)d_in[8];
    const float* bd1 = (const float*)d_in[9];
    const float* Wd2 = (const float*)d_in[10];
    const float* bd2 = (const float*)d_in[11];
    float* out = (float*)d_out;

    cudaFuncSetAttribute(gemm0_kernel,   cudaFuncAttributeMaxDynamicSharedMemorySize, G0_SMEM);
    cudaFuncSetAttribute(gemm_kernel<1>, cudaFuncAttributeMaxDynamicSharedMemorySize, F_SMEM);
    cudaFuncSetAttribute(gemm_kernel<2>, cudaFuncAttributeMaxDynamicSharedMemorySize, F_SMEM);

    // weight conversion (also zeroes g_cnt) + CSR build
    conv_w_all_kernel<<<391, 256>>>(W1, W2, W3, Wd1);   // 391*256 >= NN
    detect_kernel<<<1, 1>>>(ei);
    count_kernel<<<(NE + 255) / 256, 256>>>(ei);
    scan_kernel<<<1, 1024>>>();
    fill_edges_kernel<<<(NE + 255) / 256, 256>>>(ei);

    // layer 1 (x conversion fused): h = fp16(l2norm(relu(x @ W1^T + b1)))
    gemm0_kernel<<<NB128, 256, G0_SMEM>>>(x, b1);

    // 2 conv layers
    for (int l = 0; l < 2; l++) {
        gemm_kernel<1><<<NB128, 256, F_SMEM>>>(b2, nullptr, nullptr, nullptr);
        agg_combine_kernel<<<(NN * 32 + 255) / 256, 256>>>(b3);
    }

    // head: out = relu(h @ Wd1^T + bd1) @ Wd2^T + bd2
    gemm_kernel<2><<<NB128, 256, F_SMEM>>>(bd1, Wd2, bd2, out);
}

// round 11
// speedup vs baseline: 1.6887x; 1.2253x over previous
#include <cuda_runtime.h>
#include <cuda_bf16.h>
#include <cuda_fp16.h>
#include <cstdint>
#include <cstddef>

// ============================================================
// Problem constants
// ============================================================
#define NN   100000      // nodes
#define NE   1600000     // edges
#define NP   100096      // padded: 128*782
#define NB128 782        // GEMM row tiles (128 rows each)
#define D    256
#define DH   128
#define SCAN_BLKS 98     // ceil(NN / 1024)

// ============================================================
// Device global scratch (no cudaMalloc allowed)
// ============================================================
__device__ __align__(256) __half g_h[(size_t)NP * D];   // activations (fp16)
__device__ __align__(256) float g_a[(size_t)NP * DH];   // relu(x@W2^T + b2)
__device__ __align__(256) float g_y[(size_t)NP * DH];   // x@W3^T (pre-aggregation)
__device__ __align__(256) __nv_bfloat16 g_w1hi[D * D],  g_w1lo[D * D];
__device__ __align__(256) __half g_w2hi[DH * D], g_w2lo[DH * D];   // lo scaled x1024
__device__ __align__(256) __half g_w3hi[DH * D], g_w3lo[DH * D];   // lo scaled x1024
__device__ __align__(256) __half g_wd1hi[D * D], g_wd1lo[D * D];   // lo scaled x1024
__device__ __align__(256) int g_rowptr[NN + 1];
__device__ __align__(256) int g_cursor[NN];
__device__ __align__(256) int g_cnt[NN];
__device__ __align__(256) int g_colidx[NE];
__device__ __align__(256) int g_bsum[128];
__device__ __align__(256) int g_boff[128];
__device__ int g_is64;

// ============================================================
// Helpers
// ============================================================
__device__ __forceinline__ uint32_t smem_u32(const void* p) {
    uint32_t a;
    asm("{ .reg .u64 t; cvta.to.shared.u64 t, %1; cvt.u32.u64 %0, t; }"
        : "=r"(a) : "l"(p));
    return a;
}

#define SW128(o) ((o) ^ (((o) >> 3) & 0x70))

__device__ __forceinline__ void cp16(uint32_t dst, const void* src) {
    asm volatile("cp.async.cg.shared.global [%0], [%1], 16;" :: "r"(dst), "l"(src));
}
__device__ __forceinline__ void cp_commit() {
    asm volatile("cp.async.commit_group;" ::: "memory");
}
template <int N>
__device__ __forceinline__ void cp_wait() {
    asm volatile("cp.async.wait_group %0;" :: "n"(N) : "memory");
}

__device__ __forceinline__ void ldsm4(uint32_t* r, uint32_t addr) {
    asm volatile("ldmatrix.sync.aligned.m8n8.x4.shared.b16 {%0,%1,%2,%3}, [%4];"
        : "=r"(r[0]), "=r"(r[1]), "=r"(r[2]), "=r"(r[3]) : "r"(addr));
}

__device__ __forceinline__ void mma_bf16(float* c, const uint32_t* a,
                                         uint32_t b0, uint32_t b1) {
    asm volatile(
        "mma.sync.aligned.m16n8k16.row.col.f32.bf16.bf16.f32 "
        "{%0,%1,%2,%3}, {%4,%5,%6,%7}, {%8,%9}, {%0,%1,%2,%3};"
        : "+f"(c[0]), "+f"(c[1]), "+f"(c[2]), "+f"(c[3])
        : "r"(a[0]), "r"(a[1]), "r"(a[2]), "r"(a[3]), "r"(b0), "r"(b1));
}
__device__ __forceinline__ void mma_f16(float* c, const uint32_t* a,
                                        uint32_t b0, uint32_t b1) {
    asm volatile(
        "mma.sync.aligned.m16n8k16.row.col.f32.f16.f16.f32 "
        "{%0,%1,%2,%3}, {%4,%5,%6,%7}, {%8,%9}, {%0,%1,%2,%3};"
        : "+f"(c[0]), "+f"(c[1]), "+f"(c[2]), "+f"(c[3])
        : "r"(a[0]), "r"(a[1]), "r"(a[2]), "r"(a[3]), "r"(b0), "r"(b1));
}
// f16 accumulator variant (2 f16x2 regs) — used for the lo pass
__device__ __forceinline__ void mma_f16h(uint32_t* c2, const uint32_t* a,
                                         uint32_t b0, uint32_t b1) {
    asm volatile(
        "mma.sync.aligned.m16n8k16.row.col.f16.f16.f16.f16 "
        "{%0,%1}, {%2,%3,%4,%5}, {%6,%7}, {%0,%1};"
        : "+r"(c2[0]), "+r"(c2[1])
        : "r"(a[0]), "r"(a[1]), "r"(a[2]), "r"(a[3]), "r"(b0), "r"(b1));
}

__device__ __forceinline__ void split_bf(float v, __nv_bfloat16& h, __nv_bfloat16& l) {
    h = __float2bfloat16(v);
    l = __float2bfloat16(v - __bfloat162float(h));
}
__device__ __forceinline__ uint32_t pack2(__nv_bfloat16 a, __nv_bfloat16 b) {
    __nv_bfloat162 t; t.x = a; t.y = b;
    return *reinterpret_cast<uint32_t*>(&t);
}
__device__ __forceinline__ uint32_t pack2h(__half a, __half b) {
    __half2 t; t.x = a; t.y = b;
    return *reinterpret_cast<uint32_t*>(&t);
}

// ============================================================
// Weight conversion (one kernel) + zero g_cnt piggyback
// W1 -> bf16 hi/lo ; W2/W3/Wd1 -> fp16 hi + (lo * 1024) fp16
// ============================================================
__global__ void conv_w_all_kernel(const float* __restrict__ W1,
                                  const float* __restrict__ W2,
                                  const float* __restrict__ W3,
                                  const float* __restrict__ Wd1) {
    int i = blockIdx.x * blockDim.x + threadIdx.x;
    if (i < NN) g_cnt[i] = 0;             // zero CSR histogram (grid covers NN)
    if (i >= 49152) return;
    if (i < 16384) {
        float4 v = __ldg(((const float4*)W1) + i);
        __nv_bfloat16 h0, l0, h1, l1, h2, l2, h3, l3;
        split_bf(v.x, h0, l0); split_bf(v.y, h1, l1);
        split_bf(v.z, h2, l2); split_bf(v.w, h3, l3);
        ((uint2*)g_w1hi)[i] = make_uint2(pack2(h0, h1), pack2(h2, h3));
        ((uint2*)g_w1lo)[i] = make_uint2(pack2(l0, l1), pack2(l2, l3));
        return;
    }
    const float* w; __half *hi, *lo; int off;
    if (i < 24576)      { w = W2;  hi = g_w2hi;  lo = g_w2lo;  off = i - 16384; }
    else if (i < 32768) { w = W3;  hi = g_w3hi;  lo = g_w3lo;  off = i - 24576; }
    else                { w = Wd1; hi = g_wd1hi; lo = g_wd1lo; off = i - 32768; }
    float4 v = __ldg(((const float4*)w) + off);
    __half h0 = __float2half_rn(v.x), h1 = __float2half_rn(v.y);
    __half h2 = __float2half_rn(v.z), h3 = __float2half_rn(v.w);
    __half l0 = __float2half_rn((v.x - __half2float(h0)) * 1024.0f);
    __half l1 = __float2half_rn((v.y - __half2float(h1)) * 1024.0f);
    __half l2 = __float2half_rn((v.z - __half2float(h2)) * 1024.0f);
    __half l3 = __float2half_rn((v.w - __half2float(h3)) * 1024.0f);
    ((uint2*)hi)[off] = make_uint2(pack2h(h0, h1), pack2h(h2, h3));
    ((uint2*)lo)[off] = make_uint2(pack2h(l0, l1), pack2h(l2, l3));
}

// ============================================================
// CSR build (serial; reads edge_index directly)
// ============================================================
__global__ void detect_kernel(const int* __restrict__ ei) {
    int z = 1;
    for (int i = 0; i < 64; i++)
        if (ei[2 * i + 1] != 0) { z = 0; break; }
    g_is64 = z;
}

__global__ void count_kernel(const int* __restrict__ ei) {
    int e = blockIdx.x * blockDim.x + threadIdx.x;
    if (e >= NE) return;
    int d = g_is64 ? __ldg(&ei[2 * ((size_t)NE + e)]) : __ldg(&ei[NE + e]);
    if ((unsigned)d < NN) atomicAdd(&g_cnt[d], 1);
}

// ---- 3-phase parallel exclusive scan of g_cnt -> g_rowptr/g_cursor ----
__global__ void scan_block_kernel() {          // grid SCAN_BLKS, block 1024
    __shared__ int sd[1024];
    int t = threadIdx.x;
    int i = blockIdx.x * 1024 + t;
    sd[t] = (i < NN) ? g_cnt[i] : 0;
    __syncthreads();
    #pragma unroll
    for (int off = 512; off > 0; off >>= 1) {
        if (t < off) sd[t] += sd[t + off];
        __syncthreads();
    }
    if (t == 0) g_bsum[blockIdx.x] = sd[0];
}

__global__ void scan_top_kernel() {            // 1 block, 128 threads
    __shared__ int sd[128];
    int t = threadIdx.x;
    sd[t] = (t < SCAN_BLKS) ? g_bsum[t] : 0;
    __syncthreads();
    if (t == 0) {
        int run = 0;
        for (int b = 0; b < SCAN_BLKS; b++) {
            g_boff[b] = run;
            run += sd[b];
        }
        g_rowptr[NN] = run;
    }
}

__global__ void scan_apply_kernel() {          // grid SCAN_BLKS, block 1024
    __shared__ int sd[1024];
    int t = threadIdx.x;
    int i = blockIdx.x * 1024 + t;
    int v = (i < NN) ? g_cnt[i] : 0;
    sd[t] = v;
    __syncthreads();
    #pragma unroll
    for (int off = 1; off < 1024; off <<= 1) {
        int add = (t >= off) ? sd[t - off] : 0;
        __syncthreads();
        sd[t] += add;
        __syncthreads();
    }
    if (i < NN) {
        int excl = sd[t] - v + g_boff[blockIdx.x];
        g_rowptr[i] = excl;
        g_cursor[i] = excl;
    }
}

__global__ void fill_edges_kernel(const int* __restrict__ ei) {
    int e = blockIdx.x * blockDim.x + threadIdx.x;
    if (e >= NE) return;
    int s, d;
    if (g_is64) {
        s = __ldg(&ei[2 * e]);
        d = __ldg(&ei[2 * ((size_t)NE + e)]);
    } else {
        s = __ldg(&ei[e]);
        d = __ldg(&ei[NE + e]);
    }
    if ((unsigned)s < NN && (unsigned)d < NN) {
        int p = atomicAdd(&g_cursor[d], 1);
        g_colidx[p] = s;
    }
}

// ============================================================
// Layer-1 GEMM (bf16 3-pass exact) with FUSED x fp32->bf16 hi/lo
// conversion. CTA 128x256, 8 warps (2x4), warp tile 64x64.
// smem: AH 16K | AL 16K | XRAW 32K | BH0 32K | BL0 32K | BH1 32K | BL1 32K
// ============================================================
static constexpr int G0_AH  = 0;
static constexpr int G0_AL  = 16384;
static constexpr int G0_XR  = 32768;
static constexpr int G0_B0  = 65536;     // BH0; BL0 at +32768
static constexpr int G0_B1  = 131072;    // BH1; BL1 at +32768
static constexpr int G0_SMEM = 196608;
static constexpr int SSTRIDE = 260;

__global__ void __launch_bounds__(256, 1)
gemm0_kernel(const float* __restrict__ x, const float* __restrict__ bias) {
    extern __shared__ char smem[];
    uint32_t sb = smem_u32(smem);
    int tid = threadIdx.x, wid = tid >> 5, lane = tid & 31;
    int rowbase = blockIdx.x * 128;
    int wrow = wid & 1;
    int wcol = wid >> 1;

    float c[4][8][4];
    #pragma unroll
    for (int mt = 0; mt < 4; mt++)
        #pragma unroll
        for (int nt = 0; nt < 8; nt++)
            #pragma unroll
            for (int q = 0; q < 4; q++) c[mt][nt][q] = 0.f;

    int q8 = lane >> 3, l8 = lane & 7;

    auto issue_x = [&](int kb) {
        for (int t = tid; t < 2048; t += 256) {
            int r = t >> 4, g = t & 15;
            int gr = rowbase + r; if (gr >= NN) gr = NN - 1;   // pad rows masked later
            cp16(sb + G0_XR + (uint32_t)(r * 256 + g * 16),
                 x + (size_t)gr * D + kb + g * 4);
        }
    };
    auto issue_B = [&](int st, int kb) {
        uint32_t bh = sb + (st ? G0_B1 : G0_B0);
        for (int t = tid; t < 2048; t += 256) {
            int r = t >> 3, g = t & 7;
            uint32_t so = SW128((uint32_t)(r * 128 + g * 16));
            size_t ob = ((size_t)r * D + kb + g * 8) * 2;
            cp16(bh + so,         (const uint8_t*)g_w1hi + ob);
            cp16(bh + 32768 + so, (const uint8_t*)g_w1lo + ob);
        }
    };

    issue_x(0); issue_B(0, 0); cp_commit();

    for (int ch = 0; ch < 4; ch++) {
        cp_wait<0>();
        __syncthreads();
        #pragma unroll
        for (int j = 0; j < 8; j++) {
            int idx = tid + j * 256;
            float4 v = reinterpret_cast<const float4*>(smem + G0_XR)[idx];
            int r = idx >> 4, g4 = idx & 15;
            uint32_t bo = (uint32_t)(r * 128 + g4 * 8);
            uint32_t so = bo ^ ((bo >> 3) & 0x70);
            __nv_bfloat16 h0, l0, h1, l1, h2, l2, h3, l3;
            split_bf(v.x, h0, l0); split_bf(v.y, h1, l1);
            split_bf(v.z, h2, l2); split_bf(v.w, h3, l3);
            *reinterpret_cast<uint2*>(smem + G0_AH + so) = make_uint2(pack2(h0, h1), pack2(h2, h3));
            *reinterpret_cast<uint2*>(smem + G0_AL + so) = make_uint2(pack2(l0, l1), pack2(l2, l3));
        }
        __syncthreads();
        if (ch < 3) { issue_x((ch + 1) * 64); issue_B((ch + 1) & 1, (ch + 1) * 64); cp_commit(); }

        uint32_t bbh = sb + ((ch & 1) ? G0_B1 : G0_B0);
        #pragma unroll
        for (int ks = 0; ks < 4; ks++) {
            uint32_t ah[4][4], al[4][4];
            #pragma unroll
            for (int mt = 0; mt < 4; mt++) {
                int row = wrow * 64 + mt * 16 + (q8 & 1) * 8 + l8;
                uint32_t off = SW128((uint32_t)(row * 128 + ks * 32 + (q8 >> 1) * 16));
                ldsm4(ah[mt], sb + G0_AH + off);
                ldsm4(al[mt], sb + G0_AL + off);
            }
            #pragma unroll
            for (int nt = 0; nt < 4; nt++) {
                int nrow = wcol * 64 + nt * 16 + ((q8 >> 1) & 1) * 8 + l8;
                uint32_t off = SW128((uint32_t)(nrow * 128 + ks * 32 + (q8 & 1) * 16));
                uint32_t bh[4], bl[4];
                ldsm4(bh, bbh + off);
                ldsm4(bl, bbh + 32768 + off);
                #pragma unroll
                for (int mt = 0; mt < 4; mt++) {
                    mma_bf16(c[mt][nt * 2],     ah[mt], bh[0], bh[1]);
                    mma_bf16(c[mt][nt * 2],     ah[mt], bl[0], bl[1]);
                    mma_bf16(c[mt][nt * 2],     al[mt], bh[0], bh[1]);
                    mma_bf16(c[mt][nt * 2 + 1], ah[mt], bh[2], bh[3]);
                    mma_bf16(c[mt][nt * 2 + 1], ah[mt], bl[2], bl[3]);
                    mma_bf16(c[mt][nt * 2 + 1], al[mt], bh[2], bh[3]);
                }
            }
        }
        __syncthreads();
    }

    float* stage = reinterpret_cast<float*>(smem);
    #pragma unroll
    for (int mt = 0; mt < 4; mt++)
        #pragma unroll
        for (int nt = 0; nt < 8; nt++) {
            int r0  = wrow * 64 + mt * 16 + (lane >> 2);
            int col = wcol * 64 + nt * 8 + 2 * (lane & 3);
            float* p = stage + r0 * SSTRIDE + col;
            p[0] = c[mt][nt][0];
            p[1] = c[mt][nt][1];
            p[8 * SSTRIDE]     = c[mt][nt][2];
            p[8 * SSTRIDE + 1] = c[mt][nt][3];
        }
    __syncthreads();

    for (int r = wid; r < 128; r += 8) {
        int gr = rowbase + r;
        bool ok = gr < NN;
        const float* rowp = stage + r * SSTRIDE + lane * 8;
        int cb = lane * 8;
        float v[8];
        float ss = 0.f;
        #pragma unroll
        for (int j = 0; j < 8; j++) {
            v[j] = fmaxf(rowp[j] + __ldg(&bias[cb + j]), 0.f);
            ss += v[j] * v[j];
        }
        #pragma unroll
        for (int off = 16; off >= 1; off >>= 1)
            ss += __shfl_xor_sync(0xffffffffu, ss, off);
        float rn = rsqrtf(ss);
        if (ok) {
            __half h[8];
            #pragma unroll
            for (int j = 0; j < 8; j++) h[j] = __float2half_rn(v[j] * rn);
            *reinterpret_cast<uint4*>(g_h + (size_t)gr * D + cb) =
                make_uint4(pack2h(h[0], h[1]), pack2h(h[2], h[3]),
                           pack2h(h[4], h[5]), pack2h(h[6], h[7]));
        }
    }
}

// ============================================================
// fp16 N=256 GEMM (mid MODE 1, final MODE 2): CTA 128x256,
// hi pass f32-acc + lo pass f16-acc (lo plane pre-scaled x1024).
// ============================================================
static constexpr int F_OF_BH = 16384;
static constexpr int F_OF_BL = 49152;
static constexpr int F_STG   = 81920;
static constexpr int F_SMEM  = 2 * F_STG;

template <int MODE>   // 1 = mid ([W2;W3]) , 2 = final (Wd1)
__global__ void __launch_bounds__(256, 1)
gemm_kernel(const float* __restrict__ bias, const float* __restrict__ wd2,
            const float* __restrict__ bd2, float* __restrict__ out) {
    extern __shared__ char smem[];
    uint32_t sb = smem_u32(smem);
    int tid = threadIdx.x, wid = tid >> 5, lane = tid & 31;
    int rowbase = blockIdx.x * 128;
    int wrow = wid & 1;
    int wcol = wid >> 1;

    const uint8_t *BloH, *BloL, *BupH, *BupL;
    if (MODE == 1) {
        BloH = (const uint8_t*)g_w2hi;  BloL = (const uint8_t*)g_w2lo;
        BupH = (const uint8_t*)g_w3hi;  BupL = (const uint8_t*)g_w3lo;
    } else {
        BloH = (const uint8_t*)g_wd1hi; BloL = (const uint8_t*)g_wd1lo;
        BupH = (const uint8_t*)(g_wd1hi + 128 * D); BupL = (const uint8_t*)(g_wd1lo + 128 * D);
    }

    float c[4][8][4];
    uint32_t c16[4][8][2];
    #pragma unroll
    for (int mt = 0; mt < 4; mt++)
        #pragma unroll
        for (int nt = 0; nt < 8; nt++) {
            #pragma unroll
            for (int q = 0; q < 4; q++) c[mt][nt][q] = 0.f;
            c16[mt][nt][0] = 0u; c16[mt][nt][1] = 0u;
        }

    int q8 = lane >> 3, l8 = lane & 7;

    auto issue = [&](uint32_t sbuf, int kb) {
        for (int t = tid; t < 1024; t += 256) {
            int r = t >> 3, g = t & 7;
            uint32_t so = SW128((uint32_t)(r * 128 + g * 16));
            cp16(sbuf + so,
                 (const uint8_t*)g_h + ((size_t)(rowbase + r) * D + kb + g * 8) * 2);
        }
        for (int t = tid; t < 2048; t += 256) {
            int r = t >> 3, g = t & 7;
            uint32_t so = SW128((uint32_t)(r * 128 + g * 16));
            size_t ob = ((size_t)(r < 128 ? r : r - 128) * D + kb + g * 8) * 2;
            cp16(sbuf + F_OF_BH + so, (r < 128 ? BloH : BupH) + ob);
            cp16(sbuf + F_OF_BL + so, (r < 128 ? BloL : BupL) + ob);
        }
    };

    issue(sb, 0);
    cp_commit();

    for (int ch = 0; ch < 4; ch++) {
        uint32_t buf = sb + (uint32_t)(ch & 1) * F_STG;
        if (ch < 3) {
            issue(sb + (uint32_t)((ch + 1) & 1) * F_STG, (ch + 1) * 64);
            cp_commit();
            cp_wait<1>();
        } else {
            cp_wait<0>();
        }
        __syncthreads();

        #pragma unroll
        for (int ks = 0; ks < 4; ks++) {
            uint32_t ah[4][4];
            #pragma unroll
            for (int mt = 0; mt < 4; mt++) {
                int row = wrow * 64 + mt * 16 + (q8 & 1) * 8 + l8;
                uint32_t off = SW128((uint32_t)(row * 128 + ks * 32 + (q8 >> 1) * 16));
                ldsm4(ah[mt], buf + off);
            }
            #pragma unroll
            for (int nt = 0; nt < 4; nt++) {
                int nrow = wcol * 64 + nt * 16 + ((q8 >> 1) & 1) * 8 + l8;
                uint32_t off = SW128((uint32_t)(nrow * 128 + ks * 32 + (q8 & 1) * 16));
                uint32_t bh[4], bl[4];
                ldsm4(bh, buf + F_OF_BH + off);
                ldsm4(bl, buf + F_OF_BL + off);
                #pragma unroll
                for (int mt = 0; mt < 4; mt++) {
                    mma_f16 (c[mt][nt * 2],       ah[mt], bh[0], bh[1]);   // hi, f32 acc
                    mma_f16 (c[mt][nt * 2 + 1],   ah[mt], bh[2], bh[3]);
                    mma_f16h(c16[mt][nt * 2],     ah[mt], bl[0], bl[1]);   // lo, f16 acc
                    mma_f16h(c16[mt][nt * 2 + 1], ah[mt], bl[2], bl[3]);
                }
            }
        }
        __syncthreads();
    }

    const float INV = 1.0f / 1024.0f;
    #pragma unroll
    for (int mt = 0; mt < 4; mt++)
        #pragma unroll
        for (int nt = 0; nt < 8; nt++) {
            __half2 p0 = *reinterpret_cast<__half2*>(&c16[mt][nt][0]);
            __half2 p1 = *reinterpret_cast<__half2*>(&c16[mt][nt][1]);
            c[mt][nt][0] += __low2float(p0) * INV;
            c[mt][nt][1] += __high2float(p0) * INV;
            c[mt][nt][2] += __low2float(p1) * INV;
            c[mt][nt][3] += __high2float(p1) * INV;
        }

    float* stage = reinterpret_cast<float*>(smem);
    #pragma unroll
    for (int mt = 0; mt < 4; mt++)
        #pragma unroll
        for (int nt = 0; nt < 8; nt++) {
            int r0  = wrow * 64 + mt * 16 + (lane >> 2);
            int col = wcol * 64 + nt * 8 + 2 * (lane & 3);
            float* p = stage + r0 * SSTRIDE + col;
            p[0] = c[mt][nt][0];
            p[1] = c[mt][nt][1];
            p[8 * SSTRIDE]     = c[mt][nt][2];
            p[8 * SSTRIDE + 1] = c[mt][nt][3];
        }
    __syncthreads();

    for (int r = wid; r < 128; r += 8) {
        int gr = rowbase + r;
        bool ok = gr < NN;
        const float* rowp = stage + r * SSTRIDE + lane * 8;
        int cb = lane * 8;

        if (MODE == 1) {
            float v[8];
            if (lane < 16) {
                #pragma unroll
                for (int j = 0; j < 8; j++)
                    v[j] = fmaxf(rowp[j] + __ldg(&bias[cb + j]), 0.f);
                if (ok) {
                    float4* dst = reinterpret_cast<float4*>(g_a + (size_t)gr * DH + cb);
                    dst[0] = make_float4(v[0], v[1], v[2], v[3]);
                    dst[1] = make_float4(v[4], v[5], v[6], v[7]);
                }
            } else {
                #pragma unroll
                for (int j = 0; j < 8; j++) v[j] = rowp[j];
                if (ok) {
                    float4* dst = reinterpret_cast<float4*>(g_y + (size_t)gr * DH + (cb - 128));
                    dst[0] = make_float4(v[0], v[1], v[2], v[3]);
                    dst[1] = make_float4(v[4], v[5], v[6], v[7]);
                }
            }
        } else {
            float acc = 0.f;
            #pragma unroll
            for (int j = 0; j < 8; j++) {
                float vv = fmaxf(rowp[j] + __ldg(&bias[cb + j]), 0.f);
                acc += vv * __ldg(&wd2[cb + j]);
            }
            #pragma unroll
            for (int off = 16; off >= 1; off >>= 1)
                acc += __shfl_xor_sync(0xffffffffu, acc, off);
            if (lane == 0 && ok) out[gr] = acc + __ldg(bd2);
        }
    }
}

// ============================================================
// Fused CSR gather-reduce + bias + relu + l2norm + fp16 store
// One warp per dst node; lane owns 4 cols of each 128-wide half.
// ============================================================
__global__ void agg_combine_kernel(const float* __restrict__ b3) {
    int gw = (blockIdx.x * blockDim.x + threadIdx.x) >> 5;
    int lane = threadIdx.x & 31;
    if (gw >= NN) return;
    int n = gw;
    int beg = __ldg(&g_rowptr[n]);
    int end = __ldg(&g_rowptr[n + 1]);

    float ax = 0.f, ay = 0.f, az = 0.f, aw = 0.f;
    int i = beg;
    for (; i + 4 <= end; i += 4) {
        int s0 = __ldg(&g_colidx[i]);
        int s1 = __ldg(&g_colidx[i + 1]);
        int s2 = __ldg(&g_colidx[i + 2]);
        int s3 = __ldg(&g_colidx[i + 3]);
        float4 v0 = __ldg(reinterpret_cast<const float4*>(g_y + (size_t)s0 * DH) + lane);
        float4 v1 = __ldg(reinterpret_cast<const float4*>(g_y + (size_t)s1 * DH) + lane);
        float4 v2 = __ldg(reinterpret_cast<const float4*>(g_y + (size_t)s2 * DH) + lane);
        float4 v3 = __ldg(reinterpret_cast<const float4*>(g_y + (size_t)s3 * DH) + lane);
        ax += (v0.x + v1.x) + (v2.x + v3.x);
        ay += (v0.y + v1.y) + (v2.y + v3.y);
        az += (v0.z + v1.z) + (v2.z + v3.z);
        aw += (v0.w + v1.w) + (v2.w + v3.w);
    }
    for (; i < end; i++) {
        int s = __ldg(&g_colidx[i]);
        float4 v = __ldg(reinterpret_cast<const float4*>(g_y + (size_t)s * DH) + lane);
        ax += v.x; ay += v.y; az += v.z; aw += v.w;
    }

    float4 av = __ldg(reinterpret_cast<const float4*>(g_a + (size_t)n * DH) + lane);
    float4 bb = __ldg(reinterpret_cast<const float4*>(b3) + lane);
    float m0 = fmaxf(ax + bb.x, 0.f);
    float m1 = fmaxf(ay + bb.y, 0.f);
    float m2 = fmaxf(az + bb.z, 0.f);
    float m3 = fmaxf(aw + bb.w, 0.f);

    float ss = av.x * av.x + av.y * av.y + av.z * av.z + av.w * av.w
             + m0 * m0 + m1 * m1 + m2 * m2 + m3 * m3;
    #pragma unroll
    for (int off = 16; off >= 1; off >>= 1)
        ss += __shfl_xor_sync(0xffffffffu, ss, off);
    float rn = rsqrtf(ss);

    size_t base = (size_t)n * D;
    *reinterpret_cast<uint2*>(g_h + base + lane * 4) =
        make_uint2(pack2h(__float2half_rn(av.x * rn), __float2half_rn(av.y * rn)),
                   pack2h(__float2half_rn(av.z * rn), __float2half_rn(av.w * rn)));
    *reinterpret_cast<uint2*>(g_h + base + 128 + lane * 4) =
        make_uint2(pack2h(__float2half_rn(m0 * rn), __float2half_rn(m1 * rn)),
                   pack2h(__float2half_rn(m2 * rn), __float2half_rn(m3 * rn)));
}

// ============================================================
// Host launcher — single stream, fully serial
// ============================================================
extern "C" void kernel_launch(void* const* d_in, const int* in_sizes, int n_in,
                              void* d_out, int out_size) {
    const float* x   = (const float*)d_in[0];
    const int*   ei  = (const int*)d_in[1];    // int32 or int64 (auto-detected)
    const float* W1  = (const float*)d_in[2];
    const float* b1  = (const float*)d_in[3];
    const float* W2  = (const float*)d_in[4];
    const float* b2  = (const float*)d_in[5];
    const float* W3  = (const float*)d_in[6];
    const float* b3  = (const float*)d_in[7];
    const float* Wd1 = (const float*)d_in[8];
    const float* bd1 = (const float*)d_in[9];
    const float* Wd2 = (const float*)d_in[10];
    const float* bd2 = (const float*)d_in[11];
    float* out = (float*)d_out;

    cudaFuncSetAttribute(gemm0_kernel,   cudaFuncAttributeMaxDynamicSharedMemorySize, G0_SMEM);
    cudaFuncSetAttribute(gemm_kernel<1>, cudaFuncAttributeMaxDynamicSharedMemorySize, F_SMEM);
    cudaFuncSetAttribute(gemm_kernel<2>, cudaFuncAttributeMaxDynamicSharedMemorySize, F_SMEM);

    // weight conversion (also zeroes g_cnt) + CSR build (parallel scan)
    conv_w_all_kernel<<<391, 256>>>(W1, W2, W3, Wd1);   // 391*256 >= NN
    detect_kernel<<<1, 1>>>(ei);
    count_kernel<<<(NE + 255) / 256, 256>>>(ei);
    scan_block_kernel<<<SCAN_BLKS, 1024>>>();
    scan_top_kernel<<<1, 128>>>();
    scan_apply_kernel<<<SCAN_BLKS, 1024>>>();
    fill_edges_kernel<<<(NE + 255) / 256, 256>>>(ei);

    // layer 1 (x conversion fused): h = fp16(l2norm(relu(x @ W1^T + b1)))
    gemm0_kernel<<<NB128, 256, G0_SMEM>>>(x, b1);

    // 2 conv layers
    for (int l = 0; l < 2; l++) {
        gemm_kernel<1><<<NB128, 256, F_SMEM>>>(b2, nullptr, nullptr, nullptr);
        agg_combine_kernel<<<(NN * 32 + 255) / 256, 256>>>(b3);
    }

    // head: out = relu(h @ Wd1^T + bd1) @ Wd2^T + bd2
    gemm_kernel<2><<<NB128, 256, F_SMEM>>>(bd1, Wd2, bd2, out);
}

// round 14
// speedup vs baseline: 1.7703x; 1.0483x over previous
#include <cuda_runtime.h>
#include <cuda_bf16.h>
#include <cuda_fp16.h>
#include <cstdint>
#include <cstddef>

// ============================================================
// Problem constants
// ============================================================
#define NN   100000      // nodes
#define NE   1600000     // edges
#define NP   100096      // padded: 128*782
#define NB128 782        // GEMM row tiles (128 rows each)
#define D    256
#define DH   128
#define SCAN_BLKS 98     // ceil(NN / 1024)

// ============================================================
// Device global scratch (no cudaMalloc allowed)
// ============================================================
__device__ __align__(256) __half g_h[(size_t)NP * D];   // activations (fp16)
__device__ __align__(256) float g_a[(size_t)NP * DH];   // relu(x@W2^T + b2)
__device__ __align__(256) float g_y[(size_t)NP * DH];   // x@W3^T (pre-aggregation)
__device__ __align__(256) __nv_bfloat16 g_w1hi[D * D],  g_w1lo[D * D];
__device__ __align__(256) __half g_w2hi[DH * D], g_w2lo[DH * D];   // lo scaled x1024
__device__ __align__(256) __half g_w3hi[DH * D], g_w3lo[DH * D];   // lo scaled x1024
__device__ __align__(256) __half g_wd1hi[D * D], g_wd1lo[D * D];   // lo scaled x1024
__device__ __align__(256) int g_rowptr[NN + 1];
__device__ __align__(256) int g_cursor[NN];
__device__ __align__(256) int g_cnt[NN];
__device__ __align__(256) int g_colidx[NE];
__device__ __align__(256) int g_bsum[128];
__device__ __align__(256) int g_boff[128];
__device__ int g_is64;

// ============================================================
// Helpers
// ============================================================
__device__ __forceinline__ uint32_t smem_u32(const void* p) {
    uint32_t a;
    asm("{ .reg .u64 t; cvta.to.shared.u64 t, %1; cvt.u32.u64 %0, t; }"
        : "=r"(a) : "l"(p));
    return a;
}

#define SW128(o) ((o) ^ (((o) >> 3) & 0x70))

__device__ __forceinline__ void cp16(uint32_t dst, const void* src) {
    asm volatile("cp.async.cg.shared.global [%0], [%1], 16;" :: "r"(dst), "l"(src));
}
__device__ __forceinline__ void cp_commit() {
    asm volatile("cp.async.commit_group;" ::: "memory");
}
template <int N>
__device__ __forceinline__ void cp_wait() {
    asm volatile("cp.async.wait_group %0;" :: "n"(N) : "memory");
}

__device__ __forceinline__ void ldsm4(uint32_t* r, uint32_t addr) {
    asm volatile("ldmatrix.sync.aligned.m8n8.x4.shared.b16 {%0,%1,%2,%3}, [%4];"
        : "=r"(r[0]), "=r"(r[1]), "=r"(r[2]), "=r"(r[3]) : "r"(addr));
}

__device__ __forceinline__ void mma_bf16(float* c, const uint32_t* a,
                                         uint32_t b0, uint32_t b1) {
    asm volatile(
        "mma.sync.aligned.m16n8k16.row.col.f32.bf16.bf16.f32 "
        "{%0,%1,%2,%3}, {%4,%5,%6,%7}, {%8,%9}, {%0,%1,%2,%3};"
        : "+f"(c[0]), "+f"(c[1]), "+f"(c[2]), "+f"(c[3])
        : "r"(a[0]), "r"(a[1]), "r"(a[2]), "r"(a[3]), "r"(b0), "r"(b1));
}
__device__ __forceinline__ void mma_f16(float* c, const uint32_t* a,
                                        uint32_t b0, uint32_t b1) {
    asm volatile(
        "mma.sync.aligned.m16n8k16.row.col.f32.f16.f16.f32 "
        "{%0,%1,%2,%3}, {%4,%5,%6,%7}, {%8,%9}, {%0,%1,%2,%3};"
        : "+f"(c[0]), "+f"(c[1]), "+f"(c[2]), "+f"(c[3])
        : "r"(a[0]), "r"(a[1]), "r"(a[2]), "r"(a[3]), "r"(b0), "r"(b1));
}
// f16 accumulator variant (2 f16x2 regs) — used for the lo pass
__device__ __forceinline__ void mma_f16h(uint32_t* c2, const uint32_t* a,
                                         uint32_t b0, uint32_t b1) {
    asm volatile(
        "mma.sync.aligned.m16n8k16.row.col.f16.f16.f16.f16 "
        "{%0,%1}, {%2,%3,%4,%5}, {%6,%7}, {%0,%1};"
        : "+r"(c2[0]), "+r"(c2[1])
        : "r"(a[0]), "r"(a[1]), "r"(a[2]), "r"(a[3]), "r"(b0), "r"(b1));
}

__device__ __forceinline__ void split_bf(float v, __nv_bfloat16& h, __nv_bfloat16& l) {
    h = __float2bfloat16(v);
    l = __float2bfloat16(v - __bfloat162float(h));
}
__device__ __forceinline__ uint32_t pack2(__nv_bfloat16 a, __nv_bfloat16 b) {
    __nv_bfloat162 t; t.x = a; t.y = b;
    return *reinterpret_cast<uint32_t*>(&t);
}
__device__ __forceinline__ uint32_t pack2h(__half a, __half b) {
    __half2 t; t.x = a; t.y = b;
    return *reinterpret_cast<uint32_t*>(&t);
}

// ============================================================
// Weight conversion (one kernel)
// W1 -> bf16 hi/lo ; W2/W3/Wd1 -> fp16 hi + (lo * 1024) fp16
// ============================================================
__global__ void conv_w_all_kernel(const float* __restrict__ W1,
                                  const float* __restrict__ W2,
                                  const float* __restrict__ W3,
                                  const float* __restrict__ Wd1) {
    int i = blockIdx.x * blockDim.x + threadIdx.x;
    if (i >= 49152) return;
    if (i < 16384) {
        float4 v = __ldg(((const float4*)W1) + i);
        __nv_bfloat16 h0, l0, h1, l1, h2, l2, h3, l3;
        split_bf(v.x, h0, l0); split_bf(v.y, h1, l1);
        split_bf(v.z, h2, l2); split_bf(v.w, h3, l3);
        ((uint2*)g_w1hi)[i] = make_uint2(pack2(h0, h1), pack2(h2, h3));
        ((uint2*)g_w1lo)[i] = make_uint2(pack2(l0, l1), pack2(l2, l3));
        return;
    }
    const float* w; __half *hi, *lo; int off;
    if (i < 24576)      { w = W2;  hi = g_w2hi;  lo = g_w2lo;  off = i - 16384; }
    else if (i < 32768) { w = W3;  hi = g_w3hi;  lo = g_w3lo;  off = i - 24576; }
    else                { w = Wd1; hi = g_wd1hi; lo = g_wd1lo; off = i - 32768; }
    float4 v = __ldg(((const float4*)w) + off);
    __half h0 = __float2half_rn(v.x), h1 = __float2half_rn(v.y);
    __half h2 = __float2half_rn(v.z), h3 = __float2half_rn(v.w);
    __half l0 = __float2half_rn((v.x - __half2float(h0)) * 1024.0f);
    __half l1 = __float2half_rn((v.y - __half2float(h1)) * 1024.0f);
    __half l2 = __float2half_rn((v.z - __half2float(h2)) * 1024.0f);
    __half l3 = __float2half_rn((v.w - __half2float(h3)) * 1024.0f);
    ((uint2*)hi)[off] = make_uint2(pack2h(h0, h1), pack2h(h2, h3));
    ((uint2*)lo)[off] = make_uint2(pack2h(l0, l1), pack2h(l2, l3));
}

// ============================================================
// CSR build chain (side stream — all kernels wide or tiny-regs)
// ============================================================
__global__ void zero_cnt_kernel() {
    int i = blockIdx.x * blockDim.x + threadIdx.x;
    if (i < NN) g_cnt[i] = 0;
}

__global__ void detect_kernel(const int* __restrict__ ei) {
    int z = 1;
    for (int i = 0; i < 64; i++)
        if (ei[2 * i + 1] != 0) { z = 0; break; }
    g_is64 = z;
}

__global__ void count_kernel(const int* __restrict__ ei) {
    int e = blockIdx.x * blockDim.x + threadIdx.x;
    if (e >= NE) return;
    int d = g_is64 ? __ldg(&ei[2 * ((size_t)NE + e)]) : __ldg(&ei[NE + e]);
    if ((unsigned)d < NN) atomicAdd(&g_cnt[d], 1);
}

// ---- 3-phase parallel exclusive scan of g_cnt -> g_rowptr/g_cursor ----
__global__ void scan_block_kernel() {          // grid SCAN_BLKS, block 1024
    __shared__ int sd[1024];
    int t = threadIdx.x;
    int i = blockIdx.x * 1024 + t;
    sd[t] = (i < NN) ? g_cnt[i] : 0;
    __syncthreads();
    #pragma unroll
    for (int off = 512; off > 0; off >>= 1) {
        if (t < off) sd[t] += sd[t + off];
        __syncthreads();
    }
    if (t == 0) g_bsum[blockIdx.x] = sd[0];
}

__global__ void scan_top_kernel() {            // 1 block, 128 threads (small regs)
    __shared__ int sd[128];
    int t = threadIdx.x;
    sd[t] = (t < SCAN_BLKS) ? g_bsum[t] : 0;
    __syncthreads();
    if (t == 0) {
        int run = 0;
        for (int b = 0; b < SCAN_BLKS; b++) {
            g_boff[b] = run;
            run += sd[b];
        }
        g_rowptr[NN] = run;
    }
}

__global__ void scan_apply_kernel() {          // grid SCAN_BLKS, block 1024
    __shared__ int sd[1024];
    int t = threadIdx.x;
    int i = blockIdx.x * 1024 + t;
    int v = (i < NN) ? g_cnt[i] : 0;
    sd[t] = v;
    __syncthreads();
    #pragma unroll
    for (int off = 1; off < 1024; off <<= 1) {
        int add = (t >= off) ? sd[t - off] : 0;
        __syncthreads();
        sd[t] += add;
        __syncthreads();
    }
    if (i < NN) {
        int excl = sd[t] - v + g_boff[blockIdx.x];
        g_rowptr[i] = excl;
        g_cursor[i] = excl;
    }
}

__global__ void fill_edges_kernel(const int* __restrict__ ei) {
    int e = blockIdx.x * blockDim.x + threadIdx.x;
    if (e >= NE) return;
    int s, d;
    if (g_is64) {
        s = __ldg(&ei[2 * e]);
        d = __ldg(&ei[2 * ((size_t)NE + e)]);
    } else {
        s = __ldg(&ei[e]);
        d = __ldg(&ei[NE + e]);
    }
    if ((unsigned)s < NN && (unsigned)d < NN) {
        int p = atomicAdd(&g_cursor[d], 1);
        g_colidx[p] = s;
    }
}

// ============================================================
// Layer-1 GEMM (bf16 3-pass exact) with FUSED x fp32->bf16 hi/lo
// conversion. CTA 128x256, 8 warps (2x4), warp tile 64x64.
// smem: AH 16K | AL 16K | XRAW 32K | BH0 32K | BL0 32K | BH1 32K | BL1 32K
// ============================================================
static constexpr int G0_AH  = 0;
static constexpr int G0_AL  = 16384;
static constexpr int G0_XR  = 32768;
static constexpr int G0_B0  = 65536;     // BH0; BL0 at +32768
static constexpr int G0_B1  = 131072;    // BH1; BL1 at +32768
static constexpr int G0_SMEM = 196608;
static constexpr int SSTRIDE = 260;

__global__ void __launch_bounds__(256, 1)
gemm0_kernel(const float* __restrict__ x, const float* __restrict__ bias) {
    extern __shared__ char smem[];
    uint32_t sb = smem_u32(smem);
    int tid = threadIdx.x, wid = tid >> 5, lane = tid & 31;
    int rowbase = blockIdx.x * 128;
    int wrow = wid & 1;
    int wcol = wid >> 1;

    float c[4][8][4];
    #pragma unroll
    for (int mt = 0; mt < 4; mt++)
        #pragma unroll
        for (int nt = 0; nt < 8; nt++)
            #pragma unroll
            for (int q = 0; q < 4; q++) c[mt][nt][q] = 0.f;

    int q8 = lane >> 3, l8 = lane & 7;

    auto issue_x = [&](int kb) {
        for (int t = tid; t < 2048; t += 256) {
            int r = t >> 4, g = t & 15;
            int gr = rowbase + r; if (gr >= NN) gr = NN - 1;   // pad rows masked later
            cp16(sb + G0_XR + (uint32_t)(r * 256 + g * 16),
                 x + (size_t)gr * D + kb + g * 4);
        }
    };
    auto issue_B = [&](int st, int kb) {
        uint32_t bh = sb + (st ? G0_B1 : G0_B0);
        for (int t = tid; t < 2048; t += 256) {
            int r = t >> 3, g = t & 7;
            uint32_t so = SW128((uint32_t)(r * 128 + g * 16));
            size_t ob = ((size_t)r * D + kb + g * 8) * 2;
            cp16(bh + so,         (const uint8_t*)g_w1hi + ob);
            cp16(bh + 32768 + so, (const uint8_t*)g_w1lo + ob);
        }
    };

    issue_x(0); issue_B(0, 0); cp_commit();

    for (int ch = 0; ch < 4; ch++) {
        cp_wait<0>();
        __syncthreads();
        #pragma unroll
        for (int j = 0; j < 8; j++) {
            int idx = tid + j * 256;
            float4 v = reinterpret_cast<const float4*>(smem + G0_XR)[idx];
            int r = idx >> 4, g4 = idx & 15;
            uint32_t bo = (uint32_t)(r * 128 + g4 * 8);
            uint32_t so = bo ^ ((bo >> 3) & 0x70);
            __nv_bfloat16 h0, l0, h1, l1, h2, l2, h3, l3;
            split_bf(v.x, h0, l0); split_bf(v.y, h1, l1);
            split_bf(v.z, h2, l2); split_bf(v.w, h3, l3);
            *reinterpret_cast<uint2*>(smem + G0_AH + so) = make_uint2(pack2(h0, h1), pack2(h2, h3));
            *reinterpret_cast<uint2*>(smem + G0_AL + so) = make_uint2(pack2(l0, l1), pack2(l2, l3));
        }
        __syncthreads();
        if (ch < 3) { issue_x((ch + 1) * 64); issue_B((ch + 1) & 1, (ch + 1) * 64); cp_commit(); }

        uint32_t bbh = sb + ((ch & 1) ? G0_B1 : G0_B0);
        #pragma unroll
        for (int ks = 0; ks < 4; ks++) {
            uint32_t ah[4][4], al[4][4];
            #pragma unroll
            for (int mt = 0; mt < 4; mt++) {
                int row = wrow * 64 + mt * 16 + (q8 & 1) * 8 + l8;
                uint32_t off = SW128((uint32_t)(row * 128 + ks * 32 + (q8 >> 1) * 16));
                ldsm4(ah[mt], sb + G0_AH + off);
                ldsm4(al[mt], sb + G0_AL + off);
            }
            #pragma unroll
            for (int nt = 0; nt < 4; nt++) {
                int nrow = wcol * 64 + nt * 16 + ((q8 >> 1) & 1) * 8 + l8;
                uint32_t off = SW128((uint32_t)(nrow * 128 + ks * 32 + (q8 & 1) * 16));
                uint32_t bh[4], bl[4];
                ldsm4(bh, bbh + off);
                ldsm4(bl, bbh + 32768 + off);
                #pragma unroll
                for (int mt = 0; mt < 4; mt++) {
                    mma_bf16(c[mt][nt * 2],     ah[mt], bh[0], bh[1]);
                    mma_bf16(c[mt][nt * 2],     ah[mt], bl[0], bl[1]);
                    mma_bf16(c[mt][nt * 2],     al[mt], bh[0], bh[1]);
                    mma_bf16(c[mt][nt * 2 + 1], ah[mt], bh[2], bh[3]);
                    mma_bf16(c[mt][nt * 2 + 1], ah[mt], bl[2], bl[3]);
                    mma_bf16(c[mt][nt * 2 + 1], al[mt], bh[2], bh[3]);
                }
            }
        }
        __syncthreads();
    }

    float* stage = reinterpret_cast<float*>(smem);
    #pragma unroll
    for (int mt = 0; mt < 4; mt++)
        #pragma unroll
        for (int nt = 0; nt < 8; nt++) {
            int r0  = wrow * 64 + mt * 16 + (lane >> 2);
            int col = wcol * 64 + nt * 8 + 2 * (lane & 3);
            float* p = stage + r0 * SSTRIDE + col;
            p[0] = c[mt][nt][0];
            p[1] = c[mt][nt][1];
            p[8 * SSTRIDE]     = c[mt][nt][2];
            p[8 * SSTRIDE + 1] = c[mt][nt][3];
        }
    __syncthreads();

    for (int r = wid; r < 128; r += 8) {
        int gr = rowbase + r;
        bool ok = gr < NN;
        const float* rowp = stage + r * SSTRIDE + lane * 8;
        int cb = lane * 8;
        float v[8];
        float ss = 0.f;
        #pragma unroll
        for (int j = 0; j < 8; j++) {
            v[j] = fmaxf(rowp[j] + __ldg(&bias[cb + j]), 0.f);
            ss += v[j] * v[j];
        }
        #pragma unroll
        for (int off = 16; off >= 1; off >>= 1)
            ss += __shfl_xor_sync(0xffffffffu, ss, off);
        float rn = rsqrtf(ss);
        if (ok) {
            __half h[8];
            #pragma unroll
            for (int j = 0; j < 8; j++) h[j] = __float2half_rn(v[j] * rn);
            *reinterpret_cast<uint4*>(g_h + (size_t)gr * D + cb) =
                make_uint4(pack2h(h[0], h[1]), pack2h(h[2], h[3]),
                           pack2h(h[4], h[5]), pack2h(h[6], h[7]));
        }
    }
}

// ============================================================
// fp16 N=256 GEMM (mid MODE 1, final MODE 2): CTA 128x256,
// hi pass f32-acc + lo pass f16-acc (lo plane pre-scaled x1024).
// ============================================================
static constexpr int F_OF_BH = 16384;
static constexpr int F_OF_BL = 49152;
static constexpr int F_STG   = 81920;
static constexpr int F_SMEM  = 2 * F_STG;

template <int MODE>   // 1 = mid ([W2;W3]) , 2 = final (Wd1)
__global__ void __launch_bounds__(256, 1)
gemm_kernel(const float* __restrict__ bias, const float* __restrict__ wd2,
            const float* __restrict__ bd2, float* __restrict__ out) {
    extern __shared__ char smem[];
    uint32_t sb = smem_u32(smem);
    int tid = threadIdx.x, wid = tid >> 5, lane = tid & 31;
    int rowbase = blockIdx.x * 128;
    int wrow = wid & 1;
    int wcol = wid >> 1;

    const uint8_t *BloH, *BloL, *BupH, *BupL;
    if (MODE == 1) {
        BloH = (const uint8_t*)g_w2hi;  BloL = (const uint8_t*)g_w2lo;
        BupH = (const uint8_t*)g_w3hi;  BupL = (const uint8_t*)g_w3lo;
    } else {
        BloH = (const uint8_t*)g_wd1hi; BloL = (const uint8_t*)g_wd1lo;
        BupH = (const uint8_t*)(g_wd1hi + 128 * D); BupL = (const uint8_t*)(g_wd1lo + 128 * D);
    }

    float c[4][8][4];
    uint32_t c16[4][8][2];
    #pragma unroll
    for (int mt = 0; mt < 4; mt++)
        #pragma unroll
        for (int nt = 0; nt < 8; nt++) {
            #pragma unroll
            for (int q = 0; q < 4; q++) c[mt][nt][q] = 0.f;
            c16[mt][nt][0] = 0u; c16[mt][nt][1] = 0u;
        }

    int q8 = lane >> 3, l8 = lane & 7;

    auto issue = [&](uint32_t sbuf, int kb) {
        for (int t = tid; t < 1024; t += 256) {
            int r = t >> 3, g = t & 7;
            uint32_t so = SW128((uint32_t)(r * 128 + g * 16));
            cp16(sbuf + so,
                 (const uint8_t*)g_h + ((size_t)(rowbase + r) * D + kb + g * 8) * 2);
        }
        for (int t = tid; t < 2048; t += 256) {
            int r = t >> 3, g = t & 7;
            uint32_t so = SW128((uint32_t)(r * 128 + g * 16));
            size_t ob = ((size_t)(r < 128 ? r : r - 128) * D + kb + g * 8) * 2;
            cp16(sbuf + F_OF_BH + so, (r < 128 ? BloH : BupH) + ob);
            cp16(sbuf + F_OF_BL + so, (r < 128 ? BloL : BupL) + ob);
        }
    };

    issue(sb, 0);
    cp_commit();

    for (int ch = 0; ch < 4; ch++) {
        uint32_t buf = sb + (uint32_t)(ch & 1) * F_STG;
        if (ch < 3) {
            issue(sb + (uint32_t)((ch + 1) & 1) * F_STG, (ch + 1) * 64);
            cp_commit();
            cp_wait<1>();
        } else {
            cp_wait<0>();
        }
        __syncthreads();

        #pragma unroll
        for (int ks = 0; ks < 4; ks++) {
            uint32_t ah[4][4];
            #pragma unroll
            for (int mt = 0; mt < 4; mt++) {
                int row = wrow * 64 + mt * 16 + (q8 & 1) * 8 + l8;
                uint32_t off = SW128((uint32_t)(row * 128 + ks * 32 + (q8 >> 1) * 16));
                ldsm4(ah[mt], buf + off);
            }
            #pragma unroll
            for (int nt = 0; nt < 4; nt++) {
                int nrow = wcol * 64 + nt * 16 + ((q8 >> 1) & 1) * 8 + l8;
                uint32_t off = SW128((uint32_t)(nrow * 128 + ks * 32 + (q8 & 1) * 16));
                uint32_t bh[4], bl[4];
                ldsm4(bh, buf + F_OF_BH + off);
                ldsm4(bl, buf + F_OF_BL + off);
                #pragma unroll
                for (int mt = 0; mt < 4; mt++) {
                    mma_f16 (c[mt][nt * 2],       ah[mt], bh[0], bh[1]);   // hi, f32 acc
                    mma_f16 (c[mt][nt * 2 + 1],   ah[mt], bh[2], bh[3]);
                    mma_f16h(c16[mt][nt * 2],     ah[mt], bl[0], bl[1]);   // lo, f16 acc
                    mma_f16h(c16[mt][nt * 2 + 1], ah[mt], bl[2], bl[3]);
                }
            }
        }
        __syncthreads();
    }

    const float INV = 1.0f / 1024.0f;
    #pragma unroll
    for (int mt = 0; mt < 4; mt++)
        #pragma unroll
        for (int nt = 0; nt < 8; nt++) {
            __half2 p0 = *reinterpret_cast<__half2*>(&c16[mt][nt][0]);
            __half2 p1 = *reinterpret_cast<__half2*>(&c16[mt][nt][1]);
            c[mt][nt][0] += __low2float(p0) * INV;
            c[mt][nt][1] += __high2float(p0) * INV;
            c[mt][nt][2] += __low2float(p1) * INV;
            c[mt][nt][3] += __high2float(p1) * INV;
        }

    float* stage = reinterpret_cast<float*>(smem);
    #pragma unroll
    for (int mt = 0; mt < 4; mt++)
        #pragma unroll
        for (int nt = 0; nt < 8; nt++) {
            int r0  = wrow * 64 + mt * 16 + (lane >> 2);
            int col = wcol * 64 + nt * 8 + 2 * (lane & 3);
            float* p = stage + r0 * SSTRIDE + col;
            p[0] = c[mt][nt][0];
            p[1] = c[mt][nt][1];
            p[8 * SSTRIDE]     = c[mt][nt][2];
            p[8 * SSTRIDE + 1] = c[mt][nt][3];
        }
    __syncthreads();

    for (int r = wid; r < 128; r += 8) {
        int gr = rowbase + r;
        bool ok = gr < NN;
        const float* rowp = stage + r * SSTRIDE + lane * 8;
        int cb = lane * 8;

        if (MODE == 1) {
            float v[8];
            if (lane < 16) {
                #pragma unroll
                for (int j = 0; j < 8; j++)
                    v[j] = fmaxf(rowp[j] + __ldg(&bias[cb + j]), 0.f);
                if (ok) {
                    float4* dst = reinterpret_cast<float4*>(g_a + (size_t)gr * DH + cb);
                    dst[0] = make_float4(v[0], v[1], v[2], v[3]);
                    dst[1] = make_float4(v[4], v[5], v[6], v[7]);
                }
            } else {
                #pragma unroll
                for (int j = 0; j < 8; j++) v[j] = rowp[j];
                if (ok) {
                    float4* dst = reinterpret_cast<float4*>(g_y + (size_t)gr * DH + (cb - 128));
                    dst[0] = make_float4(v[0], v[1], v[2], v[3]);
                    dst[1] = make_float4(v[4], v[5], v[6], v[7]);
                }
            }
        } else {
            float acc = 0.f;
            #pragma unroll
            for (int j = 0; j < 8; j++) {
                float vv = fmaxf(rowp[j] + __ldg(&bias[cb + j]), 0.f);
                acc += vv * __ldg(&wd2[cb + j]);
            }
            #pragma unroll
            for (int off = 16; off >= 1; off >>= 1)
                acc += __shfl_xor_sync(0xffffffffu, acc, off);
            if (lane == 0 && ok) out[gr] = acc + __ldg(bd2);
        }
    }
}

// ============================================================
// Fused CSR gather-reduce + bias + relu + l2norm + fp16 store
// One warp per dst node; lane owns 4 cols of each 128-wide half.
// ============================================================
__global__ void agg_combine_kernel(const float* __restrict__ b3) {
    int gw = (blockIdx.x * blockDim.x + threadIdx.x) >> 5;
    int lane = threadIdx.x & 31;
    if (gw >= NN) return;
    int n = gw;
    int beg = __ldg(&g_rowptr[n]);
    int end = __ldg(&g_rowptr[n + 1]);

    float ax = 0.f, ay = 0.f, az = 0.f, aw = 0.f;
    int i = beg;
    for (; i + 4 <= end; i += 4) {
        int s0 = __ldg(&g_colidx[i]);
        int s1 = __ldg(&g_colidx[i + 1]);
        int s2 = __ldg(&g_colidx[i + 2]);
        int s3 = __ldg(&g_colidx[i + 3]);
        float4 v0 = __ldg(reinterpret_cast<const float4*>(g_y + (size_t)s0 * DH) + lane);
        float4 v1 = __ldg(reinterpret_cast<const float4*>(g_y + (size_t)s1 * DH) + lane);
        float4 v2 = __ldg(reinterpret_cast<const float4*>(g_y + (size_t)s2 * DH) + lane);
        float4 v3 = __ldg(reinterpret_cast<const float4*>(g_y + (size_t)s3 * DH) + lane);
        ax += (v0.x + v1.x) + (v2.x + v3.x);
        ay += (v0.y + v1.y) + (v2.y + v3.y);
        az += (v0.z + v1.z) + (v2.z + v3.z);
        aw += (v0.w + v1.w) + (v2.w + v3.w);
    }
    for (; i < end; i++) {
        int s = __ldg(&g_colidx[i]);
        float4 v = __ldg(reinterpret_cast<const float4*>(g_y + (size_t)s * DH) + lane);
        ax += v.x; ay += v.y; az += v.z; aw += v.w;
    }

    float4 av = __ldg(reinterpret_cast<const float4*>(g_a + (size_t)n * DH) + lane);
    float4 bb = __ldg(reinterpret_cast<const float4*>(b3) + lane);
    float m0 = fmaxf(ax + bb.x, 0.f);
    float m1 = fmaxf(ay + bb.y, 0.f);
    float m2 = fmaxf(az + bb.z, 0.f);
    float m3 = fmaxf(aw + bb.w, 0.f);

    float ss = av.x * av.x + av.y * av.y + av.z * av.z + av.w * av.w
             + m0 * m0 + m1 * m1 + m2 * m2 + m3 * m3;
    #pragma unroll
    for (int off = 16; off >= 1; off >>= 1)
        ss += __shfl_xor_sync(0xffffffffu, ss, off);
    float rn = rsqrtf(ss);

    size_t base = (size_t)n * D;
    *reinterpret_cast<uint2*>(g_h + base + lane * 4) =
        make_uint2(pack2h(__float2half_rn(av.x * rn), __float2half_rn(av.y * rn)),
                   pack2h(__float2half_rn(av.z * rn), __float2half_rn(av.w * rn)));
    *reinterpret_cast<uint2*>(g_h + base + 128 + lane * 4) =
        make_uint2(pack2h(__float2half_rn(m0 * rn), __float2half_rn(m1 * rn)),
                   pack2h(__float2half_rn(m2 * rn), __float2half_rn(m3 * rn)));
}

// ============================================================
// Host launcher — CSR chain (all wide / tiny-reg kernels) on a
// side stream overlapping conv_w + gemm0 + first mid GEMM;
// joins before the first agg_combine.
// ============================================================
static cudaStream_t s2 = nullptr;
static cudaEvent_t evFork, evCSR;

extern "C" void kernel_launch(void* const* d_in, const int* in_sizes, int n_in,
                              void* d_out, int out_size) {
    const float* x   = (const float*)d_in[0];
    const int*   ei  = (const int*)d_in[1];    // int32 or int64 (auto-detected)
    const float* W1  = (const float*)d_in[2];
    const float* b1  = (const float*)d_in[3];
    const float* W2  = (const float*)d_in[4];
    const float* b2  = (const float*)d_in[5];
    const float* W3  = (const float*)d_in[6];
    const float* b3  = (const float*)d_in[7];
    const float* Wd1 = (const float*)d_in[8];
    const float* bd1 = (const float*)d_in[9];
    const float* Wd2 = (const float*)d_in[10];
    const float* bd2 = (const float*)d_in[11];
    float* out = (float*)d_out;

    if (!s2) {
        cudaStreamCreateWithFlags(&s2, cudaStreamNonBlocking);
        cudaEventCreateWithFlags(&evFork, cudaEventDisableTiming);
        cudaEventCreateWithFlags(&evCSR,  cudaEventDisableTiming);
        cudaFuncSetAttribute(gemm0_kernel,   cudaFuncAttributeMaxDynamicSharedMemorySize, G0_SMEM);
        cudaFuncSetAttribute(gemm_kernel<1>, cudaFuncAttributeMaxDynamicSharedMemorySize, F_SMEM);
        cudaFuncSetAttribute(gemm_kernel<2>, cudaFuncAttributeMaxDynamicSharedMemorySize, F_SMEM);
    }

    // ---- fork side stream: full CSR build (independent of main chain)
    cudaEventRecord(evFork, 0);
    cudaStreamWaitEvent(s2, evFork, 0);
    zero_cnt_kernel<<<(NN + 255) / 256, 256, 0, s2>>>();
    detect_kernel<<<1, 1, 0, s2>>>(ei);
    count_kernel<<<(NE + 255) / 256, 256, 0, s2>>>(ei);
    scan_block_kernel<<<SCAN_BLKS, 1024, 0, s2>>>();
    scan_top_kernel<<<1, 128, 0, s2>>>();
    scan_apply_kernel<<<SCAN_BLKS, 1024, 0, s2>>>();
    fill_edges_kernel<<<(NE + 255) / 256, 256, 0, s2>>>(ei);
    cudaEventRecord(evCSR, s2);

    // ---- main stream: weights + layer 1 + first mid GEMM
    conv_w_all_kernel<<<192, 256>>>(W1, W2, W3, Wd1);
    gemm0_kernel<<<NB128, 256, G0_SMEM>>>(x, b1);

    // conv layer 1
    gemm_kernel<1><<<NB128, 256, F_SMEM>>>(b2, nullptr, nullptr, nullptr);
    cudaStreamWaitEvent(0, evCSR, 0);          // join CSR before first gather
    agg_combine_kernel<<<(NN * 32 + 255) / 256, 256>>>(b3);

    // conv layer 2
    gemm_kernel<1><<<NB128, 256, F_SMEM>>>(b2, nullptr, nullptr, nullptr);
    agg_combine_kernel<<<(NN * 32 + 255) / 256, 256>>>(b3);

    // head: out = relu(h @ Wd1^T + bd1) @ Wd2^T + bd2
    gemm_kernel<2><<<NB128, 256, F_SMEM>>>(bd1, Wd2, bd2, out);
}

// round 15
// speedup vs baseline: 1.8072x; 1.0209x over previous
#include <cuda_runtime.h>
#include <cuda_bf16.h>
#include <cuda_fp16.h>
#include <cstdint>
#include <cstddef>

// ============================================================
// Problem constants
// ============================================================
#define NN   100000      // nodes
#define NE   1600000     // edges
#define NP   100096      // padded: 128*782
#define NB128 782        // GEMM row tiles (128 rows each)
#define D    256
#define DH   128
#define SCAN_BLKS 98     // ceil(NN / 1024)

// ============================================================
// Device global scratch (no cudaMalloc allowed)
// ============================================================
__device__ __align__(256) __half g_h[(size_t)NP * D];   // activations (fp16)
__device__ __align__(256) float g_a[(size_t)NP * DH];   // relu(x@W2^T + b2)
__device__ __align__(256) float g_y[(size_t)NP * DH];   // x@W3^T fp32 (layer 1)
__device__ __align__(256) __half g_yh[(size_t)NP * DH]; // x@W3^T fp16 (layer 2)
__device__ __align__(256) __nv_bfloat16 g_w1hi[D * D],  g_w1lo[D * D];
__device__ __align__(256) __half g_w2hi[DH * D], g_w2lo[DH * D];   // lo scaled x1024
__device__ __align__(256) __half g_w3hi[DH * D], g_w3lo[DH * D];   // lo scaled x1024
__device__ __align__(256) __half g_wd1hi[D * D], g_wd1lo[D * D];   // lo scaled x1024
__device__ __align__(256) int g_rowptr[NN + 1];
__device__ __align__(256) int g_cursor[NN];
__device__ __align__(256) int g_cnt[NN];
__device__ __align__(256) int g_colidx[NE];
__device__ __align__(256) int g_bsum[128];
__device__ __align__(256) int g_boff[128];
__device__ int g_is64;

// ============================================================
// Helpers
// ============================================================
__device__ __forceinline__ uint32_t smem_u32(const void* p) {
    uint32_t a;
    asm("{ .reg .u64 t; cvta.to.shared.u64 t, %1; cvt.u32.u64 %0, t; }"
        : "=r"(a) : "l"(p));
    return a;
}

#define SW128(o) ((o) ^ (((o) >> 3) & 0x70))

__device__ __forceinline__ void cp16(uint32_t dst, const void* src) {
    asm volatile("cp.async.cg.shared.global [%0], [%1], 16;" :: "r"(dst), "l"(src));
}
__device__ __forceinline__ void cp_commit() {
    asm volatile("cp.async.commit_group;" ::: "memory");
}
template <int N>
__device__ __forceinline__ void cp_wait() {
    asm volatile("cp.async.wait_group %0;" :: "n"(N) : "memory");
}

__device__ __forceinline__ void ldsm4(uint32_t* r, uint32_t addr) {
    asm volatile("ldmatrix.sync.aligned.m8n8.x4.shared.b16 {%0,%1,%2,%3}, [%4];"
        : "=r"(r[0]), "=r"(r[1]), "=r"(r[2]), "=r"(r[3]) : "r"(addr));
}

__device__ __forceinline__ void mma_bf16(float* c, const uint32_t* a,
                                         uint32_t b0, uint32_t b1) {
    asm volatile(
        "mma.sync.aligned.m16n8k16.row.col.f32.bf16.bf16.f32 "
        "{%0,%1,%2,%3}, {%4,%5,%6,%7}, {%8,%9}, {%0,%1,%2,%3};"
        : "+f"(c[0]), "+f"(c[1]), "+f"(c[2]), "+f"(c[3])
        : "r"(a[0]), "r"(a[1]), "r"(a[2]), "r"(a[3]), "r"(b0), "r"(b1));
}
__device__ __forceinline__ void mma_f16(float* c, const uint32_t* a,
                                        uint32_t b0, uint32_t b1) {
    asm volatile(
        "mma.sync.aligned.m16n8k16.row.col.f32.f16.f16.f32 "
        "{%0,%1,%2,%3}, {%4,%5,%6,%7}, {%8,%9}, {%0,%1,%2,%3};"
        : "+f"(c[0]), "+f"(c[1]), "+f"(c[2]), "+f"(c[3])
        : "r"(a[0]), "r"(a[1]), "r"(a[2]), "r"(a[3]), "r"(b0), "r"(b1));
}
// f16 accumulator variant (2 f16x2 regs) — used for the lo pass
__device__ __forceinline__ void mma_f16h(uint32_t* c2, const uint32_t* a,
                                         uint32_t b0, uint32_t b1) {
    asm volatile(
        "mma.sync.aligned.m16n8k16.row.col.f16.f16.f16.f16 "
        "{%0,%1}, {%2,%3,%4,%5}, {%6,%7}, {%0,%1};"
        : "+r"(c2[0]), "+r"(c2[1])
        : "r"(a[0]), "r"(a[1]), "r"(a[2]), "r"(a[3]), "r"(b0), "r"(b1));
}

__device__ __forceinline__ void split_bf(float v, __nv_bfloat16& h, __nv_bfloat16& l) {
    h = __float2bfloat16(v);
    l = __float2bfloat16(v - __bfloat162float(h));
}
__device__ __forceinline__ uint32_t pack2(__nv_bfloat16 a, __nv_bfloat16 b) {
    __nv_bfloat162 t; t.x = a; t.y = b;
    return *reinterpret_cast<uint32_t*>(&t);
}
__device__ __forceinline__ uint32_t pack2h(__half a, __half b) {
    __half2 t; t.x = a; t.y = b;
    return *reinterpret_cast<uint32_t*>(&t);
}

// ============================================================
// Weight conversion (one kernel)
// W1 -> bf16 hi/lo ; W2/W3/Wd1 -> fp16 hi + (lo * 1024) fp16
// ============================================================
__global__ void conv_w_all_kernel(const float* __restrict__ W1,
                                  const float* __restrict__ W2,
                                  const float* __restrict__ W3,
                                  const float* __restrict__ Wd1) {
    int i = blockIdx.x * blockDim.x + threadIdx.x;
    if (i >= 49152) return;
    if (i < 16384) {
        float4 v = __ldg(((const float4*)W1) + i);
        __nv_bfloat16 h0, l0, h1, l1, h2, l2, h3, l3;
        split_bf(v.x, h0, l0); split_bf(v.y, h1, l1);
        split_bf(v.z, h2, l2); split_bf(v.w, h3, l3);
        ((uint2*)g_w1hi)[i] = make_uint2(pack2(h0, h1), pack2(h2, h3));
        ((uint2*)g_w1lo)[i] = make_uint2(pack2(l0, l1), pack2(l2, l3));
        return;
    }
    const float* w; __half *hi, *lo; int off;
    if (i < 24576)      { w = W2;  hi = g_w2hi;  lo = g_w2lo;  off = i - 16384; }
    else if (i < 32768) { w = W3;  hi = g_w3hi;  lo = g_w3lo;  off = i - 24576; }
    else                { w = Wd1; hi = g_wd1hi; lo = g_wd1lo; off = i - 32768; }
    float4 v = __ldg(((const float4*)w) + off);
    __half h0 = __float2half_rn(v.x), h1 = __float2half_rn(v.y);
    __half h2 = __float2half_rn(v.z), h3 = __float2half_rn(v.w);
    __half l0 = __float2half_rn((v.x - __half2float(h0)) * 1024.0f);
    __half l1 = __float2half_rn((v.y - __half2float(h1)) * 1024.0f);
    __half l2 = __float2half_rn((v.z - __half2float(h2)) * 1024.0f);
    __half l3 = __float2half_rn((v.w - __half2float(h3)) * 1024.0f);
    ((uint2*)hi)[off] = make_uint2(pack2h(h0, h1), pack2h(h2, h3));
    ((uint2*)lo)[off] = make_uint2(pack2h(l0, l1), pack2h(l2, l3));
}

// ============================================================
// CSR build chain (side stream — all kernels wide or tiny-regs)
// ============================================================
__global__ void zero_cnt_kernel() {
    int i = blockIdx.x * blockDim.x + threadIdx.x;
    if (i < NN) g_cnt[i] = 0;
}

__global__ void detect_kernel(const int* __restrict__ ei) {
    int z = 1;
    for (int i = 0; i < 64; i++)
        if (ei[2 * i + 1] != 0) { z = 0; break; }
    g_is64 = z;
}

__global__ void count_kernel(const int* __restrict__ ei) {
    int e = blockIdx.x * blockDim.x + threadIdx.x;
    if (e >= NE) return;
    int d = g_is64 ? __ldg(&ei[2 * ((size_t)NE + e)]) : __ldg(&ei[NE + e]);
    if ((unsigned)d < NN) atomicAdd(&g_cnt[d], 1);
}

// ---- 3-phase parallel exclusive scan of g_cnt -> g_rowptr/g_cursor ----
__global__ void scan_block_kernel() {          // grid SCAN_BLKS, block 1024
    __shared__ int sd[1024];
    int t = threadIdx.x;
    int i = blockIdx.x * 1024 + t;
    sd[t] = (i < NN) ? g_cnt[i] : 0;
    __syncthreads();
    #pragma unroll
    for (int off = 512; off > 0; off >>= 1) {
        if (t < off) sd[t] += sd[t + off];
        __syncthreads();
    }
    if (t == 0) g_bsum[blockIdx.x] = sd[0];
}

__global__ void scan_top_kernel() {            // 1 block, 128 threads (small regs)
    __shared__ int sd[128];
    int t = threadIdx.x;
    sd[t] = (t < SCAN_BLKS) ? g_bsum[t] : 0;
    __syncthreads();
    if (t == 0) {
        int run = 0;
        for (int b = 0; b < SCAN_BLKS; b++) {
            g_boff[b] = run;
            run += sd[b];
        }
        g_rowptr[NN] = run;
    }
}

__global__ void scan_apply_kernel() {          // grid SCAN_BLKS, block 1024
    __shared__ int sd[1024];
    int t = threadIdx.x;
    int i = blockIdx.x * 1024 + t;
    int v = (i < NN) ? g_cnt[i] : 0;
    sd[t] = v;
    __syncthreads();
    #pragma unroll
    for (int off = 1; off < 1024; off <<= 1) {
        int add = (t >= off) ? sd[t - off] : 0;
        __syncthreads();
        sd[t] += add;
        __syncthreads();
    }
    if (i < NN) {
        int excl = sd[t] - v + g_boff[blockIdx.x];
        g_rowptr[i] = excl;
        g_cursor[i] = excl;
    }
}

__global__ void fill_edges_kernel(const int* __restrict__ ei) {
    int e = blockIdx.x * blockDim.x + threadIdx.x;
    if (e >= NE) return;
    int s, d;
    if (g_is64) {
        s = __ldg(&ei[2 * e]);
        d = __ldg(&ei[2 * ((size_t)NE + e)]);
    } else {
        s = __ldg(&ei[e]);
        d = __ldg(&ei[NE + e]);
    }
    if ((unsigned)s < NN && (unsigned)d < NN) {
        int p = atomicAdd(&g_cursor[d], 1);
        g_colidx[p] = s;
    }
}

// ============================================================
// Layer-1 GEMM (bf16 3-pass exact) with FUSED x fp32->bf16 hi/lo
// conversion. CTA 128x256, 8 warps (2x4), warp tile 64x64.
// smem: AH 16K | AL 16K | XRAW 32K | BH0 32K | BL0 32K | BH1 32K | BL1 32K
// ============================================================
static constexpr int G0_AH  = 0;
static constexpr int G0_AL  = 16384;
static constexpr int G0_XR  = 32768;
static constexpr int G0_B0  = 65536;     // BH0; BL0 at +32768
static constexpr int G0_B1  = 131072;    // BH1; BL1 at +32768
static constexpr int G0_SMEM = 196608;
static constexpr int SSTRIDE = 260;

__global__ void __launch_bounds__(256, 1)
gemm0_kernel(const float* __restrict__ x, const float* __restrict__ bias) {
    extern __shared__ char smem[];
    uint32_t sb = smem_u32(smem);
    int tid = threadIdx.x, wid = tid >> 5, lane = tid & 31;
    int rowbase = blockIdx.x * 128;
    int wrow = wid & 1;
    int wcol = wid >> 1;

    float c[4][8][4];
    #pragma unroll
    for (int mt = 0; mt < 4; mt++)
        #pragma unroll
        for (int nt = 0; nt < 8; nt++)
            #pragma unroll
            for (int q = 0; q < 4; q++) c[mt][nt][q] = 0.f;

    int q8 = lane >> 3, l8 = lane & 7;

    auto issue_x = [&](int kb) {
        for (int t = tid; t < 2048; t += 256) {
            int r = t >> 4, g = t & 15;
            int gr = rowbase + r; if (gr >= NN) gr = NN - 1;   // pad rows masked later
            cp16(sb + G0_XR + (uint32_t)(r * 256 + g * 16),
                 x + (size_t)gr * D + kb + g * 4);
        }
    };
    auto issue_B = [&](int st, int kb) {
        uint32_t bh = sb + (st ? G0_B1 : G0_B0);
        for (int t = tid; t < 2048; t += 256) {
            int r = t >> 3, g = t & 7;
            uint32_t so = SW128((uint32_t)(r * 128 + g * 16));
            size_t ob = ((size_t)r * D + kb + g * 8) * 2;
            cp16(bh + so,         (const uint8_t*)g_w1hi + ob);
            cp16(bh + 32768 + so, (const uint8_t*)g_w1lo + ob);
        }
    };

    issue_x(0); issue_B(0, 0); cp_commit();

    for (int ch = 0; ch < 4; ch++) {
        cp_wait<0>();
        __syncthreads();
        #pragma unroll
        for (int j = 0; j < 8; j++) {
            int idx = tid + j * 256;
            float4 v = reinterpret_cast<const float4*>(smem + G0_XR)[idx];
            int r = idx >> 4, g4 = idx & 15;
            uint32_t bo = (uint32_t)(r * 128 + g4 * 8);
            uint32_t so = bo ^ ((bo >> 3) & 0x70);
            __nv_bfloat16 h0, l0, h1, l1, h2, l2, h3, l3;
            split_bf(v.x, h0, l0); split_bf(v.y, h1, l1);
            split_bf(v.z, h2, l2); split_bf(v.w, h3, l3);
            *reinterpret_cast<uint2*>(smem + G0_AH + so) = make_uint2(pack2(h0, h1), pack2(h2, h3));
            *reinterpret_cast<uint2*>(smem + G0_AL + so) = make_uint2(pack2(l0, l1), pack2(l2, l3));
        }
        __syncthreads();
        if (ch < 3) { issue_x((ch + 1) * 64); issue_B((ch + 1) & 1, (ch + 1) * 64); cp_commit(); }

        uint32_t bbh = sb + ((ch & 1) ? G0_B1 : G0_B0);
        #pragma unroll
        for (int ks = 0; ks < 4; ks++) {
            uint32_t ah[4][4], al[4][4];
            #pragma unroll
            for (int mt = 0; mt < 4; mt++) {
                int row = wrow * 64 + mt * 16 + (q8 & 1) * 8 + l8;
                uint32_t off = SW128((uint32_t)(row * 128 + ks * 32 + (q8 >> 1) * 16));
                ldsm4(ah[mt], sb + G0_AH + off);
                ldsm4(al[mt], sb + G0_AL + off);
            }
            #pragma unroll
            for (int nt = 0; nt < 4; nt++) {
                int nrow = wcol * 64 + nt * 16 + ((q8 >> 1) & 1) * 8 + l8;
                uint32_t off = SW128((uint32_t)(nrow * 128 + ks * 32 + (q8 & 1) * 16));
                uint32_t bh[4], bl[4];
                ldsm4(bh, bbh + off);
                ldsm4(bl, bbh + 32768 + off);
                #pragma unroll
                for (int mt = 0; mt < 4; mt++) {
                    mma_bf16(c[mt][nt * 2],     ah[mt], bh[0], bh[1]);
                    mma_bf16(c[mt][nt * 2],     ah[mt], bl[0], bl[1]);
                    mma_bf16(c[mt][nt * 2],     al[mt], bh[0], bh[1]);
                    mma_bf16(c[mt][nt * 2 + 1], ah[mt], bh[2], bh[3]);
                    mma_bf16(c[mt][nt * 2 + 1], ah[mt], bl[2], bl[3]);
                    mma_bf16(c[mt][nt * 2 + 1], al[mt], bh[2], bh[3]);
                }
            }
        }
        __syncthreads();
    }

    float* stage = reinterpret_cast<float*>(smem);
    #pragma unroll
    for (int mt = 0; mt < 4; mt++)
        #pragma unroll
        for (int nt = 0; nt < 8; nt++) {
            int r0  = wrow * 64 + mt * 16 + (lane >> 2);
            int col = wcol * 64 + nt * 8 + 2 * (lane & 3);
            float* p = stage + r0 * SSTRIDE + col;
            p[0] = c[mt][nt][0];
            p[1] = c[mt][nt][1];
            p[8 * SSTRIDE]     = c[mt][nt][2];
            p[8 * SSTRIDE + 1] = c[mt][nt][3];
        }
    __syncthreads();

    for (int r = wid; r < 128; r += 8) {
        int gr = rowbase + r;
        bool ok = gr < NN;
        const float* rowp = stage + r * SSTRIDE + lane * 8;
        int cb = lane * 8;
        float v[8];
        float ss = 0.f;
        #pragma unroll
        for (int j = 0; j < 8; j++) {
            v[j] = fmaxf(rowp[j] + __ldg(&bias[cb + j]), 0.f);
            ss += v[j] * v[j];
        }
        #pragma unroll
        for (int off = 16; off >= 1; off >>= 1)
            ss += __shfl_xor_sync(0xffffffffu, ss, off);
        float rn = rsqrtf(ss);
        if (ok) {
            __half h[8];
            #pragma unroll
            for (int j = 0; j < 8; j++) h[j] = __float2half_rn(v[j] * rn);
            *reinterpret_cast<uint4*>(g_h + (size_t)gr * D + cb) =
                make_uint4(pack2h(h[0], h[1]), pack2h(h[2], h[3]),
                           pack2h(h[4], h[5]), pack2h(h[6], h[7]));
        }
    }
}

// ============================================================
// fp16 N=256 GEMM: CTA 128x256, hi pass f32-acc + lo pass
// f16-acc (lo plane pre-scaled x1024).
//  MODE 1: mid, y -> g_y (fp32)   [layer 1]
//  MODE 3: mid, y -> g_yh (fp16)  [layer 2]
//  MODE 2: final head -> out
// ============================================================
static constexpr int F_OF_BH = 16384;
static constexpr int F_OF_BL = 49152;
static constexpr int F_STG   = 81920;
static constexpr int F_SMEM  = 2 * F_STG;

template <int MODE>
__global__ void __launch_bounds__(256, 1)
gemm_kernel(const float* __restrict__ bias, const float* __restrict__ wd2,
            const float* __restrict__ bd2, float* __restrict__ out) {
    extern __shared__ char smem[];
    uint32_t sb = smem_u32(smem);
    int tid = threadIdx.x, wid = tid >> 5, lane = tid & 31;
    int rowbase = blockIdx.x * 128;
    int wrow = wid & 1;
    int wcol = wid >> 1;

    const uint8_t *BloH, *BloL, *BupH, *BupL;
    if (MODE == 1 || MODE == 3) {
        BloH = (const uint8_t*)g_w2hi;  BloL = (const uint8_t*)g_w2lo;
        BupH = (const uint8_t*)g_w3hi;  BupL = (const uint8_t*)g_w3lo;
    } else {
        BloH = (const uint8_t*)g_wd1hi; BloL = (const uint8_t*)g_wd1lo;
        BupH = (const uint8_t*)(g_wd1hi + 128 * D); BupL = (const uint8_t*)(g_wd1lo + 128 * D);
    }

    float c[4][8][4];
    uint32_t c16[4][8][2];
    #pragma unroll
    for (int mt = 0; mt < 4; mt++)
        #pragma unroll
        for (int nt = 0; nt < 8; nt++) {
            #pragma unroll
            for (int q = 0; q < 4; q++) c[mt][nt][q] = 0.f;
            c16[mt][nt][0] = 0u; c16[mt][nt][1] = 0u;
        }

    int q8 = lane >> 3, l8 = lane & 7;

    auto issue = [&](uint32_t sbuf, int kb) {
        for (int t = tid; t < 1024; t += 256) {
            int r = t >> 3, g = t & 7;
            uint32_t so = SW128((uint32_t)(r * 128 + g * 16));
            cp16(sbuf + so,
                 (const uint8_t*)g_h + ((size_t)(rowbase + r) * D + kb + g * 8) * 2);
        }
        for (int t = tid; t < 2048; t += 256) {
            int r = t >> 3, g = t & 7;
            uint32_t so = SW128((uint32_t)(r * 128 + g * 16));
            size_t ob = ((size_t)(r < 128 ? r : r - 128) * D + kb + g * 8) * 2;
            cp16(sbuf + F_OF_BH + so, (r < 128 ? BloH : BupH) + ob);
            cp16(sbuf + F_OF_BL + so, (r < 128 ? BloL : BupL) + ob);
        }
    };

    issue(sb, 0);
    cp_commit();

    for (int ch = 0; ch < 4; ch++) {
        uint32_t buf = sb + (uint32_t)(ch & 1) * F_STG;
        if (ch < 3) {
            issue(sb + (uint32_t)((ch + 1) & 1) * F_STG, (ch + 1) * 64);
            cp_commit();
            cp_wait<1>();
        } else {
            cp_wait<0>();
        }
        __syncthreads();

        #pragma unroll
        for (int ks = 0; ks < 4; ks++) {
            uint32_t ah[4][4];
            #pragma unroll
            for (int mt = 0; mt < 4; mt++) {
                int row = wrow * 64 + mt * 16 + (q8 & 1) * 8 + l8;
                uint32_t off = SW128((uint32_t)(row * 128 + ks * 32 + (q8 >> 1) * 16));
                ldsm4(ah[mt], buf + off);
            }
            #pragma unroll
            for (int nt = 0; nt < 4; nt++) {
                int nrow = wcol * 64 + nt * 16 + ((q8 >> 1) & 1) * 8 + l8;
                uint32_t off = SW128((uint32_t)(nrow * 128 + ks * 32 + (q8 & 1) * 16));
                uint32_t bh[4], bl[4];
                ldsm4(bh, buf + F_OF_BH + off);
                ldsm4(bl, buf + F_OF_BL + off);
                #pragma unroll
                for (int mt = 0; mt < 4; mt++) {
                    mma_f16 (c[mt][nt * 2],       ah[mt], bh[0], bh[1]);   // hi, f32 acc
                    mma_f16 (c[mt][nt * 2 + 1],   ah[mt], bh[2], bh[3]);
                    mma_f16h(c16[mt][nt * 2],     ah[mt], bl[0], bl[1]);   // lo, f16 acc
                    mma_f16h(c16[mt][nt * 2 + 1], ah[mt], bl[2], bl[3]);
                }
            }
        }
        __syncthreads();
    }

    const float INV = 1.0f / 1024.0f;
    #pragma unroll
    for (int mt = 0; mt < 4; mt++)
        #pragma unroll
        for (int nt = 0; nt < 8; nt++) {
            __half2 p0 = *reinterpret_cast<__half2*>(&c16[mt][nt][0]);
            __half2 p1 = *reinterpret_cast<__half2*>(&c16[mt][nt][1]);
            c[mt][nt][0] += __low2float(p0) * INV;
            c[mt][nt][1] += __high2float(p0) * INV;
            c[mt][nt][2] += __low2float(p1) * INV;
            c[mt][nt][3] += __high2float(p1) * INV;
        }

    float* stage = reinterpret_cast<float*>(smem);
    #pragma unroll
    for (int mt = 0; mt < 4; mt++)
        #pragma unroll
        for (int nt = 0; nt < 8; nt++) {
            int r0  = wrow * 64 + mt * 16 + (lane >> 2);
            int col = wcol * 64 + nt * 8 + 2 * (lane & 3);
            float* p = stage + r0 * SSTRIDE + col;
            p[0] = c[mt][nt][0];
            p[1] = c[mt][nt][1];
            p[8 * SSTRIDE]     = c[mt][nt][2];
            p[8 * SSTRIDE + 1] = c[mt][nt][3];
        }
    __syncthreads();

    for (int r = wid; r < 128; r += 8) {
        int gr = rowbase + r;
        bool ok = gr < NN;
        const float* rowp = stage + r * SSTRIDE + lane * 8;
        int cb = lane * 8;

        if (MODE == 1 || MODE == 3) {
            float v[8];
            if (lane < 16) {
                #pragma unroll
                for (int j = 0; j < 8; j++)
                    v[j] = fmaxf(rowp[j] + __ldg(&bias[cb + j]), 0.f);
                if (ok) {
                    float4* dst = reinterpret_cast<float4*>(g_a + (size_t)gr * DH + cb);
                    dst[0] = make_float4(v[0], v[1], v[2], v[3]);
                    dst[1] = make_float4(v[4], v[5], v[6], v[7]);
                }
            } else {
                #pragma unroll
                for (int j = 0; j < 8; j++) v[j] = rowp[j];
                if (ok) {
                    if (MODE == 1) {
                        float4* dst = reinterpret_cast<float4*>(g_y + (size_t)gr * DH + (cb - 128));
                        dst[0] = make_float4(v[0], v[1], v[2], v[3]);
                        dst[1] = make_float4(v[4], v[5], v[6], v[7]);
                    } else {
                        __half hh[8];
                        #pragma unroll
                        for (int j = 0; j < 8; j++) hh[j] = __float2half_rn(v[j]);
                        *reinterpret_cast<uint4*>(g_yh + (size_t)gr * DH + (cb - 128)) =
                            make_uint4(pack2h(hh[0], hh[1]), pack2h(hh[2], hh[3]),
                                       pack2h(hh[4], hh[5]), pack2h(hh[6], hh[7]));
                    }
                }
            }
        } else {
            float acc = 0.f;
            #pragma unroll
            for (int j = 0; j < 8; j++) {
                float vv = fmaxf(rowp[j] + __ldg(&bias[cb + j]), 0.f);
                acc += vv * __ldg(&wd2[cb + j]);
            }
            #pragma unroll
            for (int off = 16; off >= 1; off >>= 1)
                acc += __shfl_xor_sync(0xffffffffu, acc, off);
            if (lane == 0 && ok) out[gr] = acc + __ldg(bd2);
        }
    }
}

// ============================================================
// Fused CSR gather-reduce + bias + relu + l2norm + fp16 store
// One warp per dst node; lane owns 4 cols of each 128-wide half.
// YH=0: gather fp32 g_y (layer 1)  YH=1: gather fp16 g_yh (layer 2)
// ============================================================
template <int YH>
__global__ void agg_combine_kernel(const float* __restrict__ b3) {
    int gw = (blockIdx.x * blockDim.x + threadIdx.x) >> 5;
    int lane = threadIdx.x & 31;
    if (gw >= NN) return;
    int n = gw;
    int beg = __ldg(&g_rowptr[n]);
    int end = __ldg(&g_rowptr[n + 1]);

    float ax = 0.f, ay = 0.f, az = 0.f, aw = 0.f;
    int i = beg;
    if (YH == 0) {
        for (; i + 4 <= end; i += 4) {
            int s0 = __ldg(&g_colidx[i]);
            int s1 = __ldg(&g_colidx[i + 1]);
            int s2 = __ldg(&g_colidx[i + 2]);
            int s3 = __ldg(&g_colidx[i + 3]);
            float4 v0 = __ldg(reinterpret_cast<const float4*>(g_y + (size_t)s0 * DH) + lane);
            float4 v1 = __ldg(reinterpret_cast<const float4*>(g_y + (size_t)s1 * DH) + lane);
            float4 v2 = __ldg(reinterpret_cast<const float4*>(g_y + (size_t)s2 * DH) + lane);
            float4 v3 = __ldg(reinterpret_cast<const float4*>(g_y + (size_t)s3 * DH) + lane);
            ax += (v0.x + v1.x) + (v2.x + v3.x);
            ay += (v0.y + v1.y) + (v2.y + v3.y);
            az += (v0.z + v1.z) + (v2.z + v3.z);
            aw += (v0.w + v1.w) + (v2.w + v3.w);
        }
        for (; i < end; i++) {
            int s = __ldg(&g_colidx[i]);
            float4 v = __ldg(reinterpret_cast<const float4*>(g_y + (size_t)s * DH) + lane);
            ax += v.x; ay += v.y; az += v.z; aw += v.w;
        }
    } else {
        for (; i + 4 <= end; i += 4) {
            int s0 = __ldg(&g_colidx[i]);
            int s1 = __ldg(&g_colidx[i + 1]);
            int s2 = __ldg(&g_colidx[i + 2]);
            int s3 = __ldg(&g_colidx[i + 3]);
            uint2 u0 = __ldg(reinterpret_cast<const uint2*>(g_yh + (size_t)s0 * DH) + lane);
            uint2 u1 = __ldg(reinterpret_cast<const uint2*>(g_yh + (size_t)s1 * DH) + lane);
            uint2 u2 = __ldg(reinterpret_cast<const uint2*>(g_yh + (size_t)s2 * DH) + lane);
            uint2 u3 = __ldg(reinterpret_cast<const uint2*>(g_yh + (size_t)s3 * DH) + lane);
            float2 a0 = __half22float2(*reinterpret_cast<__half2*>(&u0.x));
            float2 b0 = __half22float2(*reinterpret_cast<__half2*>(&u0.y));
            float2 a1 = __half22float2(*reinterpret_cast<__half2*>(&u1.x));
            float2 b1 = __half22float2(*reinterpret_cast<__half2*>(&u1.y));
            float2 a2 = __half22float2(*reinterpret_cast<__half2*>(&u2.x));
            float2 b2 = __half22float2(*reinterpret_cast<__half2*>(&u2.y));
            float2 a3 = __half22float2(*reinterpret_cast<__half2*>(&u3.x));
            float2 b3v = __half22float2(*reinterpret_cast<__half2*>(&u3.y));
            ax += (a0.x + a1.x) + (a2.x + a3.x);
            ay += (a0.y + a1.y) + (a2.y + a3.y);
            az += (b0.x + b1.x) + (b2.x + b3v.x);
            aw += (b0.y + b1.y) + (b2.y + b3v.y);
        }
        for (; i < end; i++) {
            int s = __ldg(&g_colidx[i]);
            uint2 u = __ldg(reinterpret_cast<const uint2*>(g_yh + (size_t)s * DH) + lane);
            float2 a0 = __half22float2(*reinterpret_cast<__half2*>(&u.x));
            float2 b0 = __half22float2(*reinterpret_cast<__half2*>(&u.y));
            ax += a0.x; ay += a0.y; az += b0.x; aw += b0.y;
        }
    }

    float4 av = __ldg(reinterpret_cast<const float4*>(g_a + (size_t)n * DH) + lane);
    float4 bb = __ldg(reinterpret_cast<const float4*>(b3) + lane);
    float m0 = fmaxf(ax + bb.x, 0.f);
    float m1 = fmaxf(ay + bb.y, 0.f);
    float m2 = fmaxf(az + bb.z, 0.f);
    float m3 = fmaxf(aw + bb.w, 0.f);

    float ss = av.x * av.x + av.y * av.y + av.z * av.z + av.w * av.w
             + m0 * m0 + m1 * m1 + m2 * m2 + m3 * m3;
    #pragma unroll
    for (int off = 16; off >= 1; off >>= 1)
        ss += __shfl_xor_sync(0xffffffffu, ss, off);
    float rn = rsqrtf(ss);

    size_t base = (size_t)n * D;
    *reinterpret_cast<uint2*>(g_h + base + lane * 4) =
        make_uint2(pack2h(__float2half_rn(av.x * rn), __float2half_rn(av.y * rn)),
                   pack2h(__float2half_rn(av.z * rn), __float2half_rn(av.w * rn)));
    *reinterpret_cast<uint2*>(g_h + base + 128 + lane * 4) =
        make_uint2(pack2h(__float2half_rn(m0 * rn), __float2half_rn(m1 * rn)),
                   pack2h(__float2half_rn(m2 * rn), __float2half_rn(m3 * rn)));
}

// ============================================================
// Host launcher — CSR chain (wide / tiny-reg kernels) on side
// stream overlapping conv_w + gemm0 + first mid GEMM; joins
// before the first agg_combine.
// ============================================================
static cudaStream_t s2 = nullptr;
static cudaEvent_t evFork, evCSR;

extern "C" void kernel_launch(void* const* d_in, const int* in_sizes, int n_in,
                              void* d_out, int out_size) {
    const float* x   = (const float*)d_in[0];
    const int*   ei  = (const int*)d_in[1];    // int32 or int64 (auto-detected)
    const float* W1  = (const float*)d_in[2];
    const float* b1  = (const float*)d_in[3];
    const float* W2  = (const float*)d_in[4];
    const float* b2  = (const float*)d_in[5];
    const float* W3  = (const float*)d_in[6];
    const float* b3  = (const float*)d_in[7];
    const float* Wd1 = (const float*)d_in[8];
    const float* bd1 = (const float*)d_in[9];
    const float* Wd2 = (const float*)d_in[10];
    const float* bd2 = (const float*)d_in[11];
    float* out = (float*)d_out;

    if (!s2) {
        cudaStreamCreateWithFlags(&s2, cudaStreamNonBlocking);
        cudaEventCreateWithFlags(&evFork, cudaEventDisableTiming);
        cudaEventCreateWithFlags(&evCSR,  cudaEventDisableTiming);
        cudaFuncSetAttribute(gemm0_kernel,   cudaFuncAttributeMaxDynamicSharedMemorySize, G0_SMEM);
        cudaFuncSetAttribute(gemm_kernel<1>, cudaFuncAttributeMaxDynamicSharedMemorySize, F_SMEM);
        cudaFuncSetAttribute(gemm_kernel<2>, cudaFuncAttributeMaxDynamicSharedMemorySize, F_SMEM);
        cudaFuncSetAttribute(gemm_kernel<3>, cudaFuncAttributeMaxDynamicSharedMemorySize, F_SMEM);
    }

    // ---- fork side stream: full CSR build (independent of main chain)
    cudaEventRecord(evFork, 0);
    cudaStreamWaitEvent(s2, evFork, 0);
    zero_cnt_kernel<<<(NN + 255) / 256, 256, 0, s2>>>();
    detect_kernel<<<1, 1, 0, s2>>>(ei);
    count_kernel<<<(NE + 255) / 256, 256, 0, s2>>>(ei);
    scan_block_kernel<<<SCAN_BLKS, 1024, 0, s2>>>();
    scan_top_kernel<<<1, 128, 0, s2>>>();
    scan_apply_kernel<<<SCAN_BLKS, 1024, 0, s2>>>();
    fill_edges_kernel<<<(NE + 255) / 256, 256, 0, s2>>>(ei);
    cudaEventRecord(evCSR, s2);

    // ---- main stream: weights + layer 1 + first mid GEMM
    conv_w_all_kernel<<<192, 256>>>(W1, W2, W3, Wd1);
    gemm0_kernel<<<NB128, 256, G0_SMEM>>>(x, b1);

    // conv layer 1 (fp32 y)
    gemm_kernel<1><<<NB128, 256, F_SMEM>>>(b2, nullptr, nullptr, nullptr);
    cudaStreamWaitEvent(0, evCSR, 0);          // join CSR before first gather
    agg_combine_kernel<0><<<(NN * 32 + 255) / 256, 256>>>(b3);

    // conv layer 2 (fp16 y — least error amplification, halves gather bytes)
    gemm_kernel<3><<<NB128, 256, F_SMEM>>>(b2, nullptr, nullptr, nullptr);
    agg_combine_kernel<1><<<(NN * 32 + 255) / 256, 256>>>(b3);

    // head: out = relu(h @ Wd1^T + bd1) @ Wd2^T + bd2
    gemm_kernel<2><<<NB128, 256, F_SMEM>>>(bd1, Wd2, bd2, out);
}